// round 1
// baseline (speedup 1.0000x reference)
#include <cuda_runtime.h>
#include <cuda_bf16.h>
#include <cstdint>

// ---------------------------------------------------------------------------
// GAT (3 layers, H heads, concat=False/mean) for GB/B200.
// Pipeline per layer:
//   1) SGEMM: h = x_in @ W            [N, H*C]
//   2) logits: e_src/e_dst = <h, a>   [N, H]
//   3) per-dst-node softmax + weighted gather-sum (CSR), mean heads + bias
// CSR (by dst, incl. self loops) built once per launch, reused by all layers.
// ---------------------------------------------------------------------------

#define N_MAX   10240
#define HC_MAX  1024
#define C_MAX   256
#define H_MAX   8
#define ET_MAX  204800   // E + N cap

__device__ __align__(128) float g_h[(size_t)N_MAX * HC_MAX];
__device__ __align__(128) float g_xb0[(size_t)N_MAX * C_MAX];
__device__ __align__(128) float g_xb1[(size_t)N_MAX * C_MAX];
__device__ __align__(128) float g_esrc[N_MAX * H_MAX];
__device__ __align__(128) float g_edst[N_MAX * H_MAX];
__device__ int g_rowptr[N_MAX + 1];
__device__ int g_cnt[N_MAX];
__device__ int g_cursor[N_MAX];
__device__ int g_col[ET_MAX];

// ---------------------------------------------------------------------------
// SGEMM: C[M,N] = A[M,K] @ B[K,N], row-major. BM=BN=128, BK=8, TM=TN=8,
// 256 threads. N % 128 == 0, K % 8 == 0 required; M guarded.
// ---------------------------------------------------------------------------
__global__ __launch_bounds__(256, 2)
void sgemm128(const float* __restrict__ A, const float* __restrict__ B,
              float* __restrict__ C, int M, int N, int K) {
    constexpr int BM = 128, BN = 128, BK = 8, TM = 8, TN = 8;
    __shared__ float As[BK * BM];
    __shared__ float Bs[BK * BN];

    const int tid = threadIdx.x;
    const int crow = blockIdx.y;   // M tile
    const int ccol = blockIdx.x;   // N tile

    const int threadCol = tid % (BN / TN);   // 0..15
    const int threadRow = tid / (BN / TN);   // 0..15

    const int innerRowA = tid / (BK / 4);        // 0..127
    const int innerColA = (tid % (BK / 4)) * 4;  // 0 or 4
    const int innerRowB = tid / (BN / 4);        // 0..7
    const int innerColB = (tid % (BN / 4)) * 4;  // 0..124

    const float* Ab = A + (size_t)crow * BM * K;
    const float* Bb = B + ccol * BN;

    float acc[TM][TN] = {};
    float regM[TM], regN[TN];

    const int arow = crow * BM + innerRowA;
    const bool aok = (arow < M);

    for (int kb = 0; kb < K; kb += BK) {
        float4 a = make_float4(0.f, 0.f, 0.f, 0.f);
        if (aok)
            a = *reinterpret_cast<const float4*>(&Ab[(size_t)innerRowA * K + kb + innerColA]);
        As[(innerColA + 0) * BM + innerRowA] = a.x;
        As[(innerColA + 1) * BM + innerRowA] = a.y;
        As[(innerColA + 2) * BM + innerRowA] = a.z;
        As[(innerColA + 3) * BM + innerRowA] = a.w;

        float4 b = *reinterpret_cast<const float4*>(&Bb[(size_t)(kb + innerRowB) * N + innerColB]);
        *reinterpret_cast<float4*>(&Bs[innerRowB * BN + innerColB]) = b;

        __syncthreads();

#pragma unroll
        for (int k = 0; k < BK; ++k) {
#pragma unroll
            for (int i = 0; i < TM; ++i) regM[i] = As[k * BM + threadRow * TM + i];
#pragma unroll
            for (int j = 0; j < TN; ++j) regN[j] = Bs[k * BN + threadCol * TN + j];
#pragma unroll
            for (int i = 0; i < TM; ++i)
#pragma unroll
                for (int j = 0; j < TN; ++j)
                    acc[i][j] += regM[i] * regN[j];
        }
        __syncthreads();
    }

#pragma unroll
    for (int i = 0; i < TM; ++i) {
        int row = crow * BM + threadRow * TM + i;
        if (row < M) {
            float* cp = &C[(size_t)row * N + ccol * BN + threadCol * TN];
            *reinterpret_cast<float4*>(cp + 0) = make_float4(acc[i][0], acc[i][1], acc[i][2], acc[i][3]);
            *reinterpret_cast<float4*>(cp + 4) = make_float4(acc[i][4], acc[i][5], acc[i][6], acc[i][7]);
        }
    }
}

// ---------------------------------------------------------------------------
// CSR build
// ---------------------------------------------------------------------------
__global__ void count_k(const int* __restrict__ dst, int E, int n, int* __restrict__ cnt) {
    int i = blockIdx.x * blockDim.x + threadIdx.x;
    int tot = E + n;
    if (i < tot) {
        int d = (i < E) ? dst[i] : (i - E);
        atomicAdd(&cnt[d], 1);
    }
}

__global__ void scan_k(const int* __restrict__ cnt, int* __restrict__ rowptr, int n) {
    __shared__ int sh[1024];
    __shared__ int carry_sh;
    int tid = threadIdx.x;
    if (tid == 0) carry_sh = 0;
    __syncthreads();
    for (int base = 0; base < n; base += 1024) {
        int cin = carry_sh;
        int v = (base + tid < n) ? cnt[base + tid] : 0;
        sh[tid] = v;
        __syncthreads();
#pragma unroll
        for (int off = 1; off < 1024; off <<= 1) {
            int t = (tid >= off) ? sh[tid - off] : 0;
            __syncthreads();
            sh[tid] += t;
            __syncthreads();
        }
        if (base + tid < n) rowptr[base + tid] = cin + sh[tid] - v;
        __syncthreads();
        if (tid == 0) carry_sh = cin + sh[1023];
        __syncthreads();
    }
    if (tid == 0) rowptr[n] = carry_sh;
}

__global__ void fill_k(const int* __restrict__ src, const int* __restrict__ dst,
                       int E, int n, int* __restrict__ cursor, int* __restrict__ col) {
    int i = blockIdx.x * blockDim.x + threadIdx.x;
    int tot = E + n;
    if (i < tot) {
        int s, d;
        if (i < E) { s = src[i]; d = dst[i]; }
        else       { s = d = i - E; }
        int pos = atomicAdd(&cursor[d], 1);
        col[pos] = s;
    }
}

// ---------------------------------------------------------------------------
// Per-node attention logits: e_src[n,h] = <h[n,h,:], a_src[h,:]>, same for dst.
// One block per node, warp per head.
// ---------------------------------------------------------------------------
__global__ void logits_k(const float* __restrict__ hbuf,
                         const float* __restrict__ asrc, const float* __restrict__ adst,
                         float* __restrict__ esrc, float* __restrict__ edst,
                         int H, int C) {
    int n = blockIdx.x;
    int wid = threadIdx.x >> 5, lane = threadIdx.x & 31;
    if (wid >= H) return;
    const float* hp = hbuf + (size_t)n * H * C + (size_t)wid * C;
    const float* as = asrc + (size_t)wid * C;
    const float* ad = adst + (size_t)wid * C;
    float s1 = 0.f, s2 = 0.f;
    for (int c = lane; c < C; c += 32) {
        float v = hp[c];
        s1 += v * as[c];
        s2 += v * ad[c];
    }
#pragma unroll
    for (int o = 16; o > 0; o >>= 1) {
        s1 += __shfl_xor_sync(0xffffffffu, s1, o);
        s2 += __shfl_xor_sync(0xffffffffu, s2, o);
    }
    if (lane == 0) {
        esrc[n * H + wid] = s1;
        edst[n * H + wid] = s2;
    }
}

// ---------------------------------------------------------------------------
// Aggregation: per dst node, segment softmax over incoming edges + weighted
// sum of source features; mean over heads + bias.
// Block = 256 threads, one block per node. Thread t owns channel c=t.
// Warps 0..H-1 compute per-head softmax stats and per-edge weights.
// ---------------------------------------------------------------------------
#define AGG_CAP 128

__global__ __launch_bounds__(256)
void aggregate_k(const float* __restrict__ hbuf,
                 const float* __restrict__ esrc, const float* __restrict__ edst,
                 const int* __restrict__ rowptr, const int* __restrict__ col,
                 const float* __restrict__ bias, float* __restrict__ out,
                 int H, int C, int HC, float invH) {
    __shared__ float sh_m[H_MAX];
    __shared__ float sh_dinv[H_MAX];
    __shared__ float w_sh[AGG_CAP * H_MAX];
    __shared__ int col_sh[AGG_CAP];

    int n = blockIdx.x;
    int tid = threadIdx.x;
    int wid = tid >> 5, lane = tid & 31;
    int start = rowptr[n], end = rowptr[n + 1];

    float edh = 0.f;
    if (wid < H) {
        edh = edst[n * H + wid];
        // pass 1a: max
        float mx = -1e30f;
        for (int e = start + lane; e < end; e += 32) {
            float v = esrc[col[e] * H + wid] + edh;
            v = v > 0.f ? v : 0.2f * v;
            mx = fmaxf(mx, v);
        }
#pragma unroll
        for (int o = 16; o > 0; o >>= 1) mx = fmaxf(mx, __shfl_xor_sync(0xffffffffu, mx, o));
        // pass 1b: sum exp
        float sum = 0.f;
        for (int e = start + lane; e < end; e += 32) {
            float v = esrc[col[e] * H + wid] + edh;
            v = v > 0.f ? v : 0.2f * v;
            sum += __expf(v - mx);
        }
#pragma unroll
        for (int o = 16; o > 0; o >>= 1) sum += __shfl_xor_sync(0xffffffffu, sum, o);
        if (lane == 0) {
            sh_m[wid] = mx;
            sh_dinv[wid] = 1.f / (sum + 1e-16f);
        }
    }
    __syncthreads();

    int c = tid;
    float acc = 0.f;
    for (int cb = start; cb < end; cb += AGG_CAP) {
        int cnt = end - cb;
        if (cnt > AGG_CAP) cnt = AGG_CAP;
        if (wid < H) {
            float m = sh_m[wid], dinv = sh_dinv[wid];
            for (int e = lane; e < cnt; e += 32) {
                int s = col[cb + e];
                if (wid == 0) col_sh[e] = s;
                float v = esrc[s * H + wid] + edh;
                v = v > 0.f ? v : 0.2f * v;
                w_sh[e * H + wid] = __expf(v - m) * dinv;
            }
        }
        __syncthreads();
        if (c < C) {
            for (int e = 0; e < cnt; ++e) {
                int s = col_sh[e];
                const float* hp = hbuf + (size_t)s * HC + c;
                float a = 0.f;
#pragma unroll 4
                for (int h = 0; h < H; ++h) a += w_sh[e * H + h] * hp[(size_t)h * C];
                acc += a;
            }
        }
        __syncthreads();
    }
    if (c < C) out[(size_t)n * C + c] = acc * invH + bias[c];
}

// ---------------------------------------------------------------------------
// Host launcher
// ---------------------------------------------------------------------------
extern "C" void kernel_launch(void* const* d_in, const int* in_sizes, int n_in,
                              void* d_out, int out_size) {
    const float* x  = (const float*)d_in[0];
    const int*   ei = (const int*)d_in[1];
    const float* W[3]  = {(const float*)d_in[2],  (const float*)d_in[6],  (const float*)d_in[10]};
    const float* AS[3] = {(const float*)d_in[3],  (const float*)d_in[7],  (const float*)d_in[11]};
    const float* AD[3] = {(const float*)d_in[4],  (const float*)d_in[8],  (const float*)d_in[12]};
    const float* B[3]  = {(const float*)d_in[5],  (const float*)d_in[9],  (const float*)d_in[13]};

    const int Cc[3] = {in_sizes[5], in_sizes[9], in_sizes[13]};
    const int H = in_sizes[3] / Cc[0];
    const int E = in_sizes[1] / 2;
    const int N = out_size / Cc[2];
    const int F_IN = in_sizes[0] / N;

    float *hbuf, *xb0, *xb1, *esrc, *edst;
    int *rowptr, *cnt, *cursor, *col;
    cudaGetSymbolAddress((void**)&hbuf,   g_h);
    cudaGetSymbolAddress((void**)&xb0,    g_xb0);
    cudaGetSymbolAddress((void**)&xb1,    g_xb1);
    cudaGetSymbolAddress((void**)&esrc,   g_esrc);
    cudaGetSymbolAddress((void**)&edst,   g_edst);
    cudaGetSymbolAddress((void**)&rowptr, g_rowptr);
    cudaGetSymbolAddress((void**)&cnt,    g_cnt);
    cudaGetSymbolAddress((void**)&cursor, g_cursor);
    cudaGetSymbolAddress((void**)&col,    g_col);

    // ---- CSR build (by dst, with self loops) ----
    cudaMemsetAsync(cnt, 0, N * sizeof(int));
    {
        int tot = E + N;
        int blocks = (tot + 255) / 256;
        count_k<<<blocks, 256>>>(ei + E, E, N, cnt);
        scan_k<<<1, 1024>>>(cnt, rowptr, N);
        cudaMemcpyAsync(cursor, rowptr, N * sizeof(int), cudaMemcpyDeviceToDevice);
        fill_k<<<blocks, 256>>>(ei, ei + E, E, N, cursor, col);
    }

    // ---- 3 GAT layers ----
    const float* xin = x;
    int K = F_IN;
    float* outs[3] = {xb0, xb1, (float*)d_out};
    for (int l = 0; l < 3; ++l) {
        int C = Cc[l], HC = H * C;
        dim3 g(HC / 128, (N + 127) / 128);
        sgemm128<<<g, 256>>>(xin, W[l], hbuf, N, HC, K);
        logits_k<<<N, 32 * H>>>(hbuf, AS[l], AD[l], esrc, edst, H, C);
        aggregate_k<<<N, 256>>>(hbuf, esrc, edst, rowptr, col, B[l], outs[l],
                                H, C, HC, 1.0f / (float)H);
        xin = outs[l];
        K = C;
    }
}

// round 3
// speedup vs baseline: 1.5240x; 1.5240x over previous
#include <cuda_runtime.h>
#include <cuda_bf16.h>
#include <cstdint>

// ---------------------------------------------------------------------------
// GAT (3 layers, H=4 heads, concat=False/mean) for B200 (base sm_100 PTX).
// Per layer:
//   0) split x -> bf16 hi/lo ; transpose+split W -> [HC][K] bf16 hi/lo
//   1) warp-mma bf16 GEMM (3-pass hi/lo split, fp32 accum): h = x @ W
//   2) logits e_src/e_dst = <h, a>
//   3) per-dst softmax + weighted gather-sum via CSR, mean heads + bias
// ---------------------------------------------------------------------------

#define N_MAX   10240
#define K_MAXD  512
#define HC_MAX  1024
#define C_MAX   256
#define H_MAX   8
#define ET_MAX  204800

__device__ __align__(128) float g_h[(size_t)N_MAX * HC_MAX];
__device__ __align__(128) float g_xb0[(size_t)N_MAX * C_MAX];
__device__ __align__(128) float g_xb1[(size_t)N_MAX * C_MAX];
__device__ __align__(128) float g_esrc[N_MAX * H_MAX];
__device__ __align__(128) float g_edst[N_MAX * H_MAX];
__device__ __align__(128) __nv_bfloat16 g_Ah[(size_t)N_MAX * K_MAXD];
__device__ __align__(128) __nv_bfloat16 g_Al[(size_t)N_MAX * K_MAXD];
__device__ __align__(128) __nv_bfloat16 g_Bh[(size_t)HC_MAX * K_MAXD];
__device__ __align__(128) __nv_bfloat16 g_Bl[(size_t)HC_MAX * K_MAXD];
__device__ int g_rowptr[N_MAX + 1];
__device__ int g_cnt[N_MAX];
__device__ int g_cursor[N_MAX];
__device__ int g_col[ET_MAX];

// ======================= helpers ==========================================
__device__ __forceinline__ uint32_t smem_u32(const void* p) {
    uint32_t a;
    asm("{ .reg .u64 t; cvta.to.shared.u64 t, %1; cvt.u32.u64 %0, t; }" : "=r"(a) : "l"(p));
    return a;
}

__device__ __forceinline__ void cp16(uint32_t saddr, const void* gaddr, int srcbytes) {
    asm volatile("cp.async.cg.shared.global [%0], [%1], 16, %2;"
                 :: "r"(saddr), "l"(gaddr), "r"(srcbytes) : "memory");
}
__device__ __forceinline__ void cp_commit() {
    asm volatile("cp.async.commit_group;" ::: "memory");
}
template <int NN>
__device__ __forceinline__ void cp_wait() {
    asm volatile("cp.async.wait_group %0;" :: "n"(NN) : "memory");
}

__device__ __forceinline__ void ldsm4(uint32_t* r, uint32_t addr) {
    asm volatile("ldmatrix.sync.aligned.m8n8.x4.shared.b16 {%0,%1,%2,%3}, [%4];"
                 : "=r"(r[0]), "=r"(r[1]), "=r"(r[2]), "=r"(r[3]) : "r"(addr));
}

__device__ __forceinline__ void mma16816(float* d, const uint32_t* a, const uint32_t* b) {
    asm volatile(
        "mma.sync.aligned.m16n8k16.row.col.f32.bf16.bf16.f32 "
        "{%0,%1,%2,%3}, {%4,%5,%6,%7}, {%8,%9}, {%0,%1,%2,%3};"
        : "+f"(d[0]), "+f"(d[1]), "+f"(d[2]), "+f"(d[3])
        : "r"(a[0]), "r"(a[1]), "r"(a[2]), "r"(a[3]), "r"(b[0]), "r"(b[1]));
}

// ======================= split / transpose kernels =========================
__global__ void split_k(const float* __restrict__ X, __nv_bfloat16* __restrict__ Ah,
                        __nv_bfloat16* __restrict__ Al, int total) {
    int i = blockIdx.x * blockDim.x + threadIdx.x;
    if (i < total) {
        float v = X[i];
        __nv_bfloat16 hi = __float2bfloat16(v);
        Ah[i] = hi;
        Al[i] = __float2bfloat16(v - __bfloat162float(hi));
    }
}

// W [K][HC] row-major -> Bt hi/lo [HC][K]
__global__ void tsplitW_k(const float* __restrict__ W, __nv_bfloat16* __restrict__ Bh,
                          __nv_bfloat16* __restrict__ Bl, int K, int HC) {
    __shared__ float t[32][33];
    int kb = blockIdx.y * 32, nb = blockIdx.x * 32;
    int tx = threadIdx.x, ty = threadIdx.y;   // 32 x 8
    for (int i = ty; i < 32; i += 8)
        t[i][tx] = W[(size_t)(kb + i) * HC + nb + tx];
    __syncthreads();
    for (int i = ty; i < 32; i += 8) {
        float v = t[tx][i];
        __nv_bfloat16 hi = __float2bfloat16(v);
        size_t o = (size_t)(nb + i) * K + kb + tx;
        Bh[o] = hi;
        Bl[o] = __float2bfloat16(v - __bfloat162float(hi));
    }
}

// ======================= warp-mma GEMM =====================================
// C[M, HC] = A[M,K] @ W[K,HC]. A hi/lo [M][K], B hi/lo [HC][K] (K-major).
// Block 256 thr (8 warps 4x2), tile 128x128, BK=32, double-buffered cp.async.
// Smem per stage 32KB: Ah@0, Al@8K, Bh@16K, Bl@24K. Tiles [128 rows][32 k] bf16,
// 16B chunks swizzled: off(m,k16) = m*64 + ((k16 ^ ((m>>1)&3))<<4).
#define GEMM_SMEM 65536

__global__ __launch_bounds__(256, 1)
void gemm_mma(const __nv_bfloat16* __restrict__ Ah, const __nv_bfloat16* __restrict__ Al,
              const __nv_bfloat16* __restrict__ Bh, const __nv_bfloat16* __restrict__ Bl,
              float* __restrict__ C, int M, int Ncols, int K) {
    extern __shared__ __align__(1024) char smem[];
    const uint32_t sbase = smem_u32(smem);
    const int tid = threadIdx.x;
    const int lane = tid & 31, wid = tid >> 5;
    const int warp_m = wid & 3;        // 4 warps along M (32 rows each)
    const int warp_n = wid >> 2;       // 2 warps along N (64 cols each)
    const int mtile = blockIdx.y, ntile = blockIdx.x;
    const int g = lane >> 3, r = lane & 7;

    float acc[2][8][4] = {};

    const int nch = K >> 5;   // BK=32

    // ---- stage loader ----
    auto load_stage = [&](int buf, int ch) {
        const int kb = ch << 5;
        const uint32_t sb = sbase + buf * 32768;
#pragma unroll
        for (int j = 0; j < 2; ++j) {
            int chunk = tid + (j << 8);
            int m = chunk >> 2, k16 = chunk & 3;
            uint32_t soff = m * 64 + ((k16 ^ ((m >> 1) & 3)) << 4);
            int arow = mtile * 128 + m;
            int aval = (arow < M) ? 16 : 0;
            int ar = (arow < M) ? arow : (M - 1);
            size_t aoff = (size_t)ar * K + kb + k16 * 8;
            cp16(sb + soff,          Ah + aoff, aval);
            cp16(sb + 8192 + soff,   Al + aoff, aval);
            int brow = ntile * 128 + m;
            size_t boff = (size_t)brow * K + kb + k16 * 8;
            cp16(sb + 16384 + soff,  Bh + boff, 16);
            cp16(sb + 24576 + soff,  Bl + boff, 16);
        }
    };

    load_stage(0, 0);
    cp_commit();

    for (int ch = 0; ch < nch; ++ch) {
        const int nxt = ch + 1;
        if (nxt < nch) { load_stage(nxt & 1, nxt); cp_commit(); }
        if (nxt < nch) cp_wait<1>(); else cp_wait<0>();
        __syncthreads();

        const uint32_t sb = sbase + (ch & 1) * 32768;
#pragma unroll
        for (int ks = 0; ks < 2; ++ks) {
            uint32_t ahf[2][4], alf[2][4], bhf[8][2], blf[8][2];
#pragma unroll
            for (int mt = 0; mt < 2; ++mt) {
                int ml = warp_m * 32 + mt * 16 + r + ((g & 1) << 3);
                int k16 = ks * 2 + (g >> 1);
                uint32_t ad = sb + ml * 64 + ((k16 ^ ((ml >> 1) & 3)) << 4);
                ldsm4(ahf[mt], ad);
                ldsm4(alf[mt], ad + 8192);
            }
#pragma unroll
            for (int nt2 = 0; nt2 < 4; ++nt2) {
                int nl = warp_n * 64 + nt2 * 16 + r + ((g >> 1) << 3);
                int k16 = ks * 2 + (g & 1);
                uint32_t bd = sb + 16384 + nl * 64 + ((k16 ^ ((nl >> 1) & 3)) << 4);
                uint32_t tb[4];
                ldsm4(tb, bd);
                bhf[nt2 * 2][0] = tb[0]; bhf[nt2 * 2][1] = tb[1];
                bhf[nt2 * 2 + 1][0] = tb[2]; bhf[nt2 * 2 + 1][1] = tb[3];
                ldsm4(tb, bd + 8192);
                blf[nt2 * 2][0] = tb[0]; blf[nt2 * 2][1] = tb[1];
                blf[nt2 * 2 + 1][0] = tb[2]; blf[nt2 * 2 + 1][1] = tb[3];
            }
#pragma unroll
            for (int mt = 0; mt < 2; ++mt)
#pragma unroll
                for (int nt = 0; nt < 8; ++nt) {
                    mma16816(acc[mt][nt], ahf[mt], bhf[nt]);
                    mma16816(acc[mt][nt], ahf[mt], blf[nt]);
                    mma16816(acc[mt][nt], alf[mt], bhf[nt]);
                }
        }
        __syncthreads();
    }

    // ---- epilogue: registers -> global ----
#pragma unroll
    for (int mt = 0; mt < 2; ++mt) {
        int row0 = mtile * 128 + warp_m * 32 + mt * 16 + (lane >> 2);
#pragma unroll
        for (int nt = 0; nt < 8; ++nt) {
            int col = ntile * 128 + warp_n * 64 + nt * 8 + (lane & 3) * 2;
            if (row0 < M)
                *reinterpret_cast<float2*>(&C[(size_t)row0 * Ncols + col]) =
                    make_float2(acc[mt][nt][0], acc[mt][nt][1]);
            if (row0 + 8 < M)
                *reinterpret_cast<float2*>(&C[(size_t)(row0 + 8) * Ncols + col]) =
                    make_float2(acc[mt][nt][2], acc[mt][nt][3]);
        }
    }
}

// ======================= CSR build =========================================
__global__ void count_k(const int* __restrict__ dst, int E, int n, int* __restrict__ cnt) {
    int i = blockIdx.x * blockDim.x + threadIdx.x;
    int tot = E + n;
    if (i < tot) {
        int d = (i < E) ? dst[i] : (i - E);
        atomicAdd(&cnt[d], 1);
    }
}

__global__ void scan_k(const int* __restrict__ cnt, int* __restrict__ rowptr, int n) {
    __shared__ int sh[1024];
    __shared__ int carry_sh;
    int tid = threadIdx.x;
    if (tid == 0) carry_sh = 0;
    __syncthreads();
    for (int base = 0; base < n; base += 1024) {
        int cin = carry_sh;
        int v = (base + tid < n) ? cnt[base + tid] : 0;
        sh[tid] = v;
        __syncthreads();
#pragma unroll
        for (int off = 1; off < 1024; off <<= 1) {
            int t = (tid >= off) ? sh[tid - off] : 0;
            __syncthreads();
            sh[tid] += t;
            __syncthreads();
        }
        if (base + tid < n) rowptr[base + tid] = cin + sh[tid] - v;
        __syncthreads();
        if (tid == 0) carry_sh = cin + sh[1023];
        __syncthreads();
    }
    if (tid == 0) rowptr[n] = carry_sh;
}

__global__ void fill_k(const int* __restrict__ src, const int* __restrict__ dst,
                       int E, int n, int* __restrict__ cursor, int* __restrict__ col) {
    int i = blockIdx.x * blockDim.x + threadIdx.x;
    int tot = E + n;
    if (i < tot) {
        int s, d;
        if (i < E) { s = src[i]; d = dst[i]; }
        else       { s = d = i - E; }
        int pos = atomicAdd(&cursor[d], 1);
        col[pos] = s;
    }
}

// ======================= logits ============================================
__global__ void logits_k(const float* __restrict__ hbuf,
                         const float* __restrict__ asrc, const float* __restrict__ adst,
                         float* __restrict__ esrc, float* __restrict__ edst,
                         int H, int C) {
    int n = blockIdx.x;
    int wid = threadIdx.x >> 5, lane = threadIdx.x & 31;
    if (wid >= H) return;
    const float* hp = hbuf + (size_t)n * H * C + (size_t)wid * C;
    const float* as = asrc + (size_t)wid * C;
    const float* ad = adst + (size_t)wid * C;
    float s1 = 0.f, s2 = 0.f;
    for (int c = lane; c < C; c += 32) {
        float v = hp[c];
        s1 += v * as[c];
        s2 += v * ad[c];
    }
#pragma unroll
    for (int o = 16; o > 0; o >>= 1) {
        s1 += __shfl_xor_sync(0xffffffffu, s1, o);
        s2 += __shfl_xor_sync(0xffffffffu, s2, o);
    }
    if (lane == 0) {
        esrc[n * H + wid] = s1;
        edst[n * H + wid] = s2;
    }
}

// ======================= aggregation =======================================
#define AGG_CAP 128

__global__ __launch_bounds__(256)
void aggregate_k(const float* __restrict__ hbuf,
                 const float* __restrict__ esrc, const float* __restrict__ edst,
                 const int* __restrict__ rowptr, const int* __restrict__ col,
                 const float* __restrict__ bias, float* __restrict__ out,
                 int H, int C, int HC, float invH) {
    __shared__ float sh_m[H_MAX];
    __shared__ float sh_dinv[H_MAX];
    __shared__ float w_sh[AGG_CAP * H_MAX];
    __shared__ int col_sh[AGG_CAP];

    int n = blockIdx.x;
    int tid = threadIdx.x;
    int wid = tid >> 5, lane = tid & 31;
    int start = rowptr[n], end = rowptr[n + 1];

    float edh = 0.f;
    if (wid < H) {
        edh = edst[n * H + wid];
        float mx = -1e30f;
        for (int e = start + lane; e < end; e += 32) {
            float v = esrc[col[e] * H + wid] + edh;
            v = v > 0.f ? v : 0.2f * v;
            mx = fmaxf(mx, v);
        }
#pragma unroll
        for (int o = 16; o > 0; o >>= 1) mx = fmaxf(mx, __shfl_xor_sync(0xffffffffu, mx, o));
        float sum = 0.f;
        for (int e = start + lane; e < end; e += 32) {
            float v = esrc[col[e] * H + wid] + edh;
            v = v > 0.f ? v : 0.2f * v;
            sum += __expf(v - mx);
        }
#pragma unroll
        for (int o = 16; o > 0; o >>= 1) sum += __shfl_xor_sync(0xffffffffu, sum, o);
        if (lane == 0) {
            sh_m[wid] = mx;
            sh_dinv[wid] = 1.f / (sum + 1e-16f);
        }
    }
    __syncthreads();

    int c = tid;
    float acc = 0.f;
    for (int cb = start; cb < end; cb += AGG_CAP) {
        int cnt = end - cb;
        if (cnt > AGG_CAP) cnt = AGG_CAP;
        if (wid < H) {
            float m = sh_m[wid], dinv = sh_dinv[wid];
            for (int e = lane; e < cnt; e += 32) {
                int s = col[cb + e];
                if (wid == 0) col_sh[e] = s;
                float v = esrc[s * H + wid] + edh;
                v = v > 0.f ? v : 0.2f * v;
                w_sh[e * H + wid] = __expf(v - m) * dinv;
            }
        }
        __syncthreads();
        if (c < C) {
            for (int e = 0; e < cnt; ++e) {
                int s = col_sh[e];
                const float* hp = hbuf + (size_t)s * HC + c;
                float a = 0.f;
#pragma unroll 4
                for (int h = 0; h < H; ++h) a += w_sh[e * H + h] * hp[(size_t)h * C];
                acc += a;
            }
        }
        __syncthreads();
    }
    if (c < C) out[(size_t)n * C + c] = acc * invH + bias[c];
}

// ======================= host launcher =====================================
extern "C" void kernel_launch(void* const* d_in, const int* in_sizes, int n_in,
                              void* d_out, int out_size) {
    const float* x  = (const float*)d_in[0];
    const int*   ei = (const int*)d_in[1];
    const float* W[3]  = {(const float*)d_in[2],  (const float*)d_in[6],  (const float*)d_in[10]};
    const float* AS[3] = {(const float*)d_in[3],  (const float*)d_in[7],  (const float*)d_in[11]};
    const float* AD[3] = {(const float*)d_in[4],  (const float*)d_in[8],  (const float*)d_in[12]};
    const float* B[3]  = {(const float*)d_in[5],  (const float*)d_in[9],  (const float*)d_in[13]};

    const int Cc[3] = {in_sizes[5], in_sizes[9], in_sizes[13]};
    const int H = in_sizes[3] / Cc[0];
    const int E = in_sizes[1] / 2;
    const int N = out_size / Cc[2];
    const int F_IN = in_sizes[0] / N;

    float *hbuf, *xb0, *xb1, *esrc, *edst;
    __nv_bfloat16 *Ah, *Al, *Bh, *Bl;
    int *rowptr, *cnt, *cursor, *col;
    cudaGetSymbolAddress((void**)&hbuf,   g_h);
    cudaGetSymbolAddress((void**)&xb0,    g_xb0);
    cudaGetSymbolAddress((void**)&xb1,    g_xb1);
    cudaGetSymbolAddress((void**)&esrc,   g_esrc);
    cudaGetSymbolAddress((void**)&edst,   g_edst);
    cudaGetSymbolAddress((void**)&Ah,     g_Ah);
    cudaGetSymbolAddress((void**)&Al,     g_Al);
    cudaGetSymbolAddress((void**)&Bh,     g_Bh);
    cudaGetSymbolAddress((void**)&Bl,     g_Bl);
    cudaGetSymbolAddress((void**)&rowptr, g_rowptr);
    cudaGetSymbolAddress((void**)&cnt,    g_cnt);
    cudaGetSymbolAddress((void**)&cursor, g_cursor);
    cudaGetSymbolAddress((void**)&col,    g_col);

    cudaFuncSetAttribute(gemm_mma, cudaFuncAttributeMaxDynamicSharedMemorySize, GEMM_SMEM);

    // ---- CSR build ----
    cudaMemsetAsync(cnt, 0, N * sizeof(int));
    {
        int tot = E + N;
        int blocks = (tot + 255) / 256;
        count_k<<<blocks, 256>>>(ei + E, E, N, cnt);
        scan_k<<<1, 1024>>>(cnt, rowptr, N);
        cudaMemcpyAsync(cursor, rowptr, N * sizeof(int), cudaMemcpyDeviceToDevice);
        fill_k<<<blocks, 256>>>(ei, ei + E, E, N, cursor, col);
    }

    // ---- 3 GAT layers ----
    const float* xin = x;
    int K = F_IN;
    float* outs[3] = {xb0, xb1, (float*)d_out};
    for (int l = 0; l < 3; ++l) {
        int C = Cc[l], HC = H * C;
        {
            int total = N * K;
            split_k<<<(total + 255) / 256, 256>>>(xin, Ah, Al, total);
        }
        {
            dim3 g(HC / 32, K / 32), b(32, 8);
            tsplitW_k<<<g, b>>>(W[l], Bh, Bl, K, HC);
        }
        {
            dim3 g(HC / 128, (N + 127) / 128);
            gemm_mma<<<g, 256, GEMM_SMEM>>>(Ah, Al, Bh, Bl, hbuf, N, HC, K);
        }
        logits_k<<<N, 32 * H>>>(hbuf, AS[l], AD[l], esrc, edst, H, C);
        aggregate_k<<<N, 256>>>(hbuf, esrc, edst, rowptr, col, B[l], outs[l],
                                H, C, HC, 1.0f / (float)H);
        xin = outs[l];
        K = C;
    }
}

// round 4
// speedup vs baseline: 2.0641x; 1.3544x over previous
#include <cuda_runtime.h>
#include <cuda_bf16.h>
#include <cstdint>

// ---------------------------------------------------------------------------
// GAT (3 layers, H=4 heads, concat=False/mean) for B200 (base sm_100 PTX).
// Per layer:
//   0) split x -> bf16 hi/lo (layer 0 only; layers 1,2 fused into aggregate)
//      transpose+split W -> [HC][K] bf16 hi/lo
//   1) warp-mma bf16 GEMM (3-pass hi/lo split, fp32 accum): h = x @ W
//   2) logits e_src/e_dst = <h, a>
//   3) per-dst softmax + weighted gather-sum via CSR (float4/thread),
//      mean heads + bias, fused bf16 split of the result
// ---------------------------------------------------------------------------

#define N_MAX   10240
#define K_MAXD  512
#define HC_MAX  1024
#define C_MAX   256
#define H_MAX   8
#define ET_MAX  204800

__device__ __align__(128) float g_h[(size_t)N_MAX * HC_MAX];
__device__ __align__(128) float g_xb0[(size_t)N_MAX * C_MAX];
__device__ __align__(128) float g_xb1[(size_t)N_MAX * C_MAX];
__device__ __align__(128) float g_esrc[N_MAX * H_MAX];
__device__ __align__(128) float g_edst[N_MAX * H_MAX];
__device__ __align__(128) __nv_bfloat16 g_Ah[(size_t)N_MAX * K_MAXD];
__device__ __align__(128) __nv_bfloat16 g_Al[(size_t)N_MAX * K_MAXD];
__device__ __align__(128) __nv_bfloat16 g_Bh[(size_t)HC_MAX * K_MAXD];
__device__ __align__(128) __nv_bfloat16 g_Bl[(size_t)HC_MAX * K_MAXD];
__device__ int g_rowptr[N_MAX + 1];
__device__ int g_cnt[N_MAX];
__device__ int g_cursor[N_MAX];
__device__ int g_col[ET_MAX];

// ======================= helpers ==========================================
__device__ __forceinline__ uint32_t smem_u32(const void* p) {
    uint32_t a;
    asm("{ .reg .u64 t; cvta.to.shared.u64 t, %1; cvt.u32.u64 %0, t; }" : "=r"(a) : "l"(p));
    return a;
}

__device__ __forceinline__ void cp16(uint32_t saddr, const void* gaddr, int srcbytes) {
    asm volatile("cp.async.cg.shared.global [%0], [%1], 16, %2;"
                 :: "r"(saddr), "l"(gaddr), "r"(srcbytes) : "memory");
}
__device__ __forceinline__ void cp_commit() {
    asm volatile("cp.async.commit_group;" ::: "memory");
}
template <int NN>
__device__ __forceinline__ void cp_wait() {
    asm volatile("cp.async.wait_group %0;" :: "n"(NN) : "memory");
}

__device__ __forceinline__ void ldsm4(uint32_t* r, uint32_t addr) {
    asm volatile("ldmatrix.sync.aligned.m8n8.x4.shared.b16 {%0,%1,%2,%3}, [%4];"
                 : "=r"(r[0]), "=r"(r[1]), "=r"(r[2]), "=r"(r[3]) : "r"(addr));
}

__device__ __forceinline__ void mma16816(float* d, const uint32_t* a, const uint32_t* b) {
    asm volatile(
        "mma.sync.aligned.m16n8k16.row.col.f32.bf16.bf16.f32 "
        "{%0,%1,%2,%3}, {%4,%5,%6,%7}, {%8,%9}, {%0,%1,%2,%3};"
        : "+f"(d[0]), "+f"(d[1]), "+f"(d[2]), "+f"(d[3])
        : "r"(a[0]), "r"(a[1]), "r"(a[2]), "r"(a[3]), "r"(b[0]), "r"(b[1]));
}

// ======================= split / transpose kernels =========================
__global__ void split_k(const float* __restrict__ X, __nv_bfloat16* __restrict__ Ah,
                        __nv_bfloat16* __restrict__ Al, int total) {
    int i = blockIdx.x * blockDim.x + threadIdx.x;
    if (i < total) {
        float v = X[i];
        __nv_bfloat16 hi = __float2bfloat16(v);
        Ah[i] = hi;
        Al[i] = __float2bfloat16(v - __bfloat162float(hi));
    }
}

// W [K][HC] row-major -> Bt hi/lo [HC][K]
__global__ void tsplitW_k(const float* __restrict__ W, __nv_bfloat16* __restrict__ Bh,
                          __nv_bfloat16* __restrict__ Bl, int K, int HC) {
    __shared__ float t[32][33];
    int kb = blockIdx.y * 32, nb = blockIdx.x * 32;
    int tx = threadIdx.x, ty = threadIdx.y;   // 32 x 8
    for (int i = ty; i < 32; i += 8)
        t[i][tx] = W[(size_t)(kb + i) * HC + nb + tx];
    __syncthreads();
    for (int i = ty; i < 32; i += 8) {
        float v = t[tx][i];
        __nv_bfloat16 hi = __float2bfloat16(v);
        size_t o = (size_t)(nb + i) * K + kb + tx;
        Bh[o] = hi;
        Bl[o] = __float2bfloat16(v - __bfloat162float(hi));
    }
}

// ======================= warp-mma GEMM =====================================
// C[M, HC] = A[M,K] @ W[K,HC]. A hi/lo [M][K], B hi/lo [HC][K] (K-major).
// Block 256 thr (8 warps 4x2), tile 128x128, BK=32, double-buffered cp.async.
#define GEMM_SMEM 65536

__global__ __launch_bounds__(256, 1)
void gemm_mma(const __nv_bfloat16* __restrict__ Ah, const __nv_bfloat16* __restrict__ Al,
              const __nv_bfloat16* __restrict__ Bh, const __nv_bfloat16* __restrict__ Bl,
              float* __restrict__ C, int M, int Ncols, int K) {
    extern __shared__ __align__(1024) char smem[];
    const uint32_t sbase = smem_u32(smem);
    const int tid = threadIdx.x;
    const int lane = tid & 31, wid = tid >> 5;
    const int warp_m = wid & 3;
    const int warp_n = wid >> 2;
    const int mtile = blockIdx.y, ntile = blockIdx.x;
    const int g = lane >> 3, r = lane & 7;

    float acc[2][8][4] = {};
    const int nch = K >> 5;   // BK=32

    auto load_stage = [&](int buf, int ch) {
        const int kb = ch << 5;
        const uint32_t sb = sbase + buf * 32768;
#pragma unroll
        for (int j = 0; j < 2; ++j) {
            int chunk = tid + (j << 8);
            int m = chunk >> 2, k16 = chunk & 3;
            uint32_t soff = m * 64 + ((k16 ^ ((m >> 1) & 3)) << 4);
            int arow = mtile * 128 + m;
            int aval = (arow < M) ? 16 : 0;
            int ar = (arow < M) ? arow : (M - 1);
            size_t aoff = (size_t)ar * K + kb + k16 * 8;
            cp16(sb + soff,          Ah + aoff, aval);
            cp16(sb + 8192 + soff,   Al + aoff, aval);
            int brow = ntile * 128 + m;
            size_t boff = (size_t)brow * K + kb + k16 * 8;
            cp16(sb + 16384 + soff,  Bh + boff, 16);
            cp16(sb + 24576 + soff,  Bl + boff, 16);
        }
    };

    load_stage(0, 0);
    cp_commit();

    for (int ch = 0; ch < nch; ++ch) {
        const int nxt = ch + 1;
        if (nxt < nch) { load_stage(nxt & 1, nxt); cp_commit(); }
        if (nxt < nch) cp_wait<1>(); else cp_wait<0>();
        __syncthreads();

        const uint32_t sb = sbase + (ch & 1) * 32768;
#pragma unroll
        for (int ks = 0; ks < 2; ++ks) {
            uint32_t ahf[2][4], alf[2][4], bhf[8][2], blf[8][2];
#pragma unroll
            for (int mt = 0; mt < 2; ++mt) {
                int ml = warp_m * 32 + mt * 16 + r + ((g & 1) << 3);
                int k16 = ks * 2 + (g >> 1);
                uint32_t ad = sb + ml * 64 + ((k16 ^ ((ml >> 1) & 3)) << 4);
                ldsm4(ahf[mt], ad);
                ldsm4(alf[mt], ad + 8192);
            }
#pragma unroll
            for (int nt2 = 0; nt2 < 4; ++nt2) {
                int nl = warp_n * 64 + nt2 * 16 + r + ((g >> 1) << 3);
                int k16 = ks * 2 + (g & 1);
                uint32_t bd = sb + 16384 + nl * 64 + ((k16 ^ ((nl >> 1) & 3)) << 4);
                uint32_t tb[4];
                ldsm4(tb, bd);
                bhf[nt2 * 2][0] = tb[0]; bhf[nt2 * 2][1] = tb[1];
                bhf[nt2 * 2 + 1][0] = tb[2]; bhf[nt2 * 2 + 1][1] = tb[3];
                ldsm4(tb, bd + 8192);
                blf[nt2 * 2][0] = tb[0]; blf[nt2 * 2][1] = tb[1];
                blf[nt2 * 2 + 1][0] = tb[2]; blf[nt2 * 2 + 1][1] = tb[3];
            }
#pragma unroll
            for (int mt = 0; mt < 2; ++mt)
#pragma unroll
                for (int nt = 0; nt < 8; ++nt) {
                    mma16816(acc[mt][nt], ahf[mt], bhf[nt]);
                    mma16816(acc[mt][nt], ahf[mt], blf[nt]);
                    mma16816(acc[mt][nt], alf[mt], bhf[nt]);
                }
        }
        __syncthreads();
    }

#pragma unroll
    for (int mt = 0; mt < 2; ++mt) {
        int row0 = mtile * 128 + warp_m * 32 + mt * 16 + (lane >> 2);
#pragma unroll
        for (int nt = 0; nt < 8; ++nt) {
            int col = ntile * 128 + warp_n * 64 + nt * 8 + (lane & 3) * 2;
            if (row0 < M)
                *reinterpret_cast<float2*>(&C[(size_t)row0 * Ncols + col]) =
                    make_float2(acc[mt][nt][0], acc[mt][nt][1]);
            if (row0 + 8 < M)
                *reinterpret_cast<float2*>(&C[(size_t)(row0 + 8) * Ncols + col]) =
                    make_float2(acc[mt][nt][2], acc[mt][nt][3]);
        }
    }
}

// ======================= CSR build =========================================
__global__ void count_k(const int* __restrict__ dst, int E, int n, int* __restrict__ cnt) {
    int i = blockIdx.x * blockDim.x + threadIdx.x;
    int tot = E + n;
    if (i < tot) {
        int d = (i < E) ? dst[i] : (i - E);
        atomicAdd(&cnt[d], 1);
    }
}

__global__ void scan_k(const int* __restrict__ cnt, int* __restrict__ rowptr, int n) {
    __shared__ int sh[1024];
    __shared__ int carry_sh;
    int tid = threadIdx.x;
    if (tid == 0) carry_sh = 0;
    __syncthreads();
    for (int base = 0; base < n; base += 1024) {
        int cin = carry_sh;
        int v = (base + tid < n) ? cnt[base + tid] : 0;
        sh[tid] = v;
        __syncthreads();
#pragma unroll
        for (int off = 1; off < 1024; off <<= 1) {
            int t = (tid >= off) ? sh[tid - off] : 0;
            __syncthreads();
            sh[tid] += t;
            __syncthreads();
        }
        if (base + tid < n) rowptr[base + tid] = cin + sh[tid] - v;
        __syncthreads();
        if (tid == 0) carry_sh = cin + sh[1023];
        __syncthreads();
    }
    if (tid == 0) rowptr[n] = carry_sh;
}

__global__ void fill_k(const int* __restrict__ src, const int* __restrict__ dst,
                       int E, int n, int* __restrict__ cursor, int* __restrict__ col) {
    int i = blockIdx.x * blockDim.x + threadIdx.x;
    int tot = E + n;
    if (i < tot) {
        int s, d;
        if (i < E) { s = src[i]; d = dst[i]; }
        else       { s = d = i - E; }
        int pos = atomicAdd(&cursor[d], 1);
        col[pos] = s;
    }
}

// ======================= logits ============================================
__global__ void logits_k(const float* __restrict__ hbuf,
                         const float* __restrict__ asrc, const float* __restrict__ adst,
                         float* __restrict__ esrc, float* __restrict__ edst,
                         int H, int C) {
    int n = blockIdx.x;
    int wid = threadIdx.x >> 5, lane = threadIdx.x & 31;
    if (wid >= H) return;
    const float* hp = hbuf + (size_t)n * H * C + (size_t)wid * C;
    const float* as = asrc + (size_t)wid * C;
    const float* ad = adst + (size_t)wid * C;
    float s1 = 0.f, s2 = 0.f;
    for (int c = lane; c < C; c += 32) {
        float v = hp[c];
        s1 += v * as[c];
        s2 += v * ad[c];
    }
#pragma unroll
    for (int o = 16; o > 0; o >>= 1) {
        s1 += __shfl_xor_sync(0xffffffffu, s1, o);
        s2 += __shfl_xor_sync(0xffffffffu, s2, o);
    }
    if (lane == 0) {
        esrc[n * H + wid] = s1;
        edst[n * H + wid] = s2;
    }
}

// ======================= aggregation =======================================
// Block = 256 threads, one block per dst node.
// Thread t owns head hh = t/(C/4), channels 4*(t%(C/4))..+3 -> one LDG.128
// per edge. Cross-head reduction via smem at the end. Fused bf16 hi/lo split
// of the output (next layer's GEMM A operand).
#define AGG_CAP 128

__global__ __launch_bounds__(256)
void aggregate_k(const float* __restrict__ hbuf,
                 const float* __restrict__ esrc, const float* __restrict__ edst,
                 const int* __restrict__ rowptr, const int* __restrict__ col,
                 const float* __restrict__ bias, float* __restrict__ out,
                 __nv_bfloat16* __restrict__ ah, __nv_bfloat16* __restrict__ al,
                 int write_split, int H, int C, int HC, float invH) {
    __shared__ float sh_m[H_MAX];
    __shared__ float sh_dinv[H_MAX];
    __shared__ float w_sh[AGG_CAP * H_MAX];
    __shared__ int col_sh[AGG_CAP];
    __shared__ float red_sh[HC_MAX];

    const int n = blockIdx.x;
    const int tid = threadIdx.x;
    const int wid = tid >> 5, lane = tid & 31;
    const int start = rowptr[n], end = rowptr[n + 1];

    // ---- softmax stats (warps 0..H-1, one head each) ----
    float edh = 0.f;
    if (wid < H) {
        edh = edst[n * H + wid];
        float mx = -1e30f;
        for (int e = start + lane; e < end; e += 32) {
            float v = esrc[col[e] * H + wid] + edh;
            v = v > 0.f ? v : 0.2f * v;
            mx = fmaxf(mx, v);
        }
#pragma unroll
        for (int o = 16; o > 0; o >>= 1) mx = fmaxf(mx, __shfl_xor_sync(0xffffffffu, mx, o));
        float sum = 0.f;
        for (int e = start + lane; e < end; e += 32) {
            float v = esrc[col[e] * H + wid] + edh;
            v = v > 0.f ? v : 0.2f * v;
            sum += __expf(v - mx);
        }
#pragma unroll
        for (int o = 16; o > 0; o >>= 1) sum += __shfl_xor_sync(0xffffffffu, sum, o);
        if (lane == 0) {
            sh_m[wid] = mx;
            sh_dinv[wid] = 1.f / (sum + 1e-16f);
        }
    }
    __syncthreads();

    // ---- channel ownership: one float4 per thread per edge ----
    const int qph = C >> 2;           // threads per head
    const int hh = tid / qph;         // head index
    const int q = tid - hh * qph;     // quad index within head
    const int base = hh * C + (q << 2);
    const bool act = (hh < H);

    float ax = 0.f, ay = 0.f, az = 0.f, aw = 0.f;

    for (int cb = start; cb < end; cb += AGG_CAP) {
        int cnt = end - cb;
        if (cnt > AGG_CAP) cnt = AGG_CAP;
        if (wid < H) {
            float m = sh_m[wid], dinv = sh_dinv[wid];
            for (int e = lane; e < cnt; e += 32) {
                int s = col[cb + e];
                if (wid == 0) col_sh[e] = s;
                float v = esrc[s * H + wid] + edh;
                v = v > 0.f ? v : 0.2f * v;
                w_sh[e * H + wid] = __expf(v - m) * dinv;
            }
        }
        __syncthreads();
        if (act) {
#pragma unroll 4
            for (int e = 0; e < cnt; ++e) {
                const float4 v = *reinterpret_cast<const float4*>(
                    hbuf + (size_t)col_sh[e] * HC + base);
                const float w = w_sh[e * H + hh];
                ax += w * v.x; ay += w * v.y; az += w * v.z; aw += w * v.w;
            }
        }
        __syncthreads();
    }

    // ---- cross-head reduction ----
    if (act)
        *reinterpret_cast<float4*>(red_sh + base) = make_float4(ax, ay, az, aw);
    __syncthreads();

    const int c = tid;
    if (c < C) {
        float s = 0.f;
#pragma unroll 4
        for (int h = 0; h < H; ++h) s += red_sh[h * C + c];
        float val = s * invH + bias[c];
        out[(size_t)n * C + c] = val;
        if (write_split) {
            __nv_bfloat16 hi = __float2bfloat16(val);
            ah[(size_t)n * C + c] = hi;
            al[(size_t)n * C + c] = __float2bfloat16(val - __bfloat162float(hi));
        }
    }
}

// ======================= host launcher =====================================
extern "C" void kernel_launch(void* const* d_in, const int* in_sizes, int n_in,
                              void* d_out, int out_size) {
    const float* x  = (const float*)d_in[0];
    const int*   ei = (const int*)d_in[1];
    const float* W[3]  = {(const float*)d_in[2],  (const float*)d_in[6],  (const float*)d_in[10]};
    const float* AS[3] = {(const float*)d_in[3],  (const float*)d_in[7],  (const float*)d_in[11]};
    const float* AD[3] = {(const float*)d_in[4],  (const float*)d_in[8],  (const float*)d_in[12]};
    const float* B[3]  = {(const float*)d_in[5],  (const float*)d_in[9],  (const float*)d_in[13]};

    const int Cc[3] = {in_sizes[5], in_sizes[9], in_sizes[13]};
    const int H = in_sizes[3] / Cc[0];
    const int E = in_sizes[1] / 2;
    const int N = out_size / Cc[2];
    const int F_IN = in_sizes[0] / N;

    float *hbuf, *xb0, *xb1, *esrc, *edst;
    __nv_bfloat16 *Ah, *Al, *Bh, *Bl;
    int *rowptr, *cnt, *cursor, *col;
    cudaGetSymbolAddress((void**)&hbuf,   g_h);
    cudaGetSymbolAddress((void**)&xb0,    g_xb0);
    cudaGetSymbolAddress((void**)&xb1,    g_xb1);
    cudaGetSymbolAddress((void**)&esrc,   g_esrc);
    cudaGetSymbolAddress((void**)&edst,   g_edst);
    cudaGetSymbolAddress((void**)&Ah,     g_Ah);
    cudaGetSymbolAddress((void**)&Al,     g_Al);
    cudaGetSymbolAddress((void**)&Bh,     g_Bh);
    cudaGetSymbolAddress((void**)&Bl,     g_Bl);
    cudaGetSymbolAddress((void**)&rowptr, g_rowptr);
    cudaGetSymbolAddress((void**)&cnt,    g_cnt);
    cudaGetSymbolAddress((void**)&cursor, g_cursor);
    cudaGetSymbolAddress((void**)&col,    g_col);

    cudaFuncSetAttribute(gemm_mma, cudaFuncAttributeMaxDynamicSharedMemorySize, GEMM_SMEM);

    // ---- CSR build ----
    cudaMemsetAsync(cnt, 0, N * sizeof(int));
    {
        int tot = E + N;
        int blocks = (tot + 255) / 256;
        count_k<<<blocks, 256>>>(ei + E, E, N, cnt);
        scan_k<<<1, 1024>>>(cnt, rowptr, N);
        cudaMemcpyAsync(cursor, rowptr, N * sizeof(int), cudaMemcpyDeviceToDevice);
        fill_k<<<blocks, 256>>>(ei, ei + E, E, N, cursor, col);
    }

    // ---- 3 GAT layers ----
    int K = F_IN;
    float* outs[3] = {xb0, xb1, (float*)d_out};
    for (int l = 0; l < 3; ++l) {
        int C = Cc[l], HC = H * C;
        if (l == 0) {
            int total = N * K;
            split_k<<<(total + 255) / 256, 256>>>(x, Ah, Al, total);
        }
        {
            dim3 g(HC / 32, K / 32), b(32, 8);
            tsplitW_k<<<g, b>>>(W[l], Bh, Bl, K, HC);
        }
        {
            dim3 g(HC / 128, (N + 127) / 128);
            gemm_mma<<<g, 256, GEMM_SMEM>>>(Ah, Al, Bh, Bl, hbuf, N, HC, K);
        }
        logits_k<<<N, 32 * H>>>(hbuf, AS[l], AD[l], esrc, edst, H, C);
        aggregate_k<<<N, 256>>>(hbuf, esrc, edst, rowptr, col, B[l], outs[l],
                                Ah, Al, (l < 2) ? 1 : 0, H, C, HC, 1.0f / (float)H);
        K = C;
    }
}

// round 5
// speedup vs baseline: 2.1147x; 1.0245x over previous
#include <cuda_runtime.h>
#include <cuda_bf16.h>
#include <cstdint>

// ---------------------------------------------------------------------------
// GAT (3 layers, H=4 heads, concat=False/mean) for B200 (base sm_100 PTX).
// Per layer:
//   0) split x -> bf16 hi/lo (layer 0 only; layers 1,2 fused into aggregate)
//      transpose+split W -> [HC][K] bf16 hi/lo
//   1) warp-mma bf16 GEMM (3-pass hi/lo split, fp32 accum): h = x @ W
//      + fused attention logits (atomicAdd partial dots into esrc/edst)
//   2) per-dst softmax + weighted gather-sum via CSR (float4/thread),
//      mean heads + bias, fused bf16 split of the result
// ---------------------------------------------------------------------------

#define N_MAX   10240
#define K_MAXD  512
#define HC_MAX  1024
#define C_MAX   256
#define H_MAX   8
#define ET_MAX  204800

__device__ __align__(128) float g_h[(size_t)N_MAX * HC_MAX];
__device__ __align__(128) float g_xb0[(size_t)N_MAX * C_MAX];
__device__ __align__(128) float g_xb1[(size_t)N_MAX * C_MAX];
__device__ __align__(128) float g_esrc[N_MAX * H_MAX];
__device__ __align__(128) float g_edst[N_MAX * H_MAX];
__device__ __align__(128) __nv_bfloat16 g_Ah[(size_t)N_MAX * K_MAXD];
__device__ __align__(128) __nv_bfloat16 g_Al[(size_t)N_MAX * K_MAXD];
__device__ __align__(128) __nv_bfloat16 g_Bh[(size_t)HC_MAX * K_MAXD];
__device__ __align__(128) __nv_bfloat16 g_Bl[(size_t)HC_MAX * K_MAXD];
__device__ int g_rowptr[N_MAX + 1];
__device__ int g_cnt[N_MAX];
__device__ int g_cursor[N_MAX];
__device__ int g_col[ET_MAX];

// ======================= helpers ==========================================
__device__ __forceinline__ uint32_t smem_u32(const void* p) {
    uint32_t a;
    asm("{ .reg .u64 t; cvta.to.shared.u64 t, %1; cvt.u32.u64 %0, t; }" : "=r"(a) : "l"(p));
    return a;
}

__device__ __forceinline__ void cp16(uint32_t saddr, const void* gaddr, int srcbytes) {
    asm volatile("cp.async.cg.shared.global [%0], [%1], 16, %2;"
                 :: "r"(saddr), "l"(gaddr), "r"(srcbytes) : "memory");
}
__device__ __forceinline__ void cp_commit() {
    asm volatile("cp.async.commit_group;" ::: "memory");
}
template <int NN>
__device__ __forceinline__ void cp_wait() {
    asm volatile("cp.async.wait_group %0;" :: "n"(NN) : "memory");
}

__device__ __forceinline__ void ldsm4(uint32_t* r, uint32_t addr) {
    asm volatile("ldmatrix.sync.aligned.m8n8.x4.shared.b16 {%0,%1,%2,%3}, [%4];"
                 : "=r"(r[0]), "=r"(r[1]), "=r"(r[2]), "=r"(r[3]) : "r"(addr));
}

__device__ __forceinline__ void mma16816(float* d, const uint32_t* a, const uint32_t* b) {
    asm volatile(
        "mma.sync.aligned.m16n8k16.row.col.f32.bf16.bf16.f32 "
        "{%0,%1,%2,%3}, {%4,%5,%6,%7}, {%8,%9}, {%0,%1,%2,%3};"
        : "+f"(d[0]), "+f"(d[1]), "+f"(d[2]), "+f"(d[3])
        : "r"(a[0]), "r"(a[1]), "r"(a[2]), "r"(a[3]), "r"(b[0]), "r"(b[1]));
}

// ======================= split / transpose kernels =========================
__global__ void split_k(const float* __restrict__ X, __nv_bfloat16* __restrict__ Ah,
                        __nv_bfloat16* __restrict__ Al, int total) {
    int i = blockIdx.x * blockDim.x + threadIdx.x;
    if (i < total) {
        float v = X[i];
        __nv_bfloat16 hi = __float2bfloat16(v);
        Ah[i] = hi;
        Al[i] = __float2bfloat16(v - __bfloat162float(hi));
    }
}

// W [K][HC] row-major -> Bt hi/lo [HC][K]
__global__ void tsplitW_k(const float* __restrict__ W, __nv_bfloat16* __restrict__ Bh,
                          __nv_bfloat16* __restrict__ Bl, int K, int HC) {
    __shared__ float t[32][33];
    int kb = blockIdx.y * 32, nb = blockIdx.x * 32;
    int tx = threadIdx.x, ty = threadIdx.y;   // 32 x 8
    for (int i = ty; i < 32; i += 8)
        t[i][tx] = W[(size_t)(kb + i) * HC + nb + tx];
    __syncthreads();
    for (int i = ty; i < 32; i += 8) {
        float v = t[tx][i];
        __nv_bfloat16 hi = __float2bfloat16(v);
        size_t o = (size_t)(nb + i) * K + kb + tx;
        Bh[o] = hi;
        Bl[o] = __float2bfloat16(v - __bfloat162float(hi));
    }
}

// ======================= warp-mma GEMM + fused logits ======================
// C[M, HC] = A[M,K] @ W[K,HC]. A hi/lo [M][K], B hi/lo [HC][K] (K-major).
// Block 256 thr (8 warps 4x2), tile 128x128, BK=32, 3-stage cp.async.
// Epilogue also accumulates esrc/edst partial dots via atomics.
#define GEMM_SMEM 98304

__global__ __launch_bounds__(256, 1)
void gemm_mma(const __nv_bfloat16* __restrict__ Ah, const __nv_bfloat16* __restrict__ Al,
              const __nv_bfloat16* __restrict__ Bh, const __nv_bfloat16* __restrict__ Bl,
              float* __restrict__ C, const float* __restrict__ as_g,
              const float* __restrict__ ad_g, float* __restrict__ esrc,
              float* __restrict__ edst, int M, int Ncols, int K, int Cc, int H) {
    extern __shared__ __align__(1024) char smem[];
    const uint32_t sbase = smem_u32(smem);
    const int tid = threadIdx.x;
    const int lane = tid & 31, wid = tid >> 5;
    const int warp_m = wid & 3;
    const int warp_n = wid >> 2;
    const int mtile = blockIdx.y, ntile = blockIdx.x;
    const int g = lane >> 3, r = lane & 7;

    float acc[2][8][4] = {};
    const int nch = K >> 5;   // BK=32

    auto load_stage = [&](int buf, int ch) {
        const int kb = ch << 5;
        const uint32_t sb = sbase + buf * 32768;
#pragma unroll
        for (int j = 0; j < 2; ++j) {
            int chunk = tid + (j << 8);
            int m = chunk >> 2, k16 = chunk & 3;
            uint32_t soff = m * 64 + ((k16 ^ ((m >> 1) & 3)) << 4);
            int arow = mtile * 128 + m;
            int aval = (arow < M) ? 16 : 0;
            int ar = (arow < M) ? arow : (M - 1);
            size_t aoff = (size_t)ar * K + kb + k16 * 8;
            cp16(sb + soff,          Ah + aoff, aval);
            cp16(sb + 8192 + soff,   Al + aoff, aval);
            int brow = ntile * 128 + m;
            size_t boff = (size_t)brow * K + kb + k16 * 8;
            cp16(sb + 16384 + soff,  Bh + boff, 16);
            cp16(sb + 24576 + soff,  Bl + boff, 16);
        }
    };

    // prime 2 stages
    load_stage(0, 0); cp_commit();
    if (nch > 1) { load_stage(1, 1); } cp_commit();

    int buf = 0;
    for (int ch = 0; ch < nch; ++ch) {
        const int pf = ch + 2;
        if (pf < nch) load_stage((pf >= 3) ? (pf - 3 - 3 * ((pf - 3) / 3)) : pf, pf);
        cp_commit();                 // empty group when nothing loaded keeps count
        cp_wait<2>();
        __syncthreads();

        const uint32_t sb = sbase + buf * 32768;
#pragma unroll
        for (int ks = 0; ks < 2; ++ks) {
            uint32_t ahf[2][4], alf[2][4], bhf[8][2], blf[8][2];
#pragma unroll
            for (int mt = 0; mt < 2; ++mt) {
                int ml = warp_m * 32 + mt * 16 + r + ((g & 1) << 3);
                int k16 = ks * 2 + (g >> 1);
                uint32_t ad = sb + ml * 64 + ((k16 ^ ((ml >> 1) & 3)) << 4);
                ldsm4(ahf[mt], ad);
                ldsm4(alf[mt], ad + 8192);
            }
#pragma unroll
            for (int nt2 = 0; nt2 < 4; ++nt2) {
                int nl = warp_n * 64 + nt2 * 16 + r + ((g >> 1) << 3);
                int k16 = ks * 2 + (g & 1);
                uint32_t bd = sb + 16384 + nl * 64 + ((k16 ^ ((nl >> 1) & 3)) << 4);
                uint32_t tb[4];
                ldsm4(tb, bd);
                bhf[nt2 * 2][0] = tb[0]; bhf[nt2 * 2][1] = tb[1];
                bhf[nt2 * 2 + 1][0] = tb[2]; bhf[nt2 * 2 + 1][1] = tb[3];
                ldsm4(tb, bd + 8192);
                blf[nt2 * 2][0] = tb[0]; blf[nt2 * 2][1] = tb[1];
                blf[nt2 * 2 + 1][0] = tb[2]; blf[nt2 * 2 + 1][1] = tb[3];
            }
#pragma unroll
            for (int mt = 0; mt < 2; ++mt)
#pragma unroll
                for (int nt = 0; nt < 8; ++nt) {
                    mma16816(acc[mt][nt], ahf[mt], bhf[nt]);
                    mma16816(acc[mt][nt], ahf[mt], blf[nt]);
                    mma16816(acc[mt][nt], alf[mt], bhf[nt]);
                }
        }
        __syncthreads();
        buf = (buf == 2) ? 0 : buf + 1;
    }

    // ---- epilogue 1: store C ----
#pragma unroll
    for (int mt = 0; mt < 2; ++mt) {
        int row0 = mtile * 128 + warp_m * 32 + mt * 16 + (lane >> 2);
#pragma unroll
        for (int nt = 0; nt < 8; ++nt) {
            int col = ntile * 128 + warp_n * 64 + nt * 8 + (lane & 3) * 2;
            if (row0 < M)
                *reinterpret_cast<float2*>(&C[(size_t)row0 * Ncols + col]) =
                    make_float2(acc[mt][nt][0], acc[mt][nt][1]);
            if (row0 + 8 < M)
                *reinterpret_cast<float2*>(&C[(size_t)(row0 + 8) * Ncols + col]) =
                    make_float2(acc[mt][nt][2], acc[mt][nt][3]);
        }
    }

    // ---- epilogue 2: fused logits partial dots ----
    // (all cols of this warp's 64-col span lie in one head: Cc >= 64, 64 | Cc)
    float es[4] = {0.f, 0.f, 0.f, 0.f}, ed[4] = {0.f, 0.f, 0.f, 0.f};
#pragma unroll
    for (int nt = 0; nt < 8; ++nt) {
        int col = ntile * 128 + warp_n * 64 + nt * 8 + (lane & 3) * 2;
        float a0 = as_g[col], a1 = as_g[col + 1];
        float d0 = ad_g[col], d1 = ad_g[col + 1];
#pragma unroll
        for (int mt = 0; mt < 2; ++mt) {
            es[mt * 2 + 0] += acc[mt][nt][0] * a0 + acc[mt][nt][1] * a1;
            es[mt * 2 + 1] += acc[mt][nt][2] * a0 + acc[mt][nt][3] * a1;
            ed[mt * 2 + 0] += acc[mt][nt][0] * d0 + acc[mt][nt][1] * d1;
            ed[mt * 2 + 1] += acc[mt][nt][2] * d0 + acc[mt][nt][3] * d1;
        }
    }
#pragma unroll
    for (int o = 1; o <= 2; o <<= 1)
#pragma unroll
        for (int i = 0; i < 4; ++i) {
            es[i] += __shfl_xor_sync(0xffffffffu, es[i], o);
            ed[i] += __shfl_xor_sync(0xffffffffu, ed[i], o);
        }
    if ((lane & 3) == 0) {
        int hh = (ntile * 128 + warp_n * 64) / Cc;
#pragma unroll
        for (int mt = 0; mt < 2; ++mt) {
            int row = mtile * 128 + warp_m * 32 + mt * 16 + (lane >> 2);
            if (row < M) {
                atomicAdd(&esrc[row * H + hh], es[mt * 2 + 0]);
                atomicAdd(&edst[row * H + hh], ed[mt * 2 + 0]);
            }
            if (row + 8 < M) {
                atomicAdd(&esrc[(row + 8) * H + hh], es[mt * 2 + 1]);
                atomicAdd(&edst[(row + 8) * H + hh], ed[mt * 2 + 1]);
            }
        }
    }
}

// ======================= CSR build =========================================
__global__ void count_k(const int* __restrict__ dst, int E, int n, int* __restrict__ cnt) {
    int i = blockIdx.x * blockDim.x + threadIdx.x;
    int tot = E + n;
    if (i < tot) {
        int d = (i < E) ? dst[i] : (i - E);
        atomicAdd(&cnt[d], 1);
    }
}

__global__ void scan_k(const int* __restrict__ cnt, int* __restrict__ rowptr, int n) {
    __shared__ int sh[1024];
    __shared__ int carry_sh;
    int tid = threadIdx.x;
    if (tid == 0) carry_sh = 0;
    __syncthreads();
    for (int base = 0; base < n; base += 1024) {
        int cin = carry_sh;
        int v = (base + tid < n) ? cnt[base + tid] : 0;
        sh[tid] = v;
        __syncthreads();
#pragma unroll
        for (int off = 1; off < 1024; off <<= 1) {
            int t = (tid >= off) ? sh[tid - off] : 0;
            __syncthreads();
            sh[tid] += t;
            __syncthreads();
        }
        if (base + tid < n) rowptr[base + tid] = cin + sh[tid] - v;
        __syncthreads();
        if (tid == 0) carry_sh = cin + sh[1023];
        __syncthreads();
    }
    if (tid == 0) rowptr[n] = carry_sh;
}

__global__ void fill_k(const int* __restrict__ src, const int* __restrict__ dst,
                       int E, int n, int* __restrict__ cursor, int* __restrict__ col) {
    int i = blockIdx.x * blockDim.x + threadIdx.x;
    int tot = E + n;
    if (i < tot) {
        int s, d;
        if (i < E) { s = src[i]; d = dst[i]; }
        else       { s = d = i - E; }
        int pos = atomicAdd(&cursor[d], 1);
        col[pos] = s;
    }
}

// ======================= aggregation =======================================
#define AGG_CAP 128

__global__ __launch_bounds__(256)
void aggregate_k(const float* __restrict__ hbuf,
                 const float* __restrict__ esrc, const float* __restrict__ edst,
                 const int* __restrict__ rowptr, const int* __restrict__ col,
                 const float* __restrict__ bias, float* __restrict__ out,
                 __nv_bfloat16* __restrict__ ah, __nv_bfloat16* __restrict__ al,
                 int write_split, int H, int C, int HC, float invH) {
    __shared__ float sh_m[H_MAX];
    __shared__ float sh_dinv[H_MAX];
    __shared__ float w_sh[AGG_CAP * H_MAX];
    __shared__ int col_sh[AGG_CAP];
    __shared__ float red_sh[HC_MAX];

    const int n = blockIdx.x;
    const int tid = threadIdx.x;
    const int wid = tid >> 5, lane = tid & 31;
    const int start = rowptr[n], end = rowptr[n + 1];

    float edh = 0.f;
    if (wid < H) {
        edh = edst[n * H + wid];
        float mx = -1e30f;
        for (int e = start + lane; e < end; e += 32) {
            float v = esrc[col[e] * H + wid] + edh;
            v = v > 0.f ? v : 0.2f * v;
            mx = fmaxf(mx, v);
        }
#pragma unroll
        for (int o = 16; o > 0; o >>= 1) mx = fmaxf(mx, __shfl_xor_sync(0xffffffffu, mx, o));
        float sum = 0.f;
        for (int e = start + lane; e < end; e += 32) {
            float v = esrc[col[e] * H + wid] + edh;
            v = v > 0.f ? v : 0.2f * v;
            sum += __expf(v - mx);
        }
#pragma unroll
        for (int o = 16; o > 0; o >>= 1) sum += __shfl_xor_sync(0xffffffffu, sum, o);
        if (lane == 0) {
            sh_m[wid] = mx;
            sh_dinv[wid] = 1.f / (sum + 1e-16f);
        }
    }
    __syncthreads();

    const int qph = C >> 2;
    const int hh = tid / qph;
    const int q = tid - hh * qph;
    const int base = hh * C + (q << 2);
    const bool act = (hh < H);

    float ax = 0.f, ay = 0.f, az = 0.f, aw = 0.f;

    for (int cb = start; cb < end; cb += AGG_CAP) {
        int cnt = end - cb;
        if (cnt > AGG_CAP) cnt = AGG_CAP;
        if (wid < H) {
            float m = sh_m[wid], dinv = sh_dinv[wid];
            for (int e = lane; e < cnt; e += 32) {
                int s = col[cb + e];
                if (wid == 0) col_sh[e] = s;
                float v = esrc[s * H + wid] + edh;
                v = v > 0.f ? v : 0.2f * v;
                w_sh[e * H + wid] = __expf(v - m) * dinv;
            }
        }
        __syncthreads();
        if (act) {
#pragma unroll 4
            for (int e = 0; e < cnt; ++e) {
                const float4 v = *reinterpret_cast<const float4*>(
                    hbuf + (size_t)col_sh[e] * HC + base);
                const float w = w_sh[e * H + hh];
                ax += w * v.x; ay += w * v.y; az += w * v.z; aw += w * v.w;
            }
        }
        __syncthreads();
    }

    if (act)
        *reinterpret_cast<float4*>(red_sh + base) = make_float4(ax, ay, az, aw);
    __syncthreads();

    const int c = tid;
    if (c < C) {
        float s = 0.f;
#pragma unroll 4
        for (int h = 0; h < H; ++h) s += red_sh[h * C + c];
        float val = s * invH + bias[c];
        out[(size_t)n * C + c] = val;
        if (write_split) {
            __nv_bfloat16 hi = __float2bfloat16(val);
            ah[(size_t)n * C + c] = hi;
            al[(size_t)n * C + c] = __float2bfloat16(val - __bfloat162float(hi));
        }
    }
}

// ======================= host launcher =====================================
extern "C" void kernel_launch(void* const* d_in, const int* in_sizes, int n_in,
                              void* d_out, int out_size) {
    const float* x  = (const float*)d_in[0];
    const int*   ei = (const int*)d_in[1];
    const float* W[3]  = {(const float*)d_in[2],  (const float*)d_in[6],  (const float*)d_in[10]};
    const float* AS[3] = {(const float*)d_in[3],  (const float*)d_in[7],  (const float*)d_in[11]};
    const float* AD[3] = {(const float*)d_in[4],  (const float*)d_in[8],  (const float*)d_in[12]};
    const float* B[3]  = {(const float*)d_in[5],  (const float*)d_in[9],  (const float*)d_in[13]};

    const int Cc[3] = {in_sizes[5], in_sizes[9], in_sizes[13]};
    const int H = in_sizes[3] / Cc[0];
    const int E = in_sizes[1] / 2;
    const int N = out_size / Cc[2];
    const int F_IN = in_sizes[0] / N;

    float *hbuf, *xb0, *xb1, *esrc, *edst;
    __nv_bfloat16 *Ah, *Al, *Bh, *Bl;
    int *rowptr, *cnt, *cursor, *col;
    cudaGetSymbolAddress((void**)&hbuf,   g_h);
    cudaGetSymbolAddress((void**)&xb0,    g_xb0);
    cudaGetSymbolAddress((void**)&xb1,    g_xb1);
    cudaGetSymbolAddress((void**)&esrc,   g_esrc);
    cudaGetSymbolAddress((void**)&edst,   g_edst);
    cudaGetSymbolAddress((void**)&Ah,     g_Ah);
    cudaGetSymbolAddress((void**)&Al,     g_Al);
    cudaGetSymbolAddress((void**)&Bh,     g_Bh);
    cudaGetSymbolAddress((void**)&Bl,     g_Bl);
    cudaGetSymbolAddress((void**)&rowptr, g_rowptr);
    cudaGetSymbolAddress((void**)&cnt,    g_cnt);
    cudaGetSymbolAddress((void**)&cursor, g_cursor);
    cudaGetSymbolAddress((void**)&col,    g_col);

    cudaFuncSetAttribute(gemm_mma, cudaFuncAttributeMaxDynamicSharedMemorySize, GEMM_SMEM);

    int K = F_IN;
    float* outs[3] = {xb0, xb1, (float*)d_out};

    for (int l = 0; l < 3; ++l) {
        int C = Cc[l], HC = H * C;

        if (l == 0) {
            // Launch order chosen so layer-0 gemm_mma is the 6th op (ncu -s 5 -c 1).
            int total = N * K;
            split_k<<<(total + 255) / 256, 256>>>(x, Ah, Al, total);         // 1
        }
        {
            dim3 gr(HC / 32, K / 32), b(32, 8);
            tsplitW_k<<<gr, b>>>(W[l], Bh, Bl, K, HC);                       // 2
        }
        if (l == 0) cudaMemsetAsync(cnt, 0, N * sizeof(int));                // 3
        cudaMemsetAsync(esrc, 0, N * H * sizeof(float));                     // 4
        cudaMemsetAsync(edst, 0, N * H * sizeof(float));                     // 5
        {
            dim3 gr(HC / 128, (N + 127) / 128);
            gemm_mma<<<gr, 256, GEMM_SMEM>>>(Ah, Al, Bh, Bl, hbuf,           // 6 <- ncu
                                             AS[l], AD[l], esrc, edst,
                                             N, HC, K, C, H);
        }
        if (l == 0) {
            int tot = E + N;
            int blocks = (tot + 255) / 256;
            count_k<<<blocks, 256>>>(ei + E, E, N, cnt);
            scan_k<<<1, 1024>>>(cnt, rowptr, N);
            cudaMemcpyAsync(cursor, rowptr, N * sizeof(int), cudaMemcpyDeviceToDevice);
            fill_k<<<blocks, 256>>>(ei, ei + E, E, N, cursor, col);
        }
        aggregate_k<<<N, 256>>>(hbuf, esrc, edst, rowptr, col, B[l], outs[l],
                                Ah, Al, (l < 2) ? 1 : 0, H, C, HC, 1.0f / (float)H);
        K = C;
    }
}

// round 6
// speedup vs baseline: 2.2048x; 1.0426x over previous
#include <cuda_runtime.h>
#include <cuda_bf16.h>
#include <cuda_fp16.h>
#include <cstdint>

// ---------------------------------------------------------------------------
// GAT (3 layers, H=4 heads, concat=False/mean) for B200 (base sm_100 PTX).
// Per layer:
//   0) split x -> bf16 hi/lo (layer 0 only; layers 1,2 fused into aggregate)
//      transpose+split W -> [HC][K] bf16 hi/lo
//   1) warp-mma bf16 GEMM (3-pass hi/lo split, fp32 accum): h = x @ W
//      epilogue: h stored as fp16 (half2), fused attention logits via atomics
//   2) per-dst softmax + weighted gather-sum via CSR (half2 loads),
//      mean heads + bias, fused bf16 split of the result
// ---------------------------------------------------------------------------

#define N_MAX   10240
#define K_MAXD  512
#define HC_MAX  1024
#define C_MAX   256
#define H_MAX   8
#define ET_MAX  204800

__device__ __align__(128) __half g_h[(size_t)N_MAX * HC_MAX];
__device__ __align__(128) float g_esrc[N_MAX * H_MAX];
__device__ __align__(128) float g_edst[N_MAX * H_MAX];
__device__ __align__(128) __nv_bfloat16 g_Ah[(size_t)N_MAX * K_MAXD];
__device__ __align__(128) __nv_bfloat16 g_Al[(size_t)N_MAX * K_MAXD];
__device__ __align__(128) __nv_bfloat16 g_Bh[(size_t)HC_MAX * K_MAXD];
__device__ __align__(128) __nv_bfloat16 g_Bl[(size_t)HC_MAX * K_MAXD];
__device__ int g_rowptr[N_MAX + 1];
__device__ int g_cnt[N_MAX];
__device__ int g_cursor[N_MAX];
__device__ int g_col[ET_MAX];

// ======================= helpers ==========================================
__device__ __forceinline__ uint32_t smem_u32(const void* p) {
    uint32_t a;
    asm("{ .reg .u64 t; cvta.to.shared.u64 t, %1; cvt.u32.u64 %0, t; }" : "=r"(a) : "l"(p));
    return a;
}

__device__ __forceinline__ void cp16(uint32_t saddr, const void* gaddr, int srcbytes) {
    asm volatile("cp.async.cg.shared.global [%0], [%1], 16, %2;"
                 :: "r"(saddr), "l"(gaddr), "r"(srcbytes) : "memory");
}
__device__ __forceinline__ void cp_commit() {
    asm volatile("cp.async.commit_group;" ::: "memory");
}
template <int NN>
__device__ __forceinline__ void cp_wait() {
    asm volatile("cp.async.wait_group %0;" :: "n"(NN) : "memory");
}

__device__ __forceinline__ void ldsm4(uint32_t* r, uint32_t addr) {
    asm volatile("ldmatrix.sync.aligned.m8n8.x4.shared.b16 {%0,%1,%2,%3}, [%4];"
                 : "=r"(r[0]), "=r"(r[1]), "=r"(r[2]), "=r"(r[3]) : "r"(addr));
}

__device__ __forceinline__ void mma16816(float* d, const uint32_t* a, const uint32_t* b) {
    asm volatile(
        "mma.sync.aligned.m16n8k16.row.col.f32.bf16.bf16.f32 "
        "{%0,%1,%2,%3}, {%4,%5,%6,%7}, {%8,%9}, {%0,%1,%2,%3};"
        : "+f"(d[0]), "+f"(d[1]), "+f"(d[2]), "+f"(d[3])
        : "r"(a[0]), "r"(a[1]), "r"(a[2]), "r"(a[3]), "r"(b[0]), "r"(b[1]));
}

// ======================= split / transpose kernels =========================
__global__ void split_k(const float* __restrict__ X, __nv_bfloat16* __restrict__ Ah,
                        __nv_bfloat16* __restrict__ Al, int total) {
    int i = blockIdx.x * blockDim.x + threadIdx.x;
    if (i < total) {
        float v = X[i];
        __nv_bfloat16 hi = __float2bfloat16(v);
        Ah[i] = hi;
        Al[i] = __float2bfloat16(v - __bfloat162float(hi));
    }
}

// W [K][HC] row-major -> Bt hi/lo [HC][K]
__global__ void tsplitW_k(const float* __restrict__ W, __nv_bfloat16* __restrict__ Bh,
                          __nv_bfloat16* __restrict__ Bl, int K, int HC) {
    __shared__ float t[32][33];
    int kb = blockIdx.y * 32, nb = blockIdx.x * 32;
    int tx = threadIdx.x, ty = threadIdx.y;   // 32 x 8
    for (int i = ty; i < 32; i += 8)
        t[i][tx] = W[(size_t)(kb + i) * HC + nb + tx];
    __syncthreads();
    for (int i = ty; i < 32; i += 8) {
        float v = t[tx][i];
        __nv_bfloat16 hi = __float2bfloat16(v);
        size_t o = (size_t)(nb + i) * K + kb + tx;
        Bh[o] = hi;
        Bl[o] = __float2bfloat16(v - __bfloat162float(hi));
    }
}

// ======================= warp-mma GEMM + fused logits ======================
// C[M, HC] = A[M,K] @ W[K,HC]. Output h stored as fp16. Block 256 thr
// (8 warps 4x2), tile 128x128, BK=32, double-buffered cp.async.
#define GEMM_SMEM 65536

__global__ __launch_bounds__(256, 1)
void gemm_mma(const __nv_bfloat16* __restrict__ Ah, const __nv_bfloat16* __restrict__ Al,
              const __nv_bfloat16* __restrict__ Bh, const __nv_bfloat16* __restrict__ Bl,
              __half* __restrict__ C, const float* __restrict__ as_g,
              const float* __restrict__ ad_g, float* __restrict__ esrc,
              float* __restrict__ edst, int M, int Ncols, int K, int Cc, int H) {
    extern __shared__ __align__(1024) char smem[];
    const uint32_t sbase = smem_u32(smem);
    const int tid = threadIdx.x;
    const int lane = tid & 31, wid = tid >> 5;
    const int warp_m = wid & 3;
    const int warp_n = wid >> 2;
    const int mtile = blockIdx.y, ntile = blockIdx.x;
    const int g = lane >> 3, r = lane & 7;

    float acc[2][8][4] = {};
    const int nch = K >> 5;   // BK=32

    auto load_stage = [&](int buf, int ch) {
        const int kb = ch << 5;
        const uint32_t sb = sbase + buf * 32768;
#pragma unroll
        for (int j = 0; j < 2; ++j) {
            int chunk = tid + (j << 8);
            int m = chunk >> 2, k16 = chunk & 3;
            uint32_t soff = m * 64 + ((k16 ^ ((m >> 1) & 3)) << 4);
            int arow = mtile * 128 + m;
            int aval = (arow < M) ? 16 : 0;
            int ar = (arow < M) ? arow : (M - 1);
            size_t aoff = (size_t)ar * K + kb + k16 * 8;
            cp16(sb + soff,          Ah + aoff, aval);
            cp16(sb + 8192 + soff,   Al + aoff, aval);
            int brow = ntile * 128 + m;
            size_t boff = (size_t)brow * K + kb + k16 * 8;
            cp16(sb + 16384 + soff,  Bh + boff, 16);
            cp16(sb + 24576 + soff,  Bl + boff, 16);
        }
    };

    load_stage(0, 0);
    cp_commit();

    for (int ch = 0; ch < nch; ++ch) {
        const int nxt = ch + 1;
        if (nxt < nch) { load_stage(nxt & 1, nxt); cp_commit(); }
        if (nxt < nch) cp_wait<1>(); else cp_wait<0>();
        __syncthreads();

        const uint32_t sb = sbase + (ch & 1) * 32768;
#pragma unroll
        for (int ks = 0; ks < 2; ++ks) {
            uint32_t ahf[2][4], alf[2][4], bhf[8][2], blf[8][2];
#pragma unroll
            for (int mt = 0; mt < 2; ++mt) {
                int ml = warp_m * 32 + mt * 16 + r + ((g & 1) << 3);
                int k16 = ks * 2 + (g >> 1);
                uint32_t ad = sb + ml * 64 + ((k16 ^ ((ml >> 1) & 3)) << 4);
                ldsm4(ahf[mt], ad);
                ldsm4(alf[mt], ad + 8192);
            }
#pragma unroll
            for (int nt2 = 0; nt2 < 4; ++nt2) {
                int nl = warp_n * 64 + nt2 * 16 + r + ((g >> 1) << 3);
                int k16 = ks * 2 + (g & 1);
                uint32_t bd = sb + 16384 + nl * 64 + ((k16 ^ ((nl >> 1) & 3)) << 4);
                uint32_t tb[4];
                ldsm4(tb, bd);
                bhf[nt2 * 2][0] = tb[0]; bhf[nt2 * 2][1] = tb[1];
                bhf[nt2 * 2 + 1][0] = tb[2]; bhf[nt2 * 2 + 1][1] = tb[3];
                ldsm4(tb, bd + 8192);
                blf[nt2 * 2][0] = tb[0]; blf[nt2 * 2][1] = tb[1];
                blf[nt2 * 2 + 1][0] = tb[2]; blf[nt2 * 2 + 1][1] = tb[3];
            }
#pragma unroll
            for (int mt = 0; mt < 2; ++mt)
#pragma unroll
                for (int nt = 0; nt < 8; ++nt) {
                    mma16816(acc[mt][nt], ahf[mt], bhf[nt]);
                    mma16816(acc[mt][nt], ahf[mt], blf[nt]);
                    mma16816(acc[mt][nt], alf[mt], bhf[nt]);
                }
        }
        __syncthreads();
    }

    // ---- epilogue 1: store C as fp16 ----
#pragma unroll
    for (int mt = 0; mt < 2; ++mt) {
        int row0 = mtile * 128 + warp_m * 32 + mt * 16 + (lane >> 2);
#pragma unroll
        for (int nt = 0; nt < 8; ++nt) {
            int col = ntile * 128 + warp_n * 64 + nt * 8 + (lane & 3) * 2;
            if (row0 < M)
                *reinterpret_cast<__half2*>(&C[(size_t)row0 * Ncols + col]) =
                    __floats2half2_rn(acc[mt][nt][0], acc[mt][nt][1]);
            if (row0 + 8 < M)
                *reinterpret_cast<__half2*>(&C[(size_t)(row0 + 8) * Ncols + col]) =
                    __floats2half2_rn(acc[mt][nt][2], acc[mt][nt][3]);
        }
    }

    // ---- epilogue 2: fused logits partial dots (fp32-exact) ----
    float es[4] = {0.f, 0.f, 0.f, 0.f}, ed[4] = {0.f, 0.f, 0.f, 0.f};
#pragma unroll
    for (int nt = 0; nt < 8; ++nt) {
        int col = ntile * 128 + warp_n * 64 + nt * 8 + (lane & 3) * 2;
        float a0 = as_g[col], a1 = as_g[col + 1];
        float d0 = ad_g[col], d1 = ad_g[col + 1];
#pragma unroll
        for (int mt = 0; mt < 2; ++mt) {
            es[mt * 2 + 0] += acc[mt][nt][0] * a0 + acc[mt][nt][1] * a1;
            es[mt * 2 + 1] += acc[mt][nt][2] * a0 + acc[mt][nt][3] * a1;
            ed[mt * 2 + 0] += acc[mt][nt][0] * d0 + acc[mt][nt][1] * d1;
            ed[mt * 2 + 1] += acc[mt][nt][2] * d0 + acc[mt][nt][3] * d1;
        }
    }
#pragma unroll
    for (int o = 1; o <= 2; o <<= 1)
#pragma unroll
        for (int i = 0; i < 4; ++i) {
            es[i] += __shfl_xor_sync(0xffffffffu, es[i], o);
            ed[i] += __shfl_xor_sync(0xffffffffu, ed[i], o);
        }
    if ((lane & 3) == 0) {
        int hh = (ntile * 128 + warp_n * 64) / Cc;
#pragma unroll
        for (int mt = 0; mt < 2; ++mt) {
            int row = mtile * 128 + warp_m * 32 + mt * 16 + (lane >> 2);
            if (row < M) {
                atomicAdd(&esrc[row * H + hh], es[mt * 2 + 0]);
                atomicAdd(&edst[row * H + hh], ed[mt * 2 + 0]);
            }
            if (row + 8 < M) {
                atomicAdd(&esrc[(row + 8) * H + hh], es[mt * 2 + 1]);
                atomicAdd(&edst[(row + 8) * H + hh], ed[mt * 2 + 1]);
            }
        }
    }
}

// ======================= CSR build =========================================
__global__ void count_k(const int* __restrict__ dst, int E, int n, int* __restrict__ cnt) {
    int i = blockIdx.x * blockDim.x + threadIdx.x;
    int tot = E + n;
    if (i < tot) {
        int d = (i < E) ? dst[i] : (i - E);
        atomicAdd(&cnt[d], 1);
    }
}

__global__ void scan_k(const int* __restrict__ cnt, int* __restrict__ rowptr, int n) {
    __shared__ int sh[1024];
    __shared__ int carry_sh;
    int tid = threadIdx.x;
    if (tid == 0) carry_sh = 0;
    __syncthreads();
    for (int base = 0; base < n; base += 1024) {
        int cin = carry_sh;
        int v = (base + tid < n) ? cnt[base + tid] : 0;
        sh[tid] = v;
        __syncthreads();
#pragma unroll
        for (int off = 1; off < 1024; off <<= 1) {
            int t = (tid >= off) ? sh[tid - off] : 0;
            __syncthreads();
            sh[tid] += t;
            __syncthreads();
        }
        if (base + tid < n) rowptr[base + tid] = cin + sh[tid] - v;
        __syncthreads();
        if (tid == 0) carry_sh = cin + sh[1023];
        __syncthreads();
    }
    if (tid == 0) rowptr[n] = carry_sh;
}

__global__ void fill_k(const int* __restrict__ src, const int* __restrict__ dst,
                       int E, int n, int* __restrict__ cursor, int* __restrict__ col) {
    int i = blockIdx.x * blockDim.x + threadIdx.x;
    int tot = E + n;
    if (i < tot) {
        int s, d;
        if (i < E) { s = src[i]; d = dst[i]; }
        else       { s = d = i - E; }
        int pos = atomicAdd(&cursor[d], 1);
        col[pos] = s;
    }
}

// ======================= aggregation =======================================
// One block (256 thr) per dst node. Thread t: head hh=t/(C/4), 4 channels ->
// one 8B half2x2 load per edge. Unnormalized exp weights in smem; dinv folded
// into the final scale. Fused bf16 hi/lo split of the output.
#define AGG_CAP 128

__global__ __launch_bounds__(256)
void aggregate_k(const __half* __restrict__ hbuf,
                 const float* __restrict__ esrc, const float* __restrict__ edst,
                 const int* __restrict__ rowptr, const int* __restrict__ col,
                 const float* __restrict__ bias, float* __restrict__ out,
                 __nv_bfloat16* __restrict__ ah, __nv_bfloat16* __restrict__ al,
                 int write_out, int H, int C, int HC, float invH) {
    __shared__ float sh_m[H_MAX];
    __shared__ float sh_dinv[H_MAX];
    __shared__ float w_sh[AGG_CAP * H_MAX];
    __shared__ int col_sh[AGG_CAP];
    __shared__ float red_sh[HC_MAX];

    const int n = blockIdx.x;
    const int tid = threadIdx.x;
    const int wid = tid >> 5, lane = tid & 31;
    const int start = rowptr[n], end = rowptr[n + 1];

    float edh = 0.f;
    if (wid < H) {
        edh = edst[n * H + wid];
        float mx = -1e30f;
        for (int e = start + lane; e < end; e += 32) {
            float v = esrc[col[e] * H + wid] + edh;
            v = v > 0.f ? v : 0.2f * v;
            mx = fmaxf(mx, v);
        }
#pragma unroll
        for (int o = 16; o > 0; o >>= 1) mx = fmaxf(mx, __shfl_xor_sync(0xffffffffu, mx, o));
        float sum = 0.f;
        for (int e = start + lane; e < end; e += 32) {
            float v = esrc[col[e] * H + wid] + edh;
            v = v > 0.f ? v : 0.2f * v;
            sum += __expf(v - mx);
        }
#pragma unroll
        for (int o = 16; o > 0; o >>= 1) sum += __shfl_xor_sync(0xffffffffu, sum, o);
        if (lane == 0) {
            sh_m[wid] = mx;
            sh_dinv[wid] = 1.f / (sum + 1e-16f);
        }
    }
    __syncthreads();

    const int qph = C >> 2;
    const int hh = tid / qph;
    const int q = tid - hh * qph;
    const int base = hh * C + (q << 2);
    const bool act = (hh < H);

    float ax = 0.f, ay = 0.f, az = 0.f, aw = 0.f;

    for (int cb = start; cb < end; cb += AGG_CAP) {
        int cnt = end - cb;
        if (cnt > AGG_CAP) cnt = AGG_CAP;
        if (wid < H) {
            float m = sh_m[wid];
            for (int e = lane; e < cnt; e += 32) {
                int s = col[cb + e];
                if (wid == 0) col_sh[e] = s;
                float v = esrc[s * H + wid] + edh;
                v = v > 0.f ? v : 0.2f * v;
                w_sh[e * H + wid] = __expf(v - m);   // unnormalized
            }
        }
        __syncthreads();
        if (act) {
#pragma unroll 4
            for (int e = 0; e < cnt; ++e) {
                const uint2 pv = *reinterpret_cast<const uint2*>(
                    hbuf + (size_t)col_sh[e] * HC + base);
                const float w = w_sh[e * H + hh];
                const float2 v01 = __half22float2(*reinterpret_cast<const __half2*>(&pv.x));
                const float2 v23 = __half22float2(*reinterpret_cast<const __half2*>(&pv.y));
                ax += w * v01.x; ay += w * v01.y; az += w * v23.x; aw += w * v23.y;
            }
        }
        __syncthreads();
    }

    if (act) {
        const float dinv = sh_dinv[hh];
        *reinterpret_cast<float4*>(red_sh + base) =
            make_float4(ax * dinv, ay * dinv, az * dinv, aw * dinv);
    }
    __syncthreads();

    const int c = tid;
    if (c < C) {
        float s = 0.f;
#pragma unroll 4
        for (int h = 0; h < H; ++h) s += red_sh[h * C + c];
        float val = s * invH + bias[c];
        if (write_out) {
            out[(size_t)n * C + c] = val;
        } else {
            __nv_bfloat16 hi = __float2bfloat16(val);
            ah[(size_t)n * C + c] = hi;
            al[(size_t)n * C + c] = __float2bfloat16(val - __bfloat162float(hi));
        }
    }
}

// ======================= host launcher =====================================
extern "C" void kernel_launch(void* const* d_in, const int* in_sizes, int n_in,
                              void* d_out, int out_size) {
    const float* x  = (const float*)d_in[0];
    const int*   ei = (const int*)d_in[1];
    const float* W[3]  = {(const float*)d_in[2],  (const float*)d_in[6],  (const float*)d_in[10]};
    const float* AS[3] = {(const float*)d_in[3],  (const float*)d_in[7],  (const float*)d_in[11]};
    const float* AD[3] = {(const float*)d_in[4],  (const float*)d_in[8],  (const float*)d_in[12]};
    const float* B[3]  = {(const float*)d_in[5],  (const float*)d_in[9],  (const float*)d_in[13]};

    const int Cc[3] = {in_sizes[5], in_sizes[9], in_sizes[13]};
    const int H = in_sizes[3] / Cc[0];
    const int E = in_sizes[1] / 2;
    const int N = out_size / Cc[2];
    const int F_IN = in_sizes[0] / N;

    __half* hbuf;
    float *esrc, *edst;
    __nv_bfloat16 *Ah, *Al, *Bh, *Bl;
    int *rowptr, *cnt, *cursor, *col;
    cudaGetSymbolAddress((void**)&hbuf,   g_h);
    cudaGetSymbolAddress((void**)&esrc,   g_esrc);
    cudaGetSymbolAddress((void**)&edst,   g_edst);
    cudaGetSymbolAddress((void**)&Ah,     g_Ah);
    cudaGetSymbolAddress((void**)&Al,     g_Al);
    cudaGetSymbolAddress((void**)&Bh,     g_Bh);
    cudaGetSymbolAddress((void**)&Bl,     g_Bl);
    cudaGetSymbolAddress((void**)&rowptr, g_rowptr);
    cudaGetSymbolAddress((void**)&cnt,    g_cnt);
    cudaGetSymbolAddress((void**)&cursor, g_cursor);
    cudaGetSymbolAddress((void**)&col,    g_col);

    cudaFuncSetAttribute(gemm_mma, cudaFuncAttributeMaxDynamicSharedMemorySize, GEMM_SMEM);

    int K = F_IN;

    for (int l = 0; l < 3; ++l) {
        int C = Cc[l], HC = H * C;

        if (l == 0) {
            int total = N * K;
            split_k<<<(total + 255) / 256, 256>>>(x, Ah, Al, total);
        }
        {
            dim3 gr(HC / 32, K / 32), b(32, 8);
            tsplitW_k<<<gr, b>>>(W[l], Bh, Bl, K, HC);
        }
        if (l == 0) cudaMemsetAsync(cnt, 0, N * sizeof(int));
        cudaMemsetAsync(esrc, 0, N * H * sizeof(float));
        cudaMemsetAsync(edst, 0, N * H * sizeof(float));
        {
            dim3 gr(HC / 128, (N + 127) / 128);
            gemm_mma<<<gr, 256, GEMM_SMEM>>>(Ah, Al, Bh, Bl, hbuf,
                                             AS[l], AD[l], esrc, edst,
                                             N, HC, K, C, H);
        }
        if (l == 0) {
            int tot = E + N;
            int blocks = (tot + 255) / 256;
            count_k<<<blocks, 256>>>(ei + E, E, N, cnt);
            scan_k<<<1, 1024>>>(cnt, rowptr, N);
            cudaMemcpyAsync(cursor, rowptr, N * sizeof(int), cudaMemcpyDeviceToDevice);
            fill_k<<<blocks, 256>>>(ei, ei + E, E, N, cursor, col);
        }
        aggregate_k<<<N, 256>>>(hbuf, esrc, edst, rowptr, col, B[l], (float*)d_out,
                                Ah, Al, (l == 2) ? 1 : 0, H, C, HC, 1.0f / (float)H);
        K = C;
    }
}

// round 9
// speedup vs baseline: 2.5236x; 1.1446x over previous
#include <cuda_runtime.h>
#include <cuda_bf16.h>
#include <cuda_fp16.h>
#include <cstdint>

// ---------------------------------------------------------------------------
// GAT (3 layers, H=4 heads, concat=False/mean) for B200 (base sm_100 PTX).
// Per layer:
//   0) round x -> tf32 (layer 0 only; layers 1,2 fused into aggregate)
//      transpose+round W -> [HC][K] tf32
//   1) warp-mma tf32 GEMM (single pass, fp32 accum): h = x @ W
//      epilogue: h stored fp16, fused attention logits via atomics
//   2) per-dst softmax + weighted gather-sum via CSR (half2 loads),
//      mean heads + bias, fused tf32 rounding of the result
// ---------------------------------------------------------------------------

#define N_MAX   10240
#define K_MAXD  512
#define HC_MAX  1024
#define C_MAX   256
#define H_MAX   8
#define ET_MAX  204800

__device__ __align__(128) __half g_h[(size_t)N_MAX * HC_MAX];
__device__ __align__(128) float g_esrc[N_MAX * H_MAX];
__device__ __align__(128) float g_edst[N_MAX * H_MAX];
__device__ __align__(128) float g_At[(size_t)N_MAX * K_MAXD];     // tf32-rounded A
__device__ __align__(128) float g_Bt[(size_t)HC_MAX * K_MAXD];    // tf32-rounded W^T
__device__ int g_rowptr[N_MAX + 1];
__device__ int g_cnt[N_MAX];
__device__ int g_cursor[N_MAX];
__device__ int g_col[ET_MAX];

// ======================= helpers ==========================================
__device__ __forceinline__ uint32_t smem_u32(const void* p) {
    uint32_t a;
    asm("{ .reg .u64 t; cvta.to.shared.u64 t, %1; cvt.u32.u64 %0, t; }" : "=r"(a) : "l"(p));
    return a;
}

// cvt.rna.tf32.f32 writes a .b32 destination (NOT .f32) — use "=r".
__device__ __forceinline__ float to_tf32(float v) {
    uint32_t o;
    asm("cvt.rna.tf32.f32 %0, %1;" : "=r"(o) : "f"(v));
    return __uint_as_float(o);
}

__device__ __forceinline__ void cp16(uint32_t saddr, const void* gaddr, int srcbytes) {
    asm volatile("cp.async.cg.shared.global [%0], [%1], 16, %2;"
                 :: "r"(saddr), "l"(gaddr), "r"(srcbytes) : "memory");
}
__device__ __forceinline__ void cp_commit() {
    asm volatile("cp.async.commit_group;" ::: "memory");
}
template <int NN>
__device__ __forceinline__ void cp_wait() {
    asm volatile("cp.async.wait_group %0;" :: "n"(NN) : "memory");
}

__device__ __forceinline__ void ldsm4(uint32_t* r, uint32_t addr) {
    asm volatile("ldmatrix.sync.aligned.m8n8.x4.shared.b16 {%0,%1,%2,%3}, [%4];"
                 : "=r"(r[0]), "=r"(r[1]), "=r"(r[2]), "=r"(r[3]) : "r"(addr));
}

__device__ __forceinline__ void mma_tf32(float* d, const uint32_t* a, const uint32_t* b) {
    asm volatile(
        "mma.sync.aligned.m16n8k8.row.col.f32.tf32.tf32.f32 "
        "{%0,%1,%2,%3}, {%4,%5,%6,%7}, {%8,%9}, {%0,%1,%2,%3};"
        : "+f"(d[0]), "+f"(d[1]), "+f"(d[2]), "+f"(d[3])
        : "r"(a[0]), "r"(a[1]), "r"(a[2]), "r"(a[3]), "r"(b[0]), "r"(b[1]));
}

// ======================= pre-kernels =======================================
__global__ void round_k(const float* __restrict__ X, float* __restrict__ A, int total) {
    int i = blockIdx.x * blockDim.x + threadIdx.x;
    if (i < total) A[i] = to_tf32(X[i]);
}

// W [K][HC] row-major -> Bt [HC][K] tf32-rounded
__global__ void tW_k(const float* __restrict__ W, float* __restrict__ Bt, int K, int HC) {
    __shared__ float t[32][33];
    int kb = blockIdx.y * 32, nb = blockIdx.x * 32;
    int tx = threadIdx.x, ty = threadIdx.y;   // 32 x 8
    for (int i = ty; i < 32; i += 8)
        t[i][tx] = W[(size_t)(kb + i) * HC + nb + tx];
    __syncthreads();
    for (int i = ty; i < 32; i += 8)
        Bt[(size_t)(nb + i) * K + kb + tx] = to_tf32(t[tx][i]);
}

// ======================= warp-mma tf32 GEMM + fused logits =================
// C[M, HC] = A[M,K] @ W[K,HC]. A [M][K] fp32(tf32), B [HC][K] fp32(tf32).
// Block 256 thr (8 warps 4x2: warp tile 32x64), block tile 128x128, BK=32,
// double-buffered cp.async. Smem stage 32KB: A[128][32]f @0, B[128][32]f @16K.
// Swizzle: 16B chunk (4 floats) at soff(m,c) = m*128 + ((c ^ (m&7))<<4).
#define GEMM_SMEM 65536

__global__ __launch_bounds__(256, 1)
void gemm_mma(const float* __restrict__ At, const float* __restrict__ Bt,
              __half* __restrict__ C, const float* __restrict__ as_g,
              const float* __restrict__ ad_g, float* __restrict__ esrc,
              float* __restrict__ edst, int M, int Ncols, int K, int Cc, int H) {
    extern __shared__ __align__(1024) char smem[];
    const uint32_t sbase = smem_u32(smem);
    const int tid = threadIdx.x;
    const int lane = tid & 31, wid = tid >> 5;
    const int warp_m = wid & 3;
    const int warp_n = wid >> 2;
    const int mtile = blockIdx.y, ntile = blockIdx.x;
    const int g = lane >> 3, r = lane & 7;

    float acc[2][8][4] = {};
    const int nch = K >> 5;   // BK=32

    auto load_stage = [&](int buf, int ch) {
        const int kb = ch << 5;
        const uint32_t sb = sbase + buf * 32768;
#pragma unroll
        for (int j = 0; j < 4; ++j) {
            int chunk = tid + (j << 8);        // 0..1023
            int m = chunk >> 3, c = chunk & 7; // row, 16B chunk (4 floats)
            uint32_t soff = m * 128 + ((c ^ (m & 7)) << 4);
            int arow = mtile * 128 + m;
            int aval = (arow < M) ? 16 : 0;
            int ar = (arow < M) ? arow : (M - 1);
            cp16(sb + soff, At + (size_t)ar * K + kb + c * 4, aval);
            int brow = ntile * 128 + m;
            cp16(sb + 16384 + soff, Bt + (size_t)brow * K + kb + c * 4, 16);
        }
    };

    load_stage(0, 0);
    cp_commit();

    for (int ch = 0; ch < nch; ++ch) {
        const int nxt = ch + 1;
        if (nxt < nch) { load_stage(nxt & 1, nxt); cp_commit(); }
        if (nxt < nch) cp_wait<1>(); else cp_wait<0>();
        __syncthreads();

        const uint32_t sb = sbase + (ch & 1) * 32768;
#pragma unroll
        for (int k8 = 0; k8 < 4; ++k8) {
            const int c0 = k8 * 2;             // chunk pair for this k8
            uint32_t af[2][4], bf[8][2];
#pragma unroll
            for (int mt = 0; mt < 2; ++mt) {
                int ml = warp_m * 32 + mt * 16 + r + ((g & 1) << 3);
                int cc = c0 + (g >> 1);
                uint32_t ad = sb + ml * 128 + ((cc ^ (ml & 7)) << 4);
                ldsm4(af[mt], ad);
            }
#pragma unroll
            for (int nt2 = 0; nt2 < 4; ++nt2) {
                int nl = warp_n * 64 + nt2 * 16 + r + ((g >> 1) << 3);
                int cc = c0 + (g & 1);
                uint32_t bd = sb + 16384 + nl * 128 + ((cc ^ (nl & 7)) << 4);
                uint32_t tb[4];
                ldsm4(tb, bd);
                bf[nt2 * 2][0] = tb[0]; bf[nt2 * 2][1] = tb[1];
                bf[nt2 * 2 + 1][0] = tb[2]; bf[nt2 * 2 + 1][1] = tb[3];
            }
#pragma unroll
            for (int mt = 0; mt < 2; ++mt)
#pragma unroll
                for (int nt = 0; nt < 8; ++nt)
                    mma_tf32(acc[mt][nt], af[mt], bf[nt]);
        }
        __syncthreads();
    }

    // ---- epilogue 1: store C as fp16 ----
#pragma unroll
    for (int mt = 0; mt < 2; ++mt) {
        int row0 = mtile * 128 + warp_m * 32 + mt * 16 + (lane >> 2);
#pragma unroll
        for (int nt = 0; nt < 8; ++nt) {
            int col = ntile * 128 + warp_n * 64 + nt * 8 + (lane & 3) * 2;
            if (row0 < M)
                *reinterpret_cast<__half2*>(&C[(size_t)row0 * Ncols + col]) =
                    __floats2half2_rn(acc[mt][nt][0], acc[mt][nt][1]);
            if (row0 + 8 < M)
                *reinterpret_cast<__half2*>(&C[(size_t)(row0 + 8) * Ncols + col]) =
                    __floats2half2_rn(acc[mt][nt][2], acc[mt][nt][3]);
        }
    }

    // ---- epilogue 2: fused logits partial dots (fp32-exact) ----
    float es[4] = {0.f, 0.f, 0.f, 0.f}, ed[4] = {0.f, 0.f, 0.f, 0.f};
#pragma unroll
    for (int nt = 0; nt < 8; ++nt) {
        int col = ntile * 128 + warp_n * 64 + nt * 8 + (lane & 3) * 2;
        float a0 = as_g[col], a1 = as_g[col + 1];
        float d0 = ad_g[col], d1 = ad_g[col + 1];
#pragma unroll
        for (int mt = 0; mt < 2; ++mt) {
            es[mt * 2 + 0] += acc[mt][nt][0] * a0 + acc[mt][nt][1] * a1;
            es[mt * 2 + 1] += acc[mt][nt][2] * a0 + acc[mt][nt][3] * a1;
            ed[mt * 2 + 0] += acc[mt][nt][0] * d0 + acc[mt][nt][1] * d1;
            ed[mt * 2 + 1] += acc[mt][nt][2] * d0 + acc[mt][nt][3] * d1;
        }
    }
#pragma unroll
    for (int o = 1; o <= 2; o <<= 1)
#pragma unroll
        for (int i = 0; i < 4; ++i) {
            es[i] += __shfl_xor_sync(0xffffffffu, es[i], o);
            ed[i] += __shfl_xor_sync(0xffffffffu, ed[i], o);
        }
    if ((lane & 3) == 0) {
        int hh = (ntile * 128 + warp_n * 64) / Cc;
#pragma unroll
        for (int mt = 0; mt < 2; ++mt) {
            int row = mtile * 128 + warp_m * 32 + mt * 16 + (lane >> 2);
            if (row < M) {
                atomicAdd(&esrc[row * H + hh], es[mt * 2 + 0]);
                atomicAdd(&edst[row * H + hh], ed[mt * 2 + 0]);
            }
            if (row + 8 < M) {
                atomicAdd(&esrc[(row + 8) * H + hh], es[mt * 2 + 1]);
                atomicAdd(&edst[(row + 8) * H + hh], ed[mt * 2 + 1]);
            }
        }
    }
}

// ======================= CSR build =========================================
__global__ void count_k(const int* __restrict__ dst, int E, int n, int* __restrict__ cnt) {
    int i = blockIdx.x * blockDim.x + threadIdx.x;
    int tot = E + n;
    if (i < tot) {
        int d = (i < E) ? dst[i] : (i - E);
        atomicAdd(&cnt[d], 1);
    }
}

__global__ void scan_k(const int* __restrict__ cnt, int* __restrict__ rowptr, int n) {
    __shared__ int sh[1024];
    __shared__ int carry_sh;
    int tid = threadIdx.x;
    if (tid == 0) carry_sh = 0;
    __syncthreads();
    for (int base = 0; base < n; base += 1024) {
        int cin = carry_sh;
        int v = (base + tid < n) ? cnt[base + tid] : 0;
        sh[tid] = v;
        __syncthreads();
#pragma unroll
        for (int off = 1; off < 1024; off <<= 1) {
            int t = (tid >= off) ? sh[tid - off] : 0;
            __syncthreads();
            sh[tid] += t;
            __syncthreads();
        }
        if (base + tid < n) rowptr[base + tid] = cin + sh[tid] - v;
        __syncthreads();
        if (tid == 0) carry_sh = cin + sh[1023];
        __syncthreads();
    }
    if (tid == 0) rowptr[n] = carry_sh;
}

__global__ void fill_k(const int* __restrict__ src, const int* __restrict__ dst,
                       int E, int n, int* __restrict__ cursor, int* __restrict__ col) {
    int i = blockIdx.x * blockDim.x + threadIdx.x;
    int tot = E + n;
    if (i < tot) {
        int s, d;
        if (i < E) { s = src[i]; d = dst[i]; }
        else       { s = d = i - E; }
        int pos = atomicAdd(&cursor[d], 1);
        col[pos] = s;
    }
}

// ======================= aggregation =======================================
// One block (256 thr) per dst node. Thread t: head hh=t/(C/4), 4 channels ->
// one 8B load per edge. Unnormalized exp weights; dinv folded at the end.
// Output: fp32 (layer 2 -> d_out) or tf32-rounded fp32 (layers 0,1 -> g_At).
#define AGG_CAP 128

__global__ __launch_bounds__(256)
void aggregate_k(const __half* __restrict__ hbuf,
                 const float* __restrict__ esrc, const float* __restrict__ edst,
                 const int* __restrict__ rowptr, const int* __restrict__ col,
                 const float* __restrict__ bias, float* __restrict__ out,
                 float* __restrict__ anext, int write_out,
                 int H, int C, int HC, float invH) {
    __shared__ float sh_m[H_MAX];
    __shared__ float sh_dinv[H_MAX];
    __shared__ float w_sh[AGG_CAP * H_MAX];
    __shared__ int col_sh[AGG_CAP];
    __shared__ float red_sh[HC_MAX];

    const int n = blockIdx.x;
    const int tid = threadIdx.x;
    const int wid = tid >> 5, lane = tid & 31;
    const int start = rowptr[n], end = rowptr[n + 1];

    float edh = 0.f;
    if (wid < H) {
        edh = edst[n * H + wid];
        float mx = -1e30f;
        for (int e = start + lane; e < end; e += 32) {
            float v = esrc[col[e] * H + wid] + edh;
            v = v > 0.f ? v : 0.2f * v;
            mx = fmaxf(mx, v);
        }
#pragma unroll
        for (int o = 16; o > 0; o >>= 1) mx = fmaxf(mx, __shfl_xor_sync(0xffffffffu, mx, o));
        float sum = 0.f;
        for (int e = start + lane; e < end; e += 32) {
            float v = esrc[col[e] * H + wid] + edh;
            v = v > 0.f ? v : 0.2f * v;
            sum += __expf(v - mx);
        }
#pragma unroll
        for (int o = 16; o > 0; o >>= 1) sum += __shfl_xor_sync(0xffffffffu, sum, o);
        if (lane == 0) {
            sh_m[wid] = mx;
            sh_dinv[wid] = 1.f / (sum + 1e-16f);
        }
    }
    __syncthreads();

    const int qph = C >> 2;
    const int hh = tid / qph;
    const int q = tid - hh * qph;
    const int base = hh * C + (q << 2);
    const bool act = (hh < H);

    float ax = 0.f, ay = 0.f, az = 0.f, aw = 0.f;

    for (int cb = start; cb < end; cb += AGG_CAP) {
        int cnt = end - cb;
        if (cnt > AGG_CAP) cnt = AGG_CAP;
        if (wid < H) {
            float m = sh_m[wid];
            for (int e = lane; e < cnt; e += 32) {
                int s = col[cb + e];
                if (wid == 0) col_sh[e] = s;
                float v = esrc[s * H + wid] + edh;
                v = v > 0.f ? v : 0.2f * v;
                w_sh[e * H + wid] = __expf(v - m);   // unnormalized
            }
        }
        __syncthreads();
        if (act) {
#pragma unroll 4
            for (int e = 0; e < cnt; ++e) {
                const uint2 pv = *reinterpret_cast<const uint2*>(
                    hbuf + (size_t)col_sh[e] * HC + base);
                const float w = w_sh[e * H + hh];
                const float2 v01 = __half22float2(*reinterpret_cast<const __half2*>(&pv.x));
                const float2 v23 = __half22float2(*reinterpret_cast<const __half2*>(&pv.y));
                ax += w * v01.x; ay += w * v01.y; az += w * v23.x; aw += w * v23.y;
            }
        }
        __syncthreads();
    }

    if (act) {
        const float dinv = sh_dinv[hh];
        *reinterpret_cast<float4*>(red_sh + base) =
            make_float4(ax * dinv, ay * dinv, az * dinv, aw * dinv);
    }
    __syncthreads();

    const int c = tid;
    if (c < C) {
        float s = 0.f;
#pragma unroll 4
        for (int h = 0; h < H; ++h) s += red_sh[h * C + c];
        float val = s * invH + bias[c];
        if (write_out) out[(size_t)n * C + c] = val;
        else           anext[(size_t)n * C + c] = to_tf32(val);
    }
}

// ======================= host launcher =====================================
extern "C" void kernel_launch(void* const* d_in, const int* in_sizes, int n_in,
                              void* d_out, int out_size) {
    const float* x  = (const float*)d_in[0];
    const int*   ei = (const int*)d_in[1];
    const float* W[3]  = {(const float*)d_in[2],  (const float*)d_in[6],  (const float*)d_in[10]};
    const float* AS[3] = {(const float*)d_in[3],  (const float*)d_in[7],  (const float*)d_in[11]};
    const float* AD[3] = {(const float*)d_in[4],  (const float*)d_in[8],  (const float*)d_in[12]};
    const float* B[3]  = {(const float*)d_in[5],  (const float*)d_in[9],  (const float*)d_in[13]};

    const int Cc[3] = {in_sizes[5], in_sizes[9], in_sizes[13]};
    const int H = in_sizes[3] / Cc[0];
    const int E = in_sizes[1] / 2;
    const int N = out_size / Cc[2];
    const int F_IN = in_sizes[0] / N;

    __half* hbuf;
    float *esrc, *edst, *At, *Bt;
    int *rowptr, *cnt, *cursor, *col;
    cudaGetSymbolAddress((void**)&hbuf,   g_h);
    cudaGetSymbolAddress((void**)&esrc,   g_esrc);
    cudaGetSymbolAddress((void**)&edst,   g_edst);
    cudaGetSymbolAddress((void**)&At,     g_At);
    cudaGetSymbolAddress((void**)&Bt,     g_Bt);
    cudaGetSymbolAddress((void**)&rowptr, g_rowptr);
    cudaGetSymbolAddress((void**)&cnt,    g_cnt);
    cudaGetSymbolAddress((void**)&cursor, g_cursor);
    cudaGetSymbolAddress((void**)&col,    g_col);

    cudaFuncSetAttribute(gemm_mma, cudaFuncAttributeMaxDynamicSharedMemorySize, GEMM_SMEM);

    int K = F_IN;

    for (int l = 0; l < 3; ++l) {
        int C = Cc[l], HC = H * C;

        if (l == 0) {
            int total = N * K;
            round_k<<<(total + 255) / 256, 256>>>(x, At, total);
        }
        {
            dim3 gr(HC / 32, K / 32), b(32, 8);
            tW_k<<<gr, b>>>(W[l], Bt, K, HC);
        }
        if (l == 0) cudaMemsetAsync(cnt, 0, N * sizeof(int));
        cudaMemsetAsync(esrc, 0, N * H * sizeof(float));
        cudaMemsetAsync(edst, 0, N * H * sizeof(float));
        {
            dim3 gr(HC / 128, (N + 127) / 128);
            gemm_mma<<<gr, 256, GEMM_SMEM>>>(At, Bt, hbuf,
                                             AS[l], AD[l], esrc, edst,
                                             N, HC, K, C, H);
        }
        if (l == 0) {
            int tot = E + N;
            int blocks = (tot + 255) / 256;
            count_k<<<blocks, 256>>>(ei + E, E, N, cnt);
            scan_k<<<1, 1024>>>(cnt, rowptr, N);
            cudaMemcpyAsync(cursor, rowptr, N * sizeof(int), cudaMemcpyDeviceToDevice);
            fill_k<<<blocks, 256>>>(ei, ei + E, E, N, cursor, col);
        }
        aggregate_k<<<N, 256>>>(hbuf, esrc, edst, rowptr, col, B[l], (float*)d_out,
                                At, (l == 2) ? 1 : 0, H, C, HC, 1.0f / (float)H);
        K = C;
    }
}

// round 10
// speedup vs baseline: 2.7551x; 1.0917x over previous
#include <cuda_runtime.h>
#include <cuda_bf16.h>
#include <cuda_fp16.h>
#include <cstdint>

// ---------------------------------------------------------------------------
// GAT (3 layers, H=4 heads, concat=False/mean) for B200 (base sm_100 PTX).
// Per layer:
//   0) round x -> tf32 (layer 0 only; layers 1,2 fused into aggregate)
//      transpose+round W -> [HC][K] tf32
//   1) warp-mma tf32 GEMM (single pass, fp32 accum, 2 CTAs/SM): h = x @ W
//      epilogue: h stored fp16, fused attention logits via atomics
//   2) per-dst softmax + weighted gather-sum via CSR (half2 loads),
//      mean heads + bias, fused tf32 rounding of the result
// ---------------------------------------------------------------------------

#define N_MAX   10240
#define K_MAXD  512
#define HC_MAX  1024
#define C_MAX   256
#define H_MAX   8
#define ET_MAX  204800

__device__ __align__(128) __half g_h[(size_t)N_MAX * HC_MAX];
__device__ __align__(128) float g_esrc[N_MAX * H_MAX];
__device__ __align__(128) float g_edst[N_MAX * H_MAX];
__device__ __align__(128) float g_At[(size_t)N_MAX * K_MAXD];     // tf32-rounded A
__device__ __align__(128) float g_Bt[(size_t)HC_MAX * K_MAXD];    // tf32-rounded W^T
__device__ int g_rowptr[N_MAX + 1];
__device__ int g_cnt[N_MAX];
__device__ int g_cursor[N_MAX];
__device__ int g_col[ET_MAX];

// ======================= helpers ==========================================
__device__ __forceinline__ uint32_t smem_u32(const void* p) {
    uint32_t a;
    asm("{ .reg .u64 t; cvta.to.shared.u64 t, %1; cvt.u32.u64 %0, t; }" : "=r"(a) : "l"(p));
    return a;
}

// cvt.rna.tf32.f32 writes a .b32 destination (NOT .f32) — use "=r".
__device__ __forceinline__ float to_tf32(float v) {
    uint32_t o;
    asm("cvt.rna.tf32.f32 %0, %1;" : "=r"(o) : "f"(v));
    return __uint_as_float(o);
}

__device__ __forceinline__ void cp16(uint32_t saddr, const void* gaddr, int srcbytes) {
    asm volatile("cp.async.cg.shared.global [%0], [%1], 16, %2;"
                 :: "r"(saddr), "l"(gaddr), "r"(srcbytes) : "memory");
}
__device__ __forceinline__ void cp_commit() {
    asm volatile("cp.async.commit_group;" ::: "memory");
}
template <int NN>
__device__ __forceinline__ void cp_wait() {
    asm volatile("cp.async.wait_group %0;" :: "n"(NN) : "memory");
}

__device__ __forceinline__ void ldsm4(uint32_t* r, uint32_t addr) {
    asm volatile("ldmatrix.sync.aligned.m8n8.x4.shared.b16 {%0,%1,%2,%3}, [%4];"
                 : "=r"(r[0]), "=r"(r[1]), "=r"(r[2]), "=r"(r[3]) : "r"(addr));
}

__device__ __forceinline__ void mma_tf32(float* d, const uint32_t* a, const uint32_t* b) {
    asm volatile(
        "mma.sync.aligned.m16n8k8.row.col.f32.tf32.tf32.f32 "
        "{%0,%1,%2,%3}, {%4,%5,%6,%7}, {%8,%9}, {%0,%1,%2,%3};"
        : "+f"(d[0]), "+f"(d[1]), "+f"(d[2]), "+f"(d[3])
        : "r"(a[0]), "r"(a[1]), "r"(a[2]), "r"(a[3]), "r"(b[0]), "r"(b[1]));
}

// ======================= pre-kernels =======================================
__global__ void round_k(const float* __restrict__ X, float* __restrict__ A, int total) {
    int i = blockIdx.x * blockDim.x + threadIdx.x;
    if (i < total) A[i] = to_tf32(X[i]);
}

// W [K][HC] row-major -> Bt [HC][K] tf32-rounded
__global__ void tW_k(const float* __restrict__ W, float* __restrict__ Bt, int K, int HC) {
    __shared__ float t[32][33];
    int kb = blockIdx.y * 32, nb = blockIdx.x * 32;
    int tx = threadIdx.x, ty = threadIdx.y;   // 32 x 8
    for (int i = ty; i < 32; i += 8)
        t[i][tx] = W[(size_t)(kb + i) * HC + nb + tx];
    __syncthreads();
    for (int i = ty; i < 32; i += 8)
        Bt[(size_t)(nb + i) * K + kb + tx] = to_tf32(t[tx][i]);
}

// ======================= warp-mma tf32 GEMM + fused logits =================
// C[M, HC] = A[M,K] @ W[K,HC]. A [M][K] fp32(tf32), B [HC][K] fp32(tf32).
// Block 256 thr (8 warps 4x2: warp tile 32x64), block tile 128x128, BK=32,
// double-buffered cp.async, 2 CTAs/SM (cross-covers barrier bubbles).
// Smem stage 32KB: A[128][32]f @0, B[128][32]f @16K.
// Swizzle: 16B chunk (4 floats) at soff(m,c) = m*128 + ((c ^ (m&7))<<4).
#define GEMM_SMEM 65536

__global__ __launch_bounds__(256, 2)
void gemm_mma(const float* __restrict__ At, const float* __restrict__ Bt,
              __half* __restrict__ C, const float* __restrict__ as_g,
              const float* __restrict__ ad_g, float* __restrict__ esrc,
              float* __restrict__ edst, int M, int Ncols, int K, int Cc, int H) {
    extern __shared__ __align__(1024) char smem[];
    const uint32_t sbase = smem_u32(smem);
    const int tid = threadIdx.x;
    const int lane = tid & 31, wid = tid >> 5;
    const int warp_m = wid & 3;
    const int warp_n = wid >> 2;
    const int mtile = blockIdx.y, ntile = blockIdx.x;
    const int g = lane >> 3, r = lane & 7;

    float acc[2][8][4] = {};
    const int nch = K >> 5;   // BK=32

    auto load_stage = [&](int buf, int ch) {
        const int kb = ch << 5;
        const uint32_t sb = sbase + buf * 32768;
#pragma unroll
        for (int j = 0; j < 4; ++j) {
            int chunk = tid + (j << 8);        // 0..1023
            int m = chunk >> 3, c = chunk & 7; // row, 16B chunk (4 floats)
            uint32_t soff = m * 128 + ((c ^ (m & 7)) << 4);
            int arow = mtile * 128 + m;
            int aval = (arow < M) ? 16 : 0;
            int ar = (arow < M) ? arow : (M - 1);
            cp16(sb + soff, At + (size_t)ar * K + kb + c * 4, aval);
            int brow = ntile * 128 + m;
            cp16(sb + 16384 + soff, Bt + (size_t)brow * K + kb + c * 4, 16);
        }
    };

    load_stage(0, 0);
    cp_commit();

    for (int ch = 0; ch < nch; ++ch) {
        const int nxt = ch + 1;
        if (nxt < nch) { load_stage(nxt & 1, nxt); cp_commit(); }
        if (nxt < nch) cp_wait<1>(); else cp_wait<0>();
        __syncthreads();

        const uint32_t sb = sbase + (ch & 1) * 32768;
#pragma unroll
        for (int k8 = 0; k8 < 4; ++k8) {
            const int c0 = k8 * 2;             // chunk pair for this k8
            uint32_t af[2][4], bf[8][2];
#pragma unroll
            for (int mt = 0; mt < 2; ++mt) {
                int ml = warp_m * 32 + mt * 16 + r + ((g & 1) << 3);
                int cc = c0 + (g >> 1);
                uint32_t ad = sb + ml * 128 + ((cc ^ (ml & 7)) << 4);
                ldsm4(af[mt], ad);
            }
#pragma unroll
            for (int nt2 = 0; nt2 < 4; ++nt2) {
                int nl = warp_n * 64 + nt2 * 16 + r + ((g >> 1) << 3);
                int cc = c0 + (g & 1);
                uint32_t bd = sb + 16384 + nl * 128 + ((cc ^ (nl & 7)) << 4);
                uint32_t tb[4];
                ldsm4(tb, bd);
                bf[nt2 * 2][0] = tb[0]; bf[nt2 * 2][1] = tb[1];
                bf[nt2 * 2 + 1][0] = tb[2]; bf[nt2 * 2 + 1][1] = tb[3];
            }
#pragma unroll
            for (int mt = 0; mt < 2; ++mt)
#pragma unroll
                for (int nt = 0; nt < 8; ++nt)
                    mma_tf32(acc[mt][nt], af[mt], bf[nt]);
        }
        __syncthreads();
    }

    // ---- epilogue 1: store C as fp16 ----
#pragma unroll
    for (int mt = 0; mt < 2; ++mt) {
        int row0 = mtile * 128 + warp_m * 32 + mt * 16 + (lane >> 2);
#pragma unroll
        for (int nt = 0; nt < 8; ++nt) {
            int col = ntile * 128 + warp_n * 64 + nt * 8 + (lane & 3) * 2;
            if (row0 < M)
                *reinterpret_cast<__half2*>(&C[(size_t)row0 * Ncols + col]) =
                    __floats2half2_rn(acc[mt][nt][0], acc[mt][nt][1]);
            if (row0 + 8 < M)
                *reinterpret_cast<__half2*>(&C[(size_t)(row0 + 8) * Ncols + col]) =
                    __floats2half2_rn(acc[mt][nt][2], acc[mt][nt][3]);
        }
    }

    // ---- epilogue 2: fused logits partial dots (fp32-exact) ----
    float es[4] = {0.f, 0.f, 0.f, 0.f}, ed[4] = {0.f, 0.f, 0.f, 0.f};
#pragma unroll
    for (int nt = 0; nt < 8; ++nt) {
        int col = ntile * 128 + warp_n * 64 + nt * 8 + (lane & 3) * 2;
        float a0 = as_g[col], a1 = as_g[col + 1];
        float d0 = ad_g[col], d1 = ad_g[col + 1];
#pragma unroll
        for (int mt = 0; mt < 2; ++mt) {
            es[mt * 2 + 0] += acc[mt][nt][0] * a0 + acc[mt][nt][1] * a1;
            es[mt * 2 + 1] += acc[mt][nt][2] * a0 + acc[mt][nt][3] * a1;
            ed[mt * 2 + 0] += acc[mt][nt][0] * d0 + acc[mt][nt][1] * d1;
            ed[mt * 2 + 1] += acc[mt][nt][2] * d0 + acc[mt][nt][3] * d1;
        }
    }
#pragma unroll
    for (int o = 1; o <= 2; o <<= 1)
#pragma unroll
        for (int i = 0; i < 4; ++i) {
            es[i] += __shfl_xor_sync(0xffffffffu, es[i], o);
            ed[i] += __shfl_xor_sync(0xffffffffu, ed[i], o);
        }
    if ((lane & 3) == 0) {
        int hh = (ntile * 128 + warp_n * 64) / Cc;
#pragma unroll
        for (int mt = 0; mt < 2; ++mt) {
            int row = mtile * 128 + warp_m * 32 + mt * 16 + (lane >> 2);
            if (row < M) {
                atomicAdd(&esrc[row * H + hh], es[mt * 2 + 0]);
                atomicAdd(&edst[row * H + hh], ed[mt * 2 + 0]);
            }
            if (row + 8 < M) {
                atomicAdd(&esrc[(row + 8) * H + hh], es[mt * 2 + 1]);
                atomicAdd(&edst[(row + 8) * H + hh], ed[mt * 2 + 1]);
            }
        }
    }
}

// ======================= CSR build =========================================
__global__ void count_k(const int* __restrict__ dst, int E, int n, int* __restrict__ cnt) {
    int i = blockIdx.x * blockDim.x + threadIdx.x;
    int tot = E + n;
    if (i < tot) {
        int d = (i < E) ? dst[i] : (i - E);
        atomicAdd(&cnt[d], 1);
    }
}

__global__ void scan_k(const int* __restrict__ cnt, int* __restrict__ rowptr, int n) {
    __shared__ int sh[1024];
    __shared__ int carry_sh;
    int tid = threadIdx.x;
    if (tid == 0) carry_sh = 0;
    __syncthreads();
    for (int base = 0; base < n; base += 1024) {
        int cin = carry_sh;
        int v = (base + tid < n) ? cnt[base + tid] : 0;
        sh[tid] = v;
        __syncthreads();
#pragma unroll
        for (int off = 1; off < 1024; off <<= 1) {
            int t = (tid >= off) ? sh[tid - off] : 0;
            __syncthreads();
            sh[tid] += t;
            __syncthreads();
        }
        if (base + tid < n) rowptr[base + tid] = cin + sh[tid] - v;
        __syncthreads();
        if (tid == 0) carry_sh = cin + sh[1023];
        __syncthreads();
    }
    if (tid == 0) rowptr[n] = carry_sh;
}

__global__ void fill_k(const int* __restrict__ src, const int* __restrict__ dst,
                       int E, int n, int* __restrict__ cursor, int* __restrict__ col) {
    int i = blockIdx.x * blockDim.x + threadIdx.x;
    int tot = E + n;
    if (i < tot) {
        int s, d;
        if (i < E) { s = src[i]; d = dst[i]; }
        else       { s = d = i - E; }
        int pos = atomicAdd(&cursor[d], 1);
        col[pos] = s;
    }
}

// ======================= aggregation =======================================
// One block (256 thr) per dst node. Thread t: head hh=t/(C/4), 4 channels ->
// one 8B load per edge. Unnormalized exp weights; dinv folded at the end.
// Output: fp32 (layer 2 -> d_out) or tf32-rounded fp32 (layers 0,1 -> g_At).
#define AGG_CAP 128

__global__ __launch_bounds__(256)
void aggregate_k(const __half* __restrict__ hbuf,
                 const float* __restrict__ esrc, const float* __restrict__ edst,
                 const int* __restrict__ rowptr, const int* __restrict__ col,
                 const float* __restrict__ bias, float* __restrict__ out,
                 float* __restrict__ anext, int write_out,
                 int H, int C, int HC, float invH) {
    __shared__ float sh_m[H_MAX];
    __shared__ float sh_dinv[H_MAX];
    __shared__ float w_sh[AGG_CAP * H_MAX];
    __shared__ int col_sh[AGG_CAP];
    __shared__ float red_sh[HC_MAX];

    const int n = blockIdx.x;
    const int tid = threadIdx.x;
    const int wid = tid >> 5, lane = tid & 31;
    const int start = rowptr[n], end = rowptr[n + 1];

    float edh = 0.f;
    if (wid < H) {
        edh = edst[n * H + wid];
        float mx = -1e30f;
        for (int e = start + lane; e < end; e += 32) {
            float v = esrc[col[e] * H + wid] + edh;
            v = v > 0.f ? v : 0.2f * v;
            mx = fmaxf(mx, v);
        }
#pragma unroll
        for (int o = 16; o > 0; o >>= 1) mx = fmaxf(mx, __shfl_xor_sync(0xffffffffu, mx, o));
        float sum = 0.f;
        for (int e = start + lane; e < end; e += 32) {
            float v = esrc[col[e] * H + wid] + edh;
            v = v > 0.f ? v : 0.2f * v;
            sum += __expf(v - mx);
        }
#pragma unroll
        for (int o = 16; o > 0; o >>= 1) sum += __shfl_xor_sync(0xffffffffu, sum, o);
        if (lane == 0) {
            sh_m[wid] = mx;
            sh_dinv[wid] = 1.f / (sum + 1e-16f);
        }
    }
    __syncthreads();

    const int qph = C >> 2;
    const int hh = tid / qph;
    const int q = tid - hh * qph;
    const int base = hh * C + (q << 2);
    const bool act = (hh < H);

    float ax = 0.f, ay = 0.f, az = 0.f, aw = 0.f;

    for (int cb = start; cb < end; cb += AGG_CAP) {
        int cnt = end - cb;
        if (cnt > AGG_CAP) cnt = AGG_CAP;
        if (wid < H) {
            float m = sh_m[wid];
            for (int e = lane; e < cnt; e += 32) {
                int s = col[cb + e];
                if (wid == 0) col_sh[e] = s;
                float v = esrc[s * H + wid] + edh;
                v = v > 0.f ? v : 0.2f * v;
                w_sh[e * H + wid] = __expf(v - m);   // unnormalized
            }
        }
        __syncthreads();
        if (act) {
#pragma unroll 4
            for (int e = 0; e < cnt; ++e) {
                const uint2 pv = *reinterpret_cast<const uint2*>(
                    hbuf + (size_t)col_sh[e] * HC + base);
                const float w = w_sh[e * H + hh];
                const float2 v01 = __half22float2(*reinterpret_cast<const __half2*>(&pv.x));
                const float2 v23 = __half22float2(*reinterpret_cast<const __half2*>(&pv.y));
                ax += w * v01.x; ay += w * v01.y; az += w * v23.x; aw += w * v23.y;
            }
        }
        __syncthreads();
    }

    if (act) {
        const float dinv = sh_dinv[hh];
        *reinterpret_cast<float4*>(red_sh + base) =
            make_float4(ax * dinv, ay * dinv, az * dinv, aw * dinv);
    }
    __syncthreads();

    const int c = tid;
    if (c < C) {
        float s = 0.f;
#pragma unroll 4
        for (int h = 0; h < H; ++h) s += red_sh[h * C + c];
        float val = s * invH + bias[c];
        if (write_out) out[(size_t)n * C + c] = val;
        else           anext[(size_t)n * C + c] = to_tf32(val);
    }
}

// ======================= host launcher =====================================
extern "C" void kernel_launch(void* const* d_in, const int* in_sizes, int n_in,
                              void* d_out, int out_size) {
    const float* x  = (const float*)d_in[0];
    const int*   ei = (const int*)d_in[1];
    const float* W[3]  = {(const float*)d_in[2],  (const float*)d_in[6],  (const float*)d_in[10]};
    const float* AS[3] = {(const float*)d_in[3],  (const float*)d_in[7],  (const float*)d_in[11]};
    const float* AD[3] = {(const float*)d_in[4],  (const float*)d_in[8],  (const float*)d_in[12]};
    const float* B[3]  = {(const float*)d_in[5],  (const float*)d_in[9],  (const float*)d_in[13]};

    const int Cc[3] = {in_sizes[5], in_sizes[9], in_sizes[13]};
    const int H = in_sizes[3] / Cc[0];
    const int E = in_sizes[1] / 2;
    const int N = out_size / Cc[2];
    const int F_IN = in_sizes[0] / N;

    __half* hbuf;
    float *esrc, *edst, *At, *Bt;
    int *rowptr, *cnt, *cursor, *col;
    cudaGetSymbolAddress((void**)&hbuf,   g_h);
    cudaGetSymbolAddress((void**)&esrc,   g_esrc);
    cudaGetSymbolAddress((void**)&edst,   g_edst);
    cudaGetSymbolAddress((void**)&At,     g_At);
    cudaGetSymbolAddress((void**)&Bt,     g_Bt);
    cudaGetSymbolAddress((void**)&rowptr, g_rowptr);
    cudaGetSymbolAddress((void**)&cnt,    g_cnt);
    cudaGetSymbolAddress((void**)&cursor, g_cursor);
    cudaGetSymbolAddress((void**)&col,    g_col);

    cudaFuncSetAttribute(gemm_mma, cudaFuncAttributeMaxDynamicSharedMemorySize, GEMM_SMEM);

    int K = F_IN;

    for (int l = 0; l < 3; ++l) {
        int C = Cc[l], HC = H * C;

        if (l == 0) {
            int total = N * K;
            round_k<<<(total + 255) / 256, 256>>>(x, At, total);
        }
        {
            dim3 gr(HC / 32, K / 32), b(32, 8);
            tW_k<<<gr, b>>>(W[l], Bt, K, HC);
        }
        if (l == 0) cudaMemsetAsync(cnt, 0, N * sizeof(int));
        cudaMemsetAsync(esrc, 0, N * H * sizeof(float));
        cudaMemsetAsync(edst, 0, N * H * sizeof(float));
        {
            dim3 gr(HC / 128, (N + 127) / 128);
            gemm_mma<<<gr, 256, GEMM_SMEM>>>(At, Bt, hbuf,
                                             AS[l], AD[l], esrc, edst,
                                             N, HC, K, C, H);
        }
        if (l == 0) {
            int tot = E + N;
            int blocks = (tot + 255) / 256;
            count_k<<<blocks, 256>>>(ei + E, E, N, cnt);
            scan_k<<<1, 1024>>>(cnt, rowptr, N);
            cudaMemcpyAsync(cursor, rowptr, N * sizeof(int), cudaMemcpyDeviceToDevice);
            fill_k<<<blocks, 256>>>(ei, ei + E, E, N, cursor, col);
        }
        aggregate_k<<<N, 256>>>(hbuf, esrc, edst, rowptr, col, B[l], (float*)d_out,
                                At, (l == 2) ? 1 : 0, H, C, HC, 1.0f / (float)H);
        K = C;
    }
}

// round 11
// speedup vs baseline: 3.1399x; 1.1397x over previous
#include <cuda_runtime.h>
#include <cuda_bf16.h>
#include <cuda_fp16.h>
#include <cstdint>

// ---------------------------------------------------------------------------
// GAT (3 layers, H=4 heads, concat=False/mean) for B200 (base sm_100 PTX).
// Per layer:
//   0) round x -> tf32 (layer 0 only; layers 1,2 fused into aggregate)
//      transpose+round W -> [HC][K] tf32
//   1) warp-mma tf32 GEMM (single pass, fp32 accum, 2 CTAs/SM): h = x @ W
//      epilogue: h stored fp16, fused attention logits via atomics
//   2) per-dst softmax (no-max-sub: |logit| << 88, exact) + weighted
//      gather-sum via CSR (half2 loads), mean heads + bias,
//      fused tf32 rounding of the result
// ---------------------------------------------------------------------------

#define N_MAX   10240
#define K_MAXD  512
#define HC_MAX  1024
#define C_MAX   256
#define H_MAX   8
#define ET_MAX  204800

__device__ __align__(128) __half g_h[(size_t)N_MAX * HC_MAX];
__device__ __align__(128) float g_e[2 * N_MAX * H_MAX];           // esrc | edst
__device__ __align__(128) float g_At[(size_t)N_MAX * K_MAXD];     // tf32-rounded A
__device__ __align__(128) float g_Bt[(size_t)HC_MAX * K_MAXD];    // tf32-rounded W^T
__device__ int g_rowptr[N_MAX + 1];
__device__ int g_cnt[N_MAX];
__device__ int g_cursor[N_MAX];
__device__ int g_col[ET_MAX];

// ======================= helpers ==========================================
__device__ __forceinline__ uint32_t smem_u32(const void* p) {
    uint32_t a;
    asm("{ .reg .u64 t; cvta.to.shared.u64 t, %1; cvt.u32.u64 %0, t; }" : "=r"(a) : "l"(p));
    return a;
}

// cvt.rna.tf32.f32 writes a .b32 destination (NOT .f32) — use "=r".
__device__ __forceinline__ float to_tf32(float v) {
    uint32_t o;
    asm("cvt.rna.tf32.f32 %0, %1;" : "=r"(o) : "f"(v));
    return __uint_as_float(o);
}

__device__ __forceinline__ void cp16(uint32_t saddr, const void* gaddr, int srcbytes) {
    asm volatile("cp.async.cg.shared.global [%0], [%1], 16, %2;"
                 :: "r"(saddr), "l"(gaddr), "r"(srcbytes) : "memory");
}
__device__ __forceinline__ void cp_commit() {
    asm volatile("cp.async.commit_group;" ::: "memory");
}
template <int NN>
__device__ __forceinline__ void cp_wait() {
    asm volatile("cp.async.wait_group %0;" :: "n"(NN) : "memory");
}

__device__ __forceinline__ void ldsm4(uint32_t* r, uint32_t addr) {
    asm volatile("ldmatrix.sync.aligned.m8n8.x4.shared.b16 {%0,%1,%2,%3}, [%4];"
                 : "=r"(r[0]), "=r"(r[1]), "=r"(r[2]), "=r"(r[3]) : "r"(addr));
}

__device__ __forceinline__ void mma_tf32(float* d, const uint32_t* a, const uint32_t* b) {
    asm volatile(
        "mma.sync.aligned.m16n8k8.row.col.f32.tf32.tf32.f32 "
        "{%0,%1,%2,%3}, {%4,%5,%6,%7}, {%8,%9}, {%0,%1,%2,%3};"
        : "+f"(d[0]), "+f"(d[1]), "+f"(d[2]), "+f"(d[3])
        : "r"(a[0]), "r"(a[1]), "r"(a[2]), "r"(a[3]), "r"(b[0]), "r"(b[1]));
}

// ======================= pre-kernels =======================================
__global__ void round_k(const float4* __restrict__ X, float4* __restrict__ A, int total4) {
    int stride = gridDim.x * blockDim.x;
    for (int i = blockIdx.x * blockDim.x + threadIdx.x; i < total4; i += stride) {
        float4 v = X[i];
        v.x = to_tf32(v.x); v.y = to_tf32(v.y);
        v.z = to_tf32(v.z); v.w = to_tf32(v.w);
        A[i] = v;
    }
}

// W [K][HC] row-major -> Bt [HC][K] tf32-rounded
__global__ void tW_k(const float* __restrict__ W, float* __restrict__ Bt, int K, int HC) {
    __shared__ float t[32][33];
    int kb = blockIdx.y * 32, nb = blockIdx.x * 32;
    int tx = threadIdx.x, ty = threadIdx.y;   // 32 x 8
    for (int i = ty; i < 32; i += 8)
        t[i][tx] = W[(size_t)(kb + i) * HC + nb + tx];
    __syncthreads();
    for (int i = ty; i < 32; i += 8)
        Bt[(size_t)(nb + i) * K + kb + tx] = to_tf32(t[tx][i]);
}

// ======================= warp-mma tf32 GEMM + fused logits =================
// C[M, HC] = A[M,K] @ W[K,HC]. A [M][K] fp32(tf32), B [HC][K] fp32(tf32).
// Block 256 thr (8 warps 4x2: warp tile 32x64), block tile 128x128, BK=32,
// double-buffered cp.async, 2 CTAs/SM. Smem stage 32KB.
// Swizzle: 16B chunk (4 floats) at soff(m,c) = m*128 + ((c ^ (m&7))<<4).
#define GEMM_SMEM 65536

__global__ __launch_bounds__(256, 2)
void gemm_mma(const float* __restrict__ At, const float* __restrict__ Bt,
              __half* __restrict__ C, const float* __restrict__ as_g,
              const float* __restrict__ ad_g, float* __restrict__ esrc,
              float* __restrict__ edst, int M, int Ncols, int K, int Cc, int H) {
    extern __shared__ __align__(1024) char smem[];
    const uint32_t sbase = smem_u32(smem);
    const int tid = threadIdx.x;
    const int lane = tid & 31, wid = tid >> 5;
    const int warp_m = wid & 3;
    const int warp_n = wid >> 2;
    const int mtile = blockIdx.y, ntile = blockIdx.x;
    const int g = lane >> 3, r = lane & 7;

    float acc[2][8][4] = {};
    const int nch = K >> 5;   // BK=32

    auto load_stage = [&](int buf, int ch) {
        const int kb = ch << 5;
        const uint32_t sb = sbase + buf * 32768;
#pragma unroll
        for (int j = 0; j < 4; ++j) {
            int chunk = tid + (j << 8);        // 0..1023
            int m = chunk >> 3, c = chunk & 7; // row, 16B chunk (4 floats)
            uint32_t soff = m * 128 + ((c ^ (m & 7)) << 4);
            int arow = mtile * 128 + m;
            int aval = (arow < M) ? 16 : 0;
            int ar = (arow < M) ? arow : (M - 1);
            cp16(sb + soff, At + (size_t)ar * K + kb + c * 4, aval);
            int brow = ntile * 128 + m;
            cp16(sb + 16384 + soff, Bt + (size_t)brow * K + kb + c * 4, 16);
        }
    };

    load_stage(0, 0);
    cp_commit();

    for (int ch = 0; ch < nch; ++ch) {
        const int nxt = ch + 1;
        if (nxt < nch) { load_stage(nxt & 1, nxt); cp_commit(); }
        if (nxt < nch) cp_wait<1>(); else cp_wait<0>();
        __syncthreads();

        const uint32_t sb = sbase + (ch & 1) * 32768;
#pragma unroll
        for (int k8 = 0; k8 < 4; ++k8) {
            const int c0 = k8 * 2;             // chunk pair for this k8
            uint32_t af[2][4], bf[8][2];
#pragma unroll
            for (int mt = 0; mt < 2; ++mt) {
                int ml = warp_m * 32 + mt * 16 + r + ((g & 1) << 3);
                int cc = c0 + (g >> 1);
                uint32_t ad = sb + ml * 128 + ((cc ^ (ml & 7)) << 4);
                ldsm4(af[mt], ad);
            }
#pragma unroll
            for (int nt2 = 0; nt2 < 4; ++nt2) {
                int nl = warp_n * 64 + nt2 * 16 + r + ((g >> 1) << 3);
                int cc = c0 + (g & 1);
                uint32_t bd = sb + 16384 + nl * 128 + ((cc ^ (nl & 7)) << 4);
                uint32_t tb[4];
                ldsm4(tb, bd);
                bf[nt2 * 2][0] = tb[0]; bf[nt2 * 2][1] = tb[1];
                bf[nt2 * 2 + 1][0] = tb[2]; bf[nt2 * 2 + 1][1] = tb[3];
            }
#pragma unroll
            for (int mt = 0; mt < 2; ++mt)
#pragma unroll
                for (int nt = 0; nt < 8; ++nt)
                    mma_tf32(acc[mt][nt], af[mt], bf[nt]);
        }
        __syncthreads();
    }

    // ---- epilogue 1: store C as fp16 ----
#pragma unroll
    for (int mt = 0; mt < 2; ++mt) {
        int row0 = mtile * 128 + warp_m * 32 + mt * 16 + (lane >> 2);
#pragma unroll
        for (int nt = 0; nt < 8; ++nt) {
            int col = ntile * 128 + warp_n * 64 + nt * 8 + (lane & 3) * 2;
            if (row0 < M)
                *reinterpret_cast<__half2*>(&C[(size_t)row0 * Ncols + col]) =
                    __floats2half2_rn(acc[mt][nt][0], acc[mt][nt][1]);
            if (row0 + 8 < M)
                *reinterpret_cast<__half2*>(&C[(size_t)(row0 + 8) * Ncols + col]) =
                    __floats2half2_rn(acc[mt][nt][2], acc[mt][nt][3]);
        }
    }

    // ---- epilogue 2: fused logits partial dots (fp32-exact) ----
    float es[4] = {0.f, 0.f, 0.f, 0.f}, ed[4] = {0.f, 0.f, 0.f, 0.f};
#pragma unroll
    for (int nt = 0; nt < 8; ++nt) {
        int col = ntile * 128 + warp_n * 64 + nt * 8 + (lane & 3) * 2;
        float a0 = as_g[col], a1 = as_g[col + 1];
        float d0 = ad_g[col], d1 = ad_g[col + 1];
#pragma unroll
        for (int mt = 0; mt < 2; ++mt) {
            es[mt * 2 + 0] += acc[mt][nt][0] * a0 + acc[mt][nt][1] * a1;
            es[mt * 2 + 1] += acc[mt][nt][2] * a0 + acc[mt][nt][3] * a1;
            ed[mt * 2 + 0] += acc[mt][nt][0] * d0 + acc[mt][nt][1] * d1;
            ed[mt * 2 + 1] += acc[mt][nt][2] * d0 + acc[mt][nt][3] * d1;
        }
    }
#pragma unroll
    for (int o = 1; o <= 2; o <<= 1)
#pragma unroll
        for (int i = 0; i < 4; ++i) {
            es[i] += __shfl_xor_sync(0xffffffffu, es[i], o);
            ed[i] += __shfl_xor_sync(0xffffffffu, ed[i], o);
        }
    if ((lane & 3) == 0) {
        int hh = (ntile * 128 + warp_n * 64) / Cc;
#pragma unroll
        for (int mt = 0; mt < 2; ++mt) {
            int row = mtile * 128 + warp_m * 32 + mt * 16 + (lane >> 2);
            if (row < M) {
                atomicAdd(&esrc[row * H + hh], es[mt * 2 + 0]);
                atomicAdd(&edst[row * H + hh], ed[mt * 2 + 0]);
            }
            if (row + 8 < M) {
                atomicAdd(&esrc[(row + 8) * H + hh], es[mt * 2 + 1]);
                atomicAdd(&edst[(row + 8) * H + hh], ed[mt * 2 + 1]);
            }
        }
    }
}

// ======================= CSR build =========================================
__global__ void count_k(const int* __restrict__ dst, int E, int n, int* __restrict__ cnt) {
    int i = blockIdx.x * blockDim.x + threadIdx.x;
    int tot = E + n;
    if (i < tot) {
        int d = (i < E) ? dst[i] : (i - E);
        atomicAdd(&cnt[d], 1);
    }
}

// Exclusive scan, single block 1024 thr, shfl-based (4 barriers/batch).
__global__ void scan_k(const int* __restrict__ cnt, int* __restrict__ rowptr, int n) {
    __shared__ int wsum[32];
    __shared__ int carry_sh;
    int tid = threadIdx.x, lane = tid & 31, wid = tid >> 5;
    if (tid == 0) carry_sh = 0;
    __syncthreads();
    for (int base = 0; base < n; base += 1024) {
        int v = (base + tid < n) ? cnt[base + tid] : 0;
        int x = v;
#pragma unroll
        for (int o = 1; o < 32; o <<= 1) {
            int t = __shfl_up_sync(0xffffffffu, x, o);
            if (lane >= o) x += t;
        }
        if (lane == 31) wsum[wid] = x;
        __syncthreads();
        if (wid == 0) {
            int s = wsum[lane];
#pragma unroll
            for (int o = 1; o < 32; o <<= 1) {
                int t = __shfl_up_sync(0xffffffffu, s, o);
                if (lane >= o) s += t;
            }
            wsum[lane] = s;
        }
        __syncthreads();
        int cin = carry_sh;
        int incl = x + ((wid > 0) ? wsum[wid - 1] : 0);
        if (base + tid < n) rowptr[base + tid] = cin + incl - v;
        __syncthreads();
        if (tid == 0) carry_sh = cin + wsum[31];
        __syncthreads();
    }
    if (tid == 0) rowptr[n] = carry_sh;
}

__global__ void fill_k(const int* __restrict__ src, const int* __restrict__ dst,
                       int E, int n, int* __restrict__ cursor, int* __restrict__ col) {
    int i = blockIdx.x * blockDim.x + threadIdx.x;
    int tot = E + n;
    if (i < tot) {
        int s, d;
        if (i < E) { s = src[i]; d = dst[i]; }
        else       { s = d = i - E; }
        int pos = atomicAdd(&cursor[d], 1);
        col[pos] = s;
    }
}

// ======================= aggregation =======================================
// One block (256 thr) per dst node. Single pass: weights w = exp(leaky(v))
// computed directly (no max subtraction — |logit| << 88, exact vs reference
// up to the negligible +1e-16), per-head sums accumulated inline, normalized
// at the end. Thread t: head hh=t/(C/4), 4 channels -> one 8B load per edge.
#define AGG_CAP 128

__global__ __launch_bounds__(256)
void aggregate_k(const __half* __restrict__ hbuf,
                 const float* __restrict__ esrc, const float* __restrict__ edst,
                 const int* __restrict__ rowptr, const int* __restrict__ col,
                 const float* __restrict__ bias, float* __restrict__ out,
                 float* __restrict__ anext, int write_out,
                 int H, int C, int HC, float invH) {
    __shared__ float sh_dinv[H_MAX];
    __shared__ float w_sh[AGG_CAP * H_MAX];
    __shared__ int col_sh[AGG_CAP];
    __shared__ float red_sh[HC_MAX];

    const int n = blockIdx.x;
    const int tid = threadIdx.x;
    const int wid = tid >> 5, lane = tid & 31;
    const int start = rowptr[n], end = rowptr[n + 1];

    const float edh = (wid < H) ? edst[n * H + wid] : 0.f;
    float ssum = 0.f;

    const int qph = C >> 2;
    const int hh = tid / qph;
    const int q = tid - hh * qph;
    const int base = hh * C + (q << 2);
    const bool act = (hh < H);

    float ax = 0.f, ay = 0.f, az = 0.f, aw = 0.f;

    for (int cb = start; cb < end; cb += AGG_CAP) {
        int cnt = end - cb;
        if (cnt > AGG_CAP) cnt = AGG_CAP;
        if (wid < H) {
            for (int e = lane; e < cnt; e += 32) {
                int s = col[cb + e];
                if (wid == 0) col_sh[e] = s;
                float v = esrc[s * H + wid] + edh;
                v = v > 0.f ? v : 0.2f * v;
                float w = __expf(fminf(v, 60.f));
                w_sh[e * H + wid] = w;
                ssum += w;
            }
        }
        __syncthreads();
        if (act) {
#pragma unroll 4
            for (int e = 0; e < cnt; ++e) {
                const uint2 pv = *reinterpret_cast<const uint2*>(
                    hbuf + (size_t)col_sh[e] * HC + base);
                const float w = w_sh[e * H + hh];
                const float2 v01 = __half22float2(*reinterpret_cast<const __half2*>(&pv.x));
                const float2 v23 = __half22float2(*reinterpret_cast<const __half2*>(&pv.y));
                ax += w * v01.x; ay += w * v01.y; az += w * v23.x; aw += w * v23.y;
            }
        }
        __syncthreads();
    }

    // per-head weight-sum reduction (warps 0..H-1)
    if (wid < H) {
#pragma unroll
        for (int o = 16; o > 0; o >>= 1) ssum += __shfl_xor_sync(0xffffffffu, ssum, o);
        if (lane == 0) sh_dinv[wid] = 1.f / (ssum + 1e-16f);
    }
    __syncthreads();

    if (act) {
        const float dinv = sh_dinv[hh];
        *reinterpret_cast<float4*>(red_sh + base) =
            make_float4(ax * dinv, ay * dinv, az * dinv, aw * dinv);
    }
    __syncthreads();

    const int c = tid;
    if (c < C) {
        float s = 0.f;
#pragma unroll 4
        for (int h = 0; h < H; ++h) s += red_sh[h * C + c];
        float val = s * invH + bias[c];
        if (write_out) out[(size_t)n * C + c] = val;
        else           anext[(size_t)n * C + c] = to_tf32(val);
    }
}

// ======================= host launcher =====================================
extern "C" void kernel_launch(void* const* d_in, const int* in_sizes, int n_in,
                              void* d_out, int out_size) {
    const float* x  = (const float*)d_in[0];
    const int*   ei = (const int*)d_in[1];
    const float* W[3]  = {(const float*)d_in[2],  (const float*)d_in[6],  (const float*)d_in[10]};
    const float* AS[3] = {(const float*)d_in[3],  (const float*)d_in[7],  (const float*)d_in[11]};
    const float* AD[3] = {(const float*)d_in[4],  (const float*)d_in[8],  (const float*)d_in[12]};
    const float* B[3]  = {(const float*)d_in[5],  (const float*)d_in[9],  (const float*)d_in[13]};

    const int Cc[3] = {in_sizes[5], in_sizes[9], in_sizes[13]};
    const int H = in_sizes[3] / Cc[0];
    const int E = in_sizes[1] / 2;
    const int N = out_size / Cc[2];
    const int F_IN = in_sizes[0] / N;

    __half* hbuf;
    float *ebuf, *At, *Bt;
    int *rowptr, *cnt, *cursor, *col;
    cudaGetSymbolAddress((void**)&hbuf,   g_h);
    cudaGetSymbolAddress((void**)&ebuf,   g_e);
    cudaGetSymbolAddress((void**)&At,     g_At);
    cudaGetSymbolAddress((void**)&Bt,     g_Bt);
    cudaGetSymbolAddress((void**)&rowptr, g_rowptr);
    cudaGetSymbolAddress((void**)&cnt,    g_cnt);
    cudaGetSymbolAddress((void**)&cursor, g_cursor);
    cudaGetSymbolAddress((void**)&col,    g_col);

    float* esrc = ebuf;
    float* edst = ebuf + (size_t)N_MAX * H_MAX;

    cudaFuncSetAttribute(gemm_mma, cudaFuncAttributeMaxDynamicSharedMemorySize, GEMM_SMEM);

    int K = F_IN;

    for (int l = 0; l < 3; ++l) {
        int C = Cc[l], HC = H * C;

        if (l == 0) {
            int total4 = (N * K) >> 2;
            int blocks = (total4 + 255) / 256;
            if (blocks > 4096) blocks = 4096;
            round_k<<<blocks, 256>>>((const float4*)x, (float4*)At, total4);
        }
        {
            dim3 gr(HC / 32, K / 32), b(32, 8);
            tW_k<<<gr, b>>>(W[l], Bt, K, HC);
        }
        if (l == 0) cudaMemsetAsync(cnt, 0, N * sizeof(int));
        cudaMemsetAsync(esrc, 0, N_MAX * H_MAX * sizeof(float));   // esrc region
        cudaMemsetAsync(edst, 0, N * H * sizeof(float));            // edst region
        {
            dim3 gr(HC / 128, (N + 127) / 128);
            gemm_mma<<<gr, 256, GEMM_SMEM>>>(At, Bt, hbuf,
                                             AS[l], AD[l], esrc, edst,
                                             N, HC, K, C, H);
        }
        if (l == 0) {
            int tot = E + N;
            int blocks = (tot + 255) / 256;
            count_k<<<blocks, 256>>>(ei + E, E, N, cnt);
            scan_k<<<1, 1024>>>(cnt, rowptr, N);
            cudaMemcpyAsync(cursor, rowptr, N * sizeof(int), cudaMemcpyDeviceToDevice);
            fill_k<<<blocks, 256>>>(ei, ei + E, E, N, cursor, col);
        }
        aggregate_k<<<N, 256>>>(hbuf, esrc, edst, rowptr, col, B[l], (float*)d_out,
                                At, (l == 2) ? 1 : 0, H, C, HC, 1.0f / (float)H);
        K = C;
    }
}

// round 12
// speedup vs baseline: 3.2138x; 1.0236x over previous
#include <cuda_runtime.h>
#include <cuda_bf16.h>
#include <cuda_fp16.h>
#include <cstdint>

// ---------------------------------------------------------------------------
// GAT (3 layers, H=4 heads, concat=False/mean) for B200 (base sm_100 PTX).
// Per layer:
//   0) round x -> tf32 (layer 0 only; layers 1,2 fused into aggregate)
//      transpose+round W -> [HC][K] tf32
//   1) PERSISTENT warp-mma tf32 GEMM (single pass, fp32 accum, 2 CTAs/SM,
//      grid=2*SMs, tiles strided): h = x @ W; epilogue: h fp16 + fused logits
//   2) per-dst softmax (no-max-sub, exact) + weighted gather-sum via CSR
//      (half2 loads), mean heads + bias, fused tf32 rounding of the result
// ---------------------------------------------------------------------------

#define N_MAX   10240
#define K_MAXD  512
#define HC_MAX  1024
#define C_MAX   256
#define H_MAX   8
#define ET_MAX  204800
#define GEMM_GRID 296   // 2 CTAs/SM x 148 SMs

__device__ __align__(128) __half g_h[(size_t)N_MAX * HC_MAX];
__device__ __align__(128) float g_e[2 * N_MAX * H_MAX];           // esrc | edst
__device__ __align__(128) float g_At[(size_t)N_MAX * K_MAXD];     // tf32-rounded A
__device__ __align__(128) float g_Bt[(size_t)HC_MAX * K_MAXD];    // tf32-rounded W^T
__device__ int g_rowptr[N_MAX + 1];
__device__ int g_cnt[N_MAX];
__device__ int g_cursor[N_MAX];
__device__ int g_col[ET_MAX];

// ======================= helpers ==========================================
__device__ __forceinline__ uint32_t smem_u32(const void* p) {
    uint32_t a;
    asm("{ .reg .u64 t; cvta.to.shared.u64 t, %1; cvt.u32.u64 %0, t; }" : "=r"(a) : "l"(p));
    return a;
}

// cvt.rna.tf32.f32 writes a .b32 destination (NOT .f32) — use "=r".
__device__ __forceinline__ float to_tf32(float v) {
    uint32_t o;
    asm("cvt.rna.tf32.f32 %0, %1;" : "=r"(o) : "f"(v));
    return __uint_as_float(o);
}

__device__ __forceinline__ void cp16(uint32_t saddr, const void* gaddr, int srcbytes) {
    asm volatile("cp.async.cg.shared.global [%0], [%1], 16, %2;"
                 :: "r"(saddr), "l"(gaddr), "r"(srcbytes) : "memory");
}
__device__ __forceinline__ void cp_commit() {
    asm volatile("cp.async.commit_group;" ::: "memory");
}
template <int NN>
__device__ __forceinline__ void cp_wait() {
    asm volatile("cp.async.wait_group %0;" :: "n"(NN) : "memory");
}

__device__ __forceinline__ void ldsm4(uint32_t* r, uint32_t addr) {
    asm volatile("ldmatrix.sync.aligned.m8n8.x4.shared.b16 {%0,%1,%2,%3}, [%4];"
                 : "=r"(r[0]), "=r"(r[1]), "=r"(r[2]), "=r"(r[3]) : "r"(addr));
}

__device__ __forceinline__ void mma_tf32(float* d, const uint32_t* a, const uint32_t* b) {
    asm volatile(
        "mma.sync.aligned.m16n8k8.row.col.f32.tf32.tf32.f32 "
        "{%0,%1,%2,%3}, {%4,%5,%6,%7}, {%8,%9}, {%0,%1,%2,%3};"
        : "+f"(d[0]), "+f"(d[1]), "+f"(d[2]), "+f"(d[3])
        : "r"(a[0]), "r"(a[1]), "r"(a[2]), "r"(a[3]), "r"(b[0]), "r"(b[1]));
}

// ======================= pre-kernels =======================================
__global__ void round_k(const float4* __restrict__ X, float4* __restrict__ A, int total4) {
    int stride = gridDim.x * blockDim.x;
    for (int i = blockIdx.x * blockDim.x + threadIdx.x; i < total4; i += stride) {
        float4 v = X[i];
        v.x = to_tf32(v.x); v.y = to_tf32(v.y);
        v.z = to_tf32(v.z); v.w = to_tf32(v.w);
        A[i] = v;
    }
}

// W [K][HC] row-major -> Bt [HC][K] tf32-rounded
__global__ void tW_k(const float* __restrict__ W, float* __restrict__ Bt, int K, int HC) {
    __shared__ float t[32][33];
    int kb = blockIdx.y * 32, nb = blockIdx.x * 32;
    int tx = threadIdx.x, ty = threadIdx.y;   // 32 x 8
    for (int i = ty; i < 32; i += 8)
        t[i][tx] = W[(size_t)(kb + i) * HC + nb + tx];
    __syncthreads();
    for (int i = ty; i < 32; i += 8)
        Bt[(size_t)(nb + i) * K + kb + tx] = to_tf32(t[tx][i]);
}

// ======================= persistent warp-mma tf32 GEMM + fused logits ======
// C[M, HC] = A[M,K] @ W[K,HC]. Block 256 thr (8 warps 4x2: warp tile 32x64),
// block tile 128x128, BK=32, double-buffered cp.async, 2 CTAs/SM,
// grid = GEMM_GRID persistent CTAs looping over tiles (no wave quantization).
// Smem stage 32KB. Swizzle: 16B chunk at soff(m,c) = m*128 + ((c^(m&7))<<4).
#define GEMM_SMEM 65536

__global__ __launch_bounds__(256, 2)
void gemm_mma(const float* __restrict__ At, const float* __restrict__ Bt,
              __half* __restrict__ C, const float* __restrict__ as_g,
              const float* __restrict__ ad_g, float* __restrict__ esrc,
              float* __restrict__ edst, int M, int Ncols, int K, int Cc, int H,
              int ntiles_x, int ntiles) {
    extern __shared__ __align__(1024) char smem[];
    const uint32_t sbase = smem_u32(smem);
    const int tid = threadIdx.x;
    const int lane = tid & 31, wid = tid >> 5;
    const int warp_m = wid & 3;
    const int warp_n = wid >> 2;
    const int g = lane >> 3, r = lane & 7;
    const int nch = K >> 5;   // BK=32

    for (int tile = blockIdx.x; tile < ntiles; tile += gridDim.x) {
        const int mtile = tile / ntiles_x;
        const int ntile = tile - mtile * ntiles_x;

        float acc[2][8][4] = {};

        auto load_stage = [&](int buf, int ch) {
            const int kb = ch << 5;
            const uint32_t sb = sbase + buf * 32768;
#pragma unroll
            for (int j = 0; j < 4; ++j) {
                int chunk = tid + (j << 8);        // 0..1023
                int m = chunk >> 3, c = chunk & 7; // row, 16B chunk
                uint32_t soff = m * 128 + ((c ^ (m & 7)) << 4);
                int arow = mtile * 128 + m;
                int aval = (arow < M) ? 16 : 0;
                int ar = (arow < M) ? arow : (M - 1);
                cp16(sb + soff, At + (size_t)ar * K + kb + c * 4, aval);
                int brow = ntile * 128 + m;
                cp16(sb + 16384 + soff, Bt + (size_t)brow * K + kb + c * 4, 16);
            }
        };

        load_stage(0, 0);
        cp_commit();

        for (int ch = 0; ch < nch; ++ch) {
            const int nxt = ch + 1;
            if (nxt < nch) { load_stage(nxt & 1, nxt); cp_commit(); }
            if (nxt < nch) cp_wait<1>(); else cp_wait<0>();
            __syncthreads();

            const uint32_t sb = sbase + (ch & 1) * 32768;
#pragma unroll
            for (int k8 = 0; k8 < 4; ++k8) {
                const int c0 = k8 * 2;
                uint32_t af[2][4], bf[8][2];
#pragma unroll
                for (int mt = 0; mt < 2; ++mt) {
                    int ml = warp_m * 32 + mt * 16 + r + ((g & 1) << 3);
                    int cc = c0 + (g >> 1);
                    uint32_t ad = sb + ml * 128 + ((cc ^ (ml & 7)) << 4);
                    ldsm4(af[mt], ad);
                }
#pragma unroll
                for (int nt2 = 0; nt2 < 4; ++nt2) {
                    int nl = warp_n * 64 + nt2 * 16 + r + ((g >> 1) << 3);
                    int cc = c0 + (g & 1);
                    uint32_t bd = sb + 16384 + nl * 128 + ((cc ^ (nl & 7)) << 4);
                    uint32_t tb[4];
                    ldsm4(tb, bd);
                    bf[nt2 * 2][0] = tb[0]; bf[nt2 * 2][1] = tb[1];
                    bf[nt2 * 2 + 1][0] = tb[2]; bf[nt2 * 2 + 1][1] = tb[3];
                }
#pragma unroll
                for (int mt = 0; mt < 2; ++mt)
#pragma unroll
                    for (int nt = 0; nt < 8; ++nt)
                        mma_tf32(acc[mt][nt], af[mt], bf[nt]);
            }
            __syncthreads();
        }

        // ---- epilogue 1: store C as fp16 ----
#pragma unroll
        for (int mt = 0; mt < 2; ++mt) {
            int row0 = mtile * 128 + warp_m * 32 + mt * 16 + (lane >> 2);
#pragma unroll
            for (int nt = 0; nt < 8; ++nt) {
                int col = ntile * 128 + warp_n * 64 + nt * 8 + (lane & 3) * 2;
                if (row0 < M)
                    *reinterpret_cast<__half2*>(&C[(size_t)row0 * Ncols + col]) =
                        __floats2half2_rn(acc[mt][nt][0], acc[mt][nt][1]);
                if (row0 + 8 < M)
                    *reinterpret_cast<__half2*>(&C[(size_t)(row0 + 8) * Ncols + col]) =
                        __floats2half2_rn(acc[mt][nt][2], acc[mt][nt][3]);
            }
        }

        // ---- epilogue 2: fused logits partial dots (fp32-exact) ----
        float es[4] = {0.f, 0.f, 0.f, 0.f}, ed[4] = {0.f, 0.f, 0.f, 0.f};
#pragma unroll
        for (int nt = 0; nt < 8; ++nt) {
            int col = ntile * 128 + warp_n * 64 + nt * 8 + (lane & 3) * 2;
            float a0 = as_g[col], a1 = as_g[col + 1];
            float d0 = ad_g[col], d1 = ad_g[col + 1];
#pragma unroll
            for (int mt = 0; mt < 2; ++mt) {
                es[mt * 2 + 0] += acc[mt][nt][0] * a0 + acc[mt][nt][1] * a1;
                es[mt * 2 + 1] += acc[mt][nt][2] * a0 + acc[mt][nt][3] * a1;
                ed[mt * 2 + 0] += acc[mt][nt][0] * d0 + acc[mt][nt][1] * d1;
                ed[mt * 2 + 1] += acc[mt][nt][2] * d0 + acc[mt][nt][3] * d1;
            }
        }
#pragma unroll
        for (int o = 1; o <= 2; o <<= 1)
#pragma unroll
            for (int i = 0; i < 4; ++i) {
                es[i] += __shfl_xor_sync(0xffffffffu, es[i], o);
                ed[i] += __shfl_xor_sync(0xffffffffu, ed[i], o);
            }
        if ((lane & 3) == 0) {
            int hh = (ntile * 128 + warp_n * 64) / Cc;
#pragma unroll
            for (int mt = 0; mt < 2; ++mt) {
                int row = mtile * 128 + warp_m * 32 + mt * 16 + (lane >> 2);
                if (row < M) {
                    atomicAdd(&esrc[row * H + hh], es[mt * 2 + 0]);
                    atomicAdd(&edst[row * H + hh], ed[mt * 2 + 0]);
                }
                if (row + 8 < M) {
                    atomicAdd(&esrc[(row + 8) * H + hh], es[mt * 2 + 1]);
                    atomicAdd(&edst[(row + 8) * H + hh], ed[mt * 2 + 1]);
                }
            }
        }
        __syncthreads();   // smem safe before next tile's loads
    }
}

// ======================= CSR build =========================================
__global__ void count_k(const int* __restrict__ dst, int E, int n, int* __restrict__ cnt) {
    int i = blockIdx.x * blockDim.x + threadIdx.x;
    int tot = E + n;
    if (i < tot) {
        int d = (i < E) ? dst[i] : (i - E);
        atomicAdd(&cnt[d], 1);
    }
}

// Exclusive scan, single block 1024 thr, shfl-based (4 barriers/batch).
__global__ void scan_k(const int* __restrict__ cnt, int* __restrict__ rowptr, int n) {
    __shared__ int wsum[32];
    __shared__ int carry_sh;
    int tid = threadIdx.x, lane = tid & 31, wid = tid >> 5;
    if (tid == 0) carry_sh = 0;
    __syncthreads();
    for (int base = 0; base < n; base += 1024) {
        int v = (base + tid < n) ? cnt[base + tid] : 0;
        int x = v;
#pragma unroll
        for (int o = 1; o < 32; o <<= 1) {
            int t = __shfl_up_sync(0xffffffffu, x, o);
            if (lane >= o) x += t;
        }
        if (lane == 31) wsum[wid] = x;
        __syncthreads();
        if (wid == 0) {
            int s = wsum[lane];
#pragma unroll
            for (int o = 1; o < 32; o <<= 1) {
                int t = __shfl_up_sync(0xffffffffu, s, o);
                if (lane >= o) s += t;
            }
            wsum[lane] = s;
        }
        __syncthreads();
        int cin = carry_sh;
        int incl = x + ((wid > 0) ? wsum[wid - 1] : 0);
        if (base + tid < n) rowptr[base + tid] = cin + incl - v;
        __syncthreads();
        if (tid == 0) carry_sh = cin + wsum[31];
        __syncthreads();
    }
    if (tid == 0) rowptr[n] = carry_sh;
}

__global__ void fill_k(const int* __restrict__ src, const int* __restrict__ dst,
                       int E, int n, int* __restrict__ cursor, int* __restrict__ col) {
    int i = blockIdx.x * blockDim.x + threadIdx.x;
    int tot = E + n;
    if (i < tot) {
        int s, d;
        if (i < E) { s = src[i]; d = dst[i]; }
        else       { s = d = i - E; }
        int pos = atomicAdd(&cursor[d], 1);
        col[pos] = s;
    }
}

// ======================= aggregation =======================================
// One block (256 thr) per dst node. Single pass: w = exp(leaky(v)) directly,
// per-head sums inline, normalized at the end (exact vs reference).
// Thread t: head hh=t/(C/4), 4 channels -> one 8B load per edge.
#define AGG_CAP 128

__global__ __launch_bounds__(256)
void aggregate_k(const __half* __restrict__ hbuf,
                 const float* __restrict__ esrc, const float* __restrict__ edst,
                 const int* __restrict__ rowptr, const int* __restrict__ col,
                 const float* __restrict__ bias, float* __restrict__ out,
                 float* __restrict__ anext, int write_out,
                 int H, int C, int HC, float invH) {
    __shared__ float sh_dinv[H_MAX];
    __shared__ float w_sh[AGG_CAP * H_MAX];
    __shared__ int col_sh[AGG_CAP];
    __shared__ float red_sh[HC_MAX];

    const int n = blockIdx.x;
    const int tid = threadIdx.x;
    const int wid = tid >> 5, lane = tid & 31;
    const int start = rowptr[n], end = rowptr[n + 1];

    const float edh = (wid < H) ? edst[n * H + wid] : 0.f;
    float ssum = 0.f;

    const int qph = C >> 2;
    const int hh = tid / qph;
    const int q = tid - hh * qph;
    const int base = hh * C + (q << 2);
    const bool act = (hh < H);

    float ax = 0.f, ay = 0.f, az = 0.f, aw = 0.f;

    for (int cb = start; cb < end; cb += AGG_CAP) {
        int cnt = end - cb;
        if (cnt > AGG_CAP) cnt = AGG_CAP;
        if (wid < H) {
            for (int e = lane; e < cnt; e += 32) {
                int s = col[cb + e];
                if (wid == 0) col_sh[e] = s;
                float v = esrc[s * H + wid] + edh;
                v = v > 0.f ? v : 0.2f * v;
                float w = __expf(fminf(v, 60.f));
                w_sh[e * H + wid] = w;
                ssum += w;
            }
        }
        __syncthreads();
        if (act) {
#pragma unroll 4
            for (int e = 0; e < cnt; ++e) {
                const uint2 pv = *reinterpret_cast<const uint2*>(
                    hbuf + (size_t)col_sh[e] * HC + base);
                const float w = w_sh[e * H + hh];
                const float2 v01 = __half22float2(*reinterpret_cast<const __half2*>(&pv.x));
                const float2 v23 = __half22float2(*reinterpret_cast<const __half2*>(&pv.y));
                ax += w * v01.x; ay += w * v01.y; az += w * v23.x; aw += w * v23.y;
            }
        }
        __syncthreads();
    }

    if (wid < H) {
#pragma unroll
        for (int o = 16; o > 0; o >>= 1) ssum += __shfl_xor_sync(0xffffffffu, ssum, o);
        if (lane == 0) sh_dinv[wid] = 1.f / (ssum + 1e-16f);
    }
    __syncthreads();

    if (act) {
        const float dinv = sh_dinv[hh];
        *reinterpret_cast<float4*>(red_sh + base) =
            make_float4(ax * dinv, ay * dinv, az * dinv, aw * dinv);
    }
    __syncthreads();

    const int c = tid;
    if (c < C) {
        float s = 0.f;
#pragma unroll 4
        for (int h = 0; h < H; ++h) s += red_sh[h * C + c];
        float val = s * invH + bias[c];
        if (write_out) out[(size_t)n * C + c] = val;
        else           anext[(size_t)n * C + c] = to_tf32(val);
    }
}

// ======================= host launcher =====================================
extern "C" void kernel_launch(void* const* d_in, const int* in_sizes, int n_in,
                              void* d_out, int out_size) {
    const float* x  = (const float*)d_in[0];
    const int*   ei = (const int*)d_in[1];
    const float* W[3]  = {(const float*)d_in[2],  (const float*)d_in[6],  (const float*)d_in[10]};
    const float* AS[3] = {(const float*)d_in[3],  (const float*)d_in[7],  (const float*)d_in[11]};
    const float* AD[3] = {(const float*)d_in[4],  (const float*)d_in[8],  (const float*)d_in[12]};
    const float* B[3]  = {(const float*)d_in[5],  (const float*)d_in[9],  (const float*)d_in[13]};

    const int Cc[3] = {in_sizes[5], in_sizes[9], in_sizes[13]};
    const int H = in_sizes[3] / Cc[0];
    const int E = in_sizes[1] / 2;
    const int N = out_size / Cc[2];
    const int F_IN = in_sizes[0] / N;

    __half* hbuf;
    float *ebuf, *At, *Bt;
    int *rowptr, *cnt, *cursor, *col;
    cudaGetSymbolAddress((void**)&hbuf,   g_h);
    cudaGetSymbolAddress((void**)&ebuf,   g_e);
    cudaGetSymbolAddress((void**)&At,     g_At);
    cudaGetSymbolAddress((void**)&Bt,     g_Bt);
    cudaGetSymbolAddress((void**)&rowptr, g_rowptr);
    cudaGetSymbolAddress((void**)&cnt,    g_cnt);
    cudaGetSymbolAddress((void**)&cursor, g_cursor);
    cudaGetSymbolAddress((void**)&col,    g_col);

    float* esrc = ebuf;
    float* edst = ebuf + (size_t)N_MAX * H_MAX;

    cudaFuncSetAttribute(gemm_mma, cudaFuncAttributeMaxDynamicSharedMemorySize, GEMM_SMEM);

    int K = F_IN;

    for (int l = 0; l < 3; ++l) {
        int C = Cc[l], HC = H * C;

        if (l == 0) {
            int total4 = (N * K) >> 2;
            int blocks = (total4 + 255) / 256;
            if (blocks > 4096) blocks = 4096;
            round_k<<<blocks, 256>>>((const float4*)x, (float4*)At, total4);
        }
        {
            dim3 gr(HC / 32, K / 32), b(32, 8);
            tW_k<<<gr, b>>>(W[l], Bt, K, HC);
        }
        if (l == 0) cudaMemsetAsync(cnt, 0, N * sizeof(int));
        cudaMemsetAsync(ebuf, 0, 2 * N_MAX * H_MAX * sizeof(float));   // esrc+edst
        {
            int nx = HC / 128;
            int ntiles = nx * ((N + 127) / 128);
            int grid = (ntiles < GEMM_GRID) ? ntiles : GEMM_GRID;
            gemm_mma<<<grid, 256, GEMM_SMEM>>>(At, Bt, hbuf,
                                               AS[l], AD[l], esrc, edst,
                                               N, HC, K, C, H, nx, ntiles);
        }
        if (l == 0) {
            int tot = E + N;
            int blocks = (tot + 255) / 256;
            count_k<<<blocks, 256>>>(ei + E, E, N, cnt);
            scan_k<<<1, 1024>>>(cnt, rowptr, N);
            cudaMemcpyAsync(cursor, rowptr, N * sizeof(int), cudaMemcpyDeviceToDevice);
            fill_k<<<blocks, 256>>>(ei, ei + E, E, N, cursor, col);
        }
        aggregate_k<<<N, 256>>>(hbuf, esrc, edst, rowptr, col, B[l], (float*)d_out,
                                At, (l == 2) ? 1 : 0, H, C, HC, 1.0f / (float)H);
        K = C;
    }
}

// round 13
// speedup vs baseline: 3.2793x; 1.0204x over previous
#include <cuda_runtime.h>
#include <cuda_bf16.h>
#include <cuda_fp16.h>
#include <cstdint>

// ---------------------------------------------------------------------------
// GAT (3 layers, H=4 heads, concat=False/mean) for B200 (base sm_100 PTX).
// Per layer:
//   0) round x -> tf32 (layer 0 only; layers 1,2 fused into aggregate)
//      transpose+round W -> [HC][K] tf32
//   1) PERSISTENT warp-mma tf32 GEMM (single pass, fp32 accum, 2 CTAs/SM):
//      h = x @ W; epilogue: h fp16 + fused logits via atomics
//   2) per-dst softmax (no-max-sub, exact) + weighted gather-sum via CSR:
//      2 nodes per 256-thr block, 16B gather loads, mean heads + bias,
//      fused tf32 rounding of the result
// ---------------------------------------------------------------------------

#define N_MAX   10240
#define K_MAXD  512
#define HC_MAX  1024
#define C_MAX   256
#define H_MAX   8
#define ET_MAX  204800
#define GEMM_GRID 296   // 2 CTAs/SM x 148 SMs

__device__ __align__(128) __half g_h[(size_t)N_MAX * HC_MAX];
__device__ __align__(128) float g_e[2 * N_MAX * H_MAX];           // esrc | edst
__device__ __align__(128) float g_At[(size_t)N_MAX * K_MAXD];     // tf32-rounded A
__device__ __align__(128) float g_Bt[(size_t)HC_MAX * K_MAXD];    // tf32-rounded W^T
__device__ int g_rowptr[N_MAX + 1];
__device__ int g_cnt[N_MAX];
__device__ int g_cursor[N_MAX];
__device__ int g_col[ET_MAX];

// ======================= helpers ==========================================
__device__ __forceinline__ uint32_t smem_u32(const void* p) {
    uint32_t a;
    asm("{ .reg .u64 t; cvta.to.shared.u64 t, %1; cvt.u32.u64 %0, t; }" : "=r"(a) : "l"(p));
    return a;
}

// cvt.rna.tf32.f32 writes a .b32 destination (NOT .f32) — use "=r".
__device__ __forceinline__ float to_tf32(float v) {
    uint32_t o;
    asm("cvt.rna.tf32.f32 %0, %1;" : "=r"(o) : "f"(v));
    return __uint_as_float(o);
}

__device__ __forceinline__ void cp16(uint32_t saddr, const void* gaddr, int srcbytes) {
    asm volatile("cp.async.cg.shared.global [%0], [%1], 16, %2;"
                 :: "r"(saddr), "l"(gaddr), "r"(srcbytes) : "memory");
}
__device__ __forceinline__ void cp_commit() {
    asm volatile("cp.async.commit_group;" ::: "memory");
}
template <int NN>
__device__ __forceinline__ void cp_wait() {
    asm volatile("cp.async.wait_group %0;" :: "n"(NN) : "memory");
}

__device__ __forceinline__ void ldsm4(uint32_t* r, uint32_t addr) {
    asm volatile("ldmatrix.sync.aligned.m8n8.x4.shared.b16 {%0,%1,%2,%3}, [%4];"
                 : "=r"(r[0]), "=r"(r[1]), "=r"(r[2]), "=r"(r[3]) : "r"(addr));
}

__device__ __forceinline__ void mma_tf32(float* d, const uint32_t* a, const uint32_t* b) {
    asm volatile(
        "mma.sync.aligned.m16n8k8.row.col.f32.tf32.tf32.f32 "
        "{%0,%1,%2,%3}, {%4,%5,%6,%7}, {%8,%9}, {%0,%1,%2,%3};"
        : "+f"(d[0]), "+f"(d[1]), "+f"(d[2]), "+f"(d[3])
        : "r"(a[0]), "r"(a[1]), "r"(a[2]), "r"(a[3]), "r"(b[0]), "r"(b[1]));
}

// ======================= pre-kernels =======================================
__global__ void round_k(const float4* __restrict__ X, float4* __restrict__ A, int total4) {
    int stride = gridDim.x * blockDim.x;
    for (int i = blockIdx.x * blockDim.x + threadIdx.x; i < total4; i += stride) {
        float4 v = X[i];
        v.x = to_tf32(v.x); v.y = to_tf32(v.y);
        v.z = to_tf32(v.z); v.w = to_tf32(v.w);
        A[i] = v;
    }
}

// W [K][HC] row-major -> Bt [HC][K] tf32-rounded
__global__ void tW_k(const float* __restrict__ W, float* __restrict__ Bt, int K, int HC) {
    __shared__ float t[32][33];
    int kb = blockIdx.y * 32, nb = blockIdx.x * 32;
    int tx = threadIdx.x, ty = threadIdx.y;   // 32 x 8
    for (int i = ty; i < 32; i += 8)
        t[i][tx] = W[(size_t)(kb + i) * HC + nb + tx];
    __syncthreads();
    for (int i = ty; i < 32; i += 8)
        Bt[(size_t)(nb + i) * K + kb + tx] = to_tf32(t[tx][i]);
}

// ======================= persistent warp-mma tf32 GEMM + fused logits ======
// C[M, HC] = A[M,K] @ W[K,HC]. Block 256 thr (8 warps 4x2: warp tile 32x64),
// block tile 128x128, BK=32, double-buffered cp.async, 2 CTAs/SM.
// Smem stage 32KB. Swizzle: 16B chunk at soff(m,c) = m*128 + ((c^(m&7))<<4).
#define GEMM_SMEM 65536

__global__ __launch_bounds__(256, 2)
void gemm_mma(const float* __restrict__ At, const float* __restrict__ Bt,
              __half* __restrict__ C, const float* __restrict__ as_g,
              const float* __restrict__ ad_g, float* __restrict__ esrc,
              float* __restrict__ edst, int M, int Ncols, int K, int Cc, int H,
              int ntiles_x, int ntiles) {
    extern __shared__ __align__(1024) char smem[];
    const uint32_t sbase = smem_u32(smem);
    const int tid = threadIdx.x;
    const int lane = tid & 31, wid = tid >> 5;
    const int warp_m = wid & 3;
    const int warp_n = wid >> 2;
    const int g = lane >> 3, r = lane & 7;
    const int nch = K >> 5;   // BK=32

    for (int tile = blockIdx.x; tile < ntiles; tile += gridDim.x) {
        const int mtile = tile / ntiles_x;
        const int ntile = tile - mtile * ntiles_x;

        float acc[2][8][4] = {};

        auto load_stage = [&](int buf, int ch) {
            const int kb = ch << 5;
            const uint32_t sb = sbase + buf * 32768;
#pragma unroll
            for (int j = 0; j < 4; ++j) {
                int chunk = tid + (j << 8);        // 0..1023
                int m = chunk >> 3, c = chunk & 7; // row, 16B chunk
                uint32_t soff = m * 128 + ((c ^ (m & 7)) << 4);
                int arow = mtile * 128 + m;
                int aval = (arow < M) ? 16 : 0;
                int ar = (arow < M) ? arow : (M - 1);
                cp16(sb + soff, At + (size_t)ar * K + kb + c * 4, aval);
                int brow = ntile * 128 + m;
                cp16(sb + 16384 + soff, Bt + (size_t)brow * K + kb + c * 4, 16);
            }
        };

        load_stage(0, 0);
        cp_commit();

        for (int ch = 0; ch < nch; ++ch) {
            const int nxt = ch + 1;
            if (nxt < nch) { load_stage(nxt & 1, nxt); cp_commit(); }
            if (nxt < nch) cp_wait<1>(); else cp_wait<0>();
            __syncthreads();

            const uint32_t sb = sbase + (ch & 1) * 32768;
#pragma unroll
            for (int k8 = 0; k8 < 4; ++k8) {
                const int c0 = k8 * 2;
                uint32_t af[2][4], bf[8][2];
#pragma unroll
                for (int mt = 0; mt < 2; ++mt) {
                    int ml = warp_m * 32 + mt * 16 + r + ((g & 1) << 3);
                    int cc = c0 + (g >> 1);
                    uint32_t ad = sb + ml * 128 + ((cc ^ (ml & 7)) << 4);
                    ldsm4(af[mt], ad);
                }
#pragma unroll
                for (int nt2 = 0; nt2 < 4; ++nt2) {
                    int nl = warp_n * 64 + nt2 * 16 + r + ((g >> 1) << 3);
                    int cc = c0 + (g & 1);
                    uint32_t bd = sb + 16384 + nl * 128 + ((cc ^ (nl & 7)) << 4);
                    uint32_t tb[4];
                    ldsm4(tb, bd);
                    bf[nt2 * 2][0] = tb[0]; bf[nt2 * 2][1] = tb[1];
                    bf[nt2 * 2 + 1][0] = tb[2]; bf[nt2 * 2 + 1][1] = tb[3];
                }
#pragma unroll
                for (int mt = 0; mt < 2; ++mt)
#pragma unroll
                    for (int nt = 0; nt < 8; ++nt)
                        mma_tf32(acc[mt][nt], af[mt], bf[nt]);
            }
            __syncthreads();
        }

        // ---- epilogue 1: store C as fp16 ----
#pragma unroll
        for (int mt = 0; mt < 2; ++mt) {
            int row0 = mtile * 128 + warp_m * 32 + mt * 16 + (lane >> 2);
#pragma unroll
            for (int nt = 0; nt < 8; ++nt) {
                int col = ntile * 128 + warp_n * 64 + nt * 8 + (lane & 3) * 2;
                if (row0 < M)
                    *reinterpret_cast<__half2*>(&C[(size_t)row0 * Ncols + col]) =
                        __floats2half2_rn(acc[mt][nt][0], acc[mt][nt][1]);
                if (row0 + 8 < M)
                    *reinterpret_cast<__half2*>(&C[(size_t)(row0 + 8) * Ncols + col]) =
                        __floats2half2_rn(acc[mt][nt][2], acc[mt][nt][3]);
            }
        }

        // ---- epilogue 2: fused logits partial dots (fp32-exact) ----
        float es[4] = {0.f, 0.f, 0.f, 0.f}, ed[4] = {0.f, 0.f, 0.f, 0.f};
#pragma unroll
        for (int nt = 0; nt < 8; ++nt) {
            int col = ntile * 128 + warp_n * 64 + nt * 8 + (lane & 3) * 2;
            float a0 = as_g[col], a1 = as_g[col + 1];
            float d0 = ad_g[col], d1 = ad_g[col + 1];
#pragma unroll
            for (int mt = 0; mt < 2; ++mt) {
                es[mt * 2 + 0] += acc[mt][nt][0] * a0 + acc[mt][nt][1] * a1;
                es[mt * 2 + 1] += acc[mt][nt][2] * a0 + acc[mt][nt][3] * a1;
                ed[mt * 2 + 0] += acc[mt][nt][0] * d0 + acc[mt][nt][1] * d1;
                ed[mt * 2 + 1] += acc[mt][nt][2] * d0 + acc[mt][nt][3] * d1;
            }
        }
#pragma unroll
        for (int o = 1; o <= 2; o <<= 1)
#pragma unroll
            for (int i = 0; i < 4; ++i) {
                es[i] += __shfl_xor_sync(0xffffffffu, es[i], o);
                ed[i] += __shfl_xor_sync(0xffffffffu, ed[i], o);
            }
        if ((lane & 3) == 0) {
            int hh = (ntile * 128 + warp_n * 64) / Cc;
#pragma unroll
            for (int mt = 0; mt < 2; ++mt) {
                int row = mtile * 128 + warp_m * 32 + mt * 16 + (lane >> 2);
                if (row < M) {
                    atomicAdd(&esrc[row * H + hh], es[mt * 2 + 0]);
                    atomicAdd(&edst[row * H + hh], ed[mt * 2 + 0]);
                }
                if (row + 8 < M) {
                    atomicAdd(&esrc[(row + 8) * H + hh], es[mt * 2 + 1]);
                    atomicAdd(&edst[(row + 8) * H + hh], ed[mt * 2 + 1]);
                }
            }
        }
        __syncthreads();   // smem safe before next tile's loads
    }
}

// ======================= CSR build =========================================
__global__ void count_k(const int* __restrict__ dst, int E, int n, int* __restrict__ cnt) {
    int i = blockIdx.x * blockDim.x + threadIdx.x;
    int tot = E + n;
    if (i < tot) {
        int d = (i < E) ? dst[i] : (i - E);
        atomicAdd(&cnt[d], 1);
    }
}

// Exclusive scan, single block 1024 thr, shfl-based.
__global__ void scan_k(const int* __restrict__ cnt, int* __restrict__ rowptr, int n) {
    __shared__ int wsum[32];
    __shared__ int carry_sh;
    int tid = threadIdx.x, lane = tid & 31, wid = tid >> 5;
    if (tid == 0) carry_sh = 0;
    __syncthreads();
    for (int base = 0; base < n; base += 1024) {
        int v = (base + tid < n) ? cnt[base + tid] : 0;
        int x = v;
#pragma unroll
        for (int o = 1; o < 32; o <<= 1) {
            int t = __shfl_up_sync(0xffffffffu, x, o);
            if (lane >= o) x += t;
        }
        if (lane == 31) wsum[wid] = x;
        __syncthreads();
        if (wid == 0) {
            int s = wsum[lane];
#pragma unroll
            for (int o = 1; o < 32; o <<= 1) {
                int t = __shfl_up_sync(0xffffffffu, s, o);
                if (lane >= o) s += t;
            }
            wsum[lane] = s;
        }
        __syncthreads();
        int cin = carry_sh;
        int incl = x + ((wid > 0) ? wsum[wid - 1] : 0);
        if (base + tid < n) rowptr[base + tid] = cin + incl - v;
        __syncthreads();
        if (tid == 0) carry_sh = cin + wsum[31];
        __syncthreads();
    }
    if (tid == 0) rowptr[n] = carry_sh;
}

__global__ void fill_k(const int* __restrict__ src, const int* __restrict__ dst,
                       int E, int n, int* __restrict__ cursor, int* __restrict__ col) {
    int i = blockIdx.x * blockDim.x + threadIdx.x;
    int tot = E + n;
    if (i < tot) {
        int s, d;
        if (i < E) { s = src[i]; d = dst[i]; }
        else       { s = d = i - E; }
        int pos = atomicAdd(&cursor[d], 1);
        col[pos] = s;
    }
}

// ======================= aggregation =======================================
// 2 dst nodes per 256-thr block (threads 0-127 node A, 128-255 node B).
// Per node: 4 warps, warp hh handles head hh for BOTH the weight phase and
// the gather (thread u: head u>>5, 8 channels, one 16B load per edge).
// Single-pass softmax (no max-sub; |logit| << 88, exact), dinv folded at end.
#define AGG_CAP 128

__global__ __launch_bounds__(256)
void aggregate_k(const __half* __restrict__ hbuf,
                 const float* __restrict__ esrc, const float* __restrict__ edst,
                 const int* __restrict__ rowptr, const int* __restrict__ col,
                 const float* __restrict__ bias, float* __restrict__ out,
                 float* __restrict__ anext, int write_out,
                 int H, int C, int HC, float invH, int N) {
    __shared__ float sh_dinv[2][H_MAX];
    __shared__ float w_sh[2][AGG_CAP * 4];
    __shared__ int col_sh[2][AGG_CAP];
    __shared__ float red_sh[2][HC_MAX];
    __shared__ int s_iters;

    const int tid = threadIdx.x;
    const int half = tid >> 7;          // node slot 0/1
    const int u = tid & 127;            // index within node
    const int hh = u >> 5;              // head (4 warps per node)
    const int q = u & 31;               // lane within head
    const int n = blockIdx.x * 2 + half;
    const bool nok = (n < N);

    int start = 0, end = 0;
    if (nok) { start = rowptr[n]; end = rowptr[n + 1]; }
    const int len = end - start;

    if (tid == 0) s_iters = 0;
    __syncthreads();
    if (u == 0 && nok) atomicMax(&s_iters, (len + AGG_CAP - 1) / AGG_CAP);
    __syncthreads();
    const int iters = s_iters;

    const float edh = nok ? edst[n * H + hh] : 0.f;
    float ssum = 0.f;

    const int base = hh * C + (q << 3);     // 8 channels per thread
    float a0 = 0.f, a1 = 0.f, a2 = 0.f, a3 = 0.f,
          a4 = 0.f, a5 = 0.f, a6 = 0.f, a7 = 0.f;

    for (int it = 0; it < iters; ++it) {
        int cb = start + it * AGG_CAP;
        int cnt = end - cb;
        if (cnt > AGG_CAP) cnt = AGG_CAP;
        if (cnt > 0) {
            for (int e = q; e < cnt; e += 32) {
                int s = col[cb + e];
                if (hh == 0) col_sh[half][e] = s;
                float v = esrc[s * H + hh] + edh;
                v = v > 0.f ? v : 0.2f * v;
                float w = __expf(fminf(v, 60.f));
                w_sh[half][e * 4 + hh] = w;
                ssum += w;
            }
        }
        __syncthreads();
        if (cnt > 0) {
            for (int e = 0; e < cnt; ++e) {
                const uint4 pv = *reinterpret_cast<const uint4*>(
                    hbuf + (size_t)col_sh[half][e] * HC + base);
                const float w = w_sh[half][e * 4 + hh];
                const float2 v01 = __half22float2(*reinterpret_cast<const __half2*>(&pv.x));
                const float2 v23 = __half22float2(*reinterpret_cast<const __half2*>(&pv.y));
                const float2 v45 = __half22float2(*reinterpret_cast<const __half2*>(&pv.z));
                const float2 v67 = __half22float2(*reinterpret_cast<const __half2*>(&pv.w));
                a0 += w * v01.x; a1 += w * v01.y;
                a2 += w * v23.x; a3 += w * v23.y;
                a4 += w * v45.x; a5 += w * v45.y;
                a6 += w * v67.x; a7 += w * v67.y;
            }
        }
        __syncthreads();
    }

    // per-head weight-sum reduction (each warp = one head of its node)
#pragma unroll
    for (int o = 16; o > 0; o >>= 1) ssum += __shfl_xor_sync(0xffffffffu, ssum, o);
    if (q == 0) sh_dinv[half][hh] = 1.f / (ssum + 1e-16f);
    __syncthreads();

    {
        const float dinv = sh_dinv[half][hh];
        float* rp = &red_sh[half][base];
        rp[0] = a0 * dinv; rp[1] = a1 * dinv; rp[2] = a2 * dinv; rp[3] = a3 * dinv;
        rp[4] = a4 * dinv; rp[5] = a5 * dinv; rp[6] = a6 * dinv; rp[7] = a7 * dinv;
    }
    __syncthreads();

    if (nok) {
        const int cpt = C >> 7;             // channels per thread (C=256 -> 2)
        for (int j = 0; j < cpt; ++j) {
            int c = u + j * 128;
            float s = 0.f;
#pragma unroll 4
            for (int h = 0; h < H; ++h) s += red_sh[half][h * C + c];
            float val = s * invH + bias[c];
            if (write_out) out[(size_t)n * C + c] = val;
            else           anext[(size_t)n * C + c] = to_tf32(val);
        }
    }
}

// ======================= host launcher =====================================
extern "C" void kernel_launch(void* const* d_in, const int* in_sizes, int n_in,
                              void* d_out, int out_size) {
    const float* x  = (const float*)d_in[0];
    const int*   ei = (const int*)d_in[1];
    const float* W[3]  = {(const float*)d_in[2],  (const float*)d_in[6],  (const float*)d_in[10]};
    const float* AS[3] = {(const float*)d_in[3],  (const float*)d_in[7],  (const float*)d_in[11]};
    const float* AD[3] = {(const float*)d_in[4],  (const float*)d_in[8],  (const float*)d_in[12]};
    const float* B[3]  = {(const float*)d_in[5],  (const float*)d_in[9],  (const float*)d_in[13]};

    const int Cc[3] = {in_sizes[5], in_sizes[9], in_sizes[13]};
    const int H = in_sizes[3] / Cc[0];
    const int E = in_sizes[1] / 2;
    const int N = out_size / Cc[2];
    const int F_IN = in_sizes[0] / N;

    __half* hbuf;
    float *ebuf, *At, *Bt;
    int *rowptr, *cnt, *cursor, *col;
    cudaGetSymbolAddress((void**)&hbuf,   g_h);
    cudaGetSymbolAddress((void**)&ebuf,   g_e);
    cudaGetSymbolAddress((void**)&At,     g_At);
    cudaGetSymbolAddress((void**)&Bt,     g_Bt);
    cudaGetSymbolAddress((void**)&rowptr, g_rowptr);
    cudaGetSymbolAddress((void**)&cnt,    g_cnt);
    cudaGetSymbolAddress((void**)&cursor, g_cursor);
    cudaGetSymbolAddress((void**)&col,    g_col);

    float* esrc = ebuf;
    float* edst = ebuf + (size_t)N_MAX * H_MAX;

    cudaFuncSetAttribute(gemm_mma, cudaFuncAttributeMaxDynamicSharedMemorySize, GEMM_SMEM);

    int K = F_IN;

    for (int l = 0; l < 3; ++l) {
        int C = Cc[l], HC = H * C;

        if (l == 0) {
            int total4 = (N * K) >> 2;
            int blocks = (total4 + 255) / 256;
            if (blocks > 4096) blocks = 4096;
            round_k<<<blocks, 256>>>((const float4*)x, (float4*)At, total4);
        }
        {
            dim3 gr(HC / 32, K / 32), b(32, 8);
            tW_k<<<gr, b>>>(W[l], Bt, K, HC);
        }
        if (l == 0) cudaMemsetAsync(cnt, 0, N * sizeof(int));
        cudaMemsetAsync(ebuf, 0, 2 * N_MAX * H_MAX * sizeof(float));   // esrc+edst
        {
            int nx = HC / 128;
            int ntiles = nx * ((N + 127) / 128);
            int grid = (ntiles < GEMM_GRID) ? ntiles : GEMM_GRID;
            gemm_mma<<<grid, 256, GEMM_SMEM>>>(At, Bt, hbuf,
                                               AS[l], AD[l], esrc, edst,
                                               N, HC, K, C, H, nx, ntiles);
        }
        if (l == 0) {
            int tot = E + N;
            int blocks = (tot + 255) / 256;
            count_k<<<blocks, 256>>>(ei + E, E, N, cnt);
            scan_k<<<1, 1024>>>(cnt, rowptr, N);
            cudaMemcpyAsync(cursor, rowptr, N * sizeof(int), cudaMemcpyDeviceToDevice);
            fill_k<<<blocks, 256>>>(ei, ei + E, E, N, cursor, col);
        }
        aggregate_k<<<(N + 1) / 2, 256>>>(hbuf, esrc, edst, rowptr, col, B[l],
                                          (float*)d_out, At, (l == 2) ? 1 : 0,
                                          H, C, HC, 1.0f / (float)H, N);
        K = C;
    }
}

// round 14
// speedup vs baseline: 3.3864x; 1.0327x over previous
#include <cuda_runtime.h>
#include <cuda_bf16.h>
#include <cuda_fp16.h>
#include <cstdint>

// ---------------------------------------------------------------------------
// GAT (3 layers, H=4 heads, concat=False/mean) for B200 (base sm_100 PTX).
//   pre0_k : round x->tf32 + transpose W0 + zero ebuf(par0) + zero cnt (fused)
//   gemm_mma: persistent warp-mma tf32 GEMM + fused logits (atomics)
//   aggtw_k: aggregate(layer l) + transpose W(l+1) + zero ebuf(par l+1) fused
// e-buffers are parity-double-buffered so zeroing can overlap reading.
// ---------------------------------------------------------------------------

#define N_MAX   10240
#define K_MAXD  512
#define HC_MAX  1024
#define C_MAX   256
#define H_MAX   8
#define ET_MAX  204800
#define GEMM_GRID 296
#define EOFF (N_MAX * H_MAX)

__device__ __align__(128) __half g_h[(size_t)N_MAX * HC_MAX];
__device__ __align__(128) float g_e[4 * EOFF];   // [esrc0|edst0|esrc1|edst1]
__device__ __align__(128) float g_At[(size_t)N_MAX * K_MAXD];
__device__ __align__(128) float g_Bt[(size_t)HC_MAX * K_MAXD];
__device__ int g_rowptr[N_MAX + 1];
__device__ int g_cnt[N_MAX];
__device__ int g_cursor[N_MAX];
__device__ int g_col[ET_MAX];

// ======================= helpers ==========================================
__device__ __forceinline__ uint32_t smem_u32(const void* p) {
    uint32_t a;
    asm("{ .reg .u64 t; cvta.to.shared.u64 t, %1; cvt.u32.u64 %0, t; }" : "=r"(a) : "l"(p));
    return a;
}

__device__ __forceinline__ float to_tf32(float v) {
    uint32_t o;
    asm("cvt.rna.tf32.f32 %0, %1;" : "=r"(o) : "f"(v));
    return __uint_as_float(o);
}

__device__ __forceinline__ void cp16(uint32_t saddr, const void* gaddr, int srcbytes) {
    asm volatile("cp.async.cg.shared.global [%0], [%1], 16, %2;"
                 :: "r"(saddr), "l"(gaddr), "r"(srcbytes) : "memory");
}
__device__ __forceinline__ void cp_commit() {
    asm volatile("cp.async.commit_group;" ::: "memory");
}
template <int NN>
__device__ __forceinline__ void cp_wait() {
    asm volatile("cp.async.wait_group %0;" :: "n"(NN) : "memory");
}

__device__ __forceinline__ void ldsm4(uint32_t* r, uint32_t addr) {
    asm volatile("ldmatrix.sync.aligned.m8n8.x4.shared.b16 {%0,%1,%2,%3}, [%4];"
                 : "=r"(r[0]), "=r"(r[1]), "=r"(r[2]), "=r"(r[3]) : "r"(addr));
}

__device__ __forceinline__ void mma_tf32(float* d, const uint32_t* a, const uint32_t* b) {
    asm volatile(
        "mma.sync.aligned.m16n8k8.row.col.f32.tf32.tf32.f32 "
        "{%0,%1,%2,%3}, {%4,%5,%6,%7}, {%8,%9}, {%0,%1,%2,%3};"
        : "+f"(d[0]), "+f"(d[1]), "+f"(d[2]), "+f"(d[3])
        : "r"(a[0]), "r"(a[1]), "r"(a[2]), "r"(a[3]), "r"(b[0]), "r"(b[1]));
}

// W [K][HC] tile transpose+round helper (one 32x32 tile per block, 256 thr)
__device__ __forceinline__ void tw_tile(const float* __restrict__ W,
                                        float* __restrict__ Bt,
                                        int K, int HC, int kb, int nb, int tid) {
    __shared__ float t[32][33];
    int tx = tid & 31, ty = tid >> 5;     // 32 x 8
    for (int i = ty; i < 32; i += 8)
        t[i][tx] = W[(size_t)(kb + i) * HC + nb + tx];
    __syncthreads();
    for (int i = ty; i < 32; i += 8)
        Bt[(size_t)(nb + i) * K + kb + tx] = to_tf32(t[tx][i]);
}

// ======================= fused layer-0 pre-kernel ==========================
// blocks [0,twB): transpose W0; [twB,twB+rB): round x; then zero ebuf; zero cnt
__global__ void pre0_k(const float4* __restrict__ X, float4* __restrict__ At,
                       int total4, int rB,
                       const float* __restrict__ W0, float* __restrict__ Bt,
                       int K, int HC, int twB,
                       float4* __restrict__ ez, int ez4, int z1B,
                       int4* __restrict__ cz, int cz4) {
    int b = blockIdx.x;
    int tid = threadIdx.x;
    if (b < twB) {
        int nxt = HC / 32;
        int kb = (b / nxt) * 32, nb = (b % nxt) * 32;
        tw_tile(W0, Bt, K, HC, kb, nb, tid);
    } else if (b < twB + rB) {
        int i0 = (b - twB) * 256 + tid;
        int stride = rB * 256;
        for (int i = i0; i < total4; i += stride) {
            float4 v = X[i];
            v.x = to_tf32(v.x); v.y = to_tf32(v.y);
            v.z = to_tf32(v.z); v.w = to_tf32(v.w);
            At[i] = v;
        }
    } else if (b < twB + rB + z1B) {
        int i0 = (b - twB - rB) * 256 + tid;
        int stride = z1B * 256;
        float4 z = make_float4(0.f, 0.f, 0.f, 0.f);
        for (int i = i0; i < ez4; i += stride) ez[i] = z;
    } else {
        int i0 = (b - twB - rB - z1B) * 256 + tid;
        int stride = 4 * 256;
        int4 z = make_int4(0, 0, 0, 0);
        for (int i = i0; i < cz4; i += stride) cz[i] = z;
    }
}

// ======================= persistent warp-mma tf32 GEMM + fused logits ======
#define GEMM_SMEM 65536

__global__ __launch_bounds__(256, 2)
void gemm_mma(const float* __restrict__ At, const float* __restrict__ Bt,
              __half* __restrict__ C, const float* __restrict__ as_g,
              const float* __restrict__ ad_g, float* __restrict__ esrc,
              float* __restrict__ edst, int M, int Ncols, int K, int Cc, int H,
              int ntiles_x, int ntiles) {
    extern __shared__ __align__(1024) char smem[];
    const uint32_t sbase = smem_u32(smem);
    const int tid = threadIdx.x;
    const int lane = tid & 31, wid = tid >> 5;
    const int warp_m = wid & 3;
    const int warp_n = wid >> 2;
    const int g = lane >> 3, r = lane & 7;
    const int nch = K >> 5;

    for (int tile = blockIdx.x; tile < ntiles; tile += gridDim.x) {
        const int mtile = tile / ntiles_x;
        const int ntile = tile - mtile * ntiles_x;

        float acc[2][8][4] = {};

        auto load_stage = [&](int buf, int ch) {
            const int kb = ch << 5;
            const uint32_t sb = sbase + buf * 32768;
#pragma unroll
            for (int j = 0; j < 4; ++j) {
                int chunk = tid + (j << 8);
                int m = chunk >> 3, c = chunk & 7;
                uint32_t soff = m * 128 + ((c ^ (m & 7)) << 4);
                int arow = mtile * 128 + m;
                int aval = (arow < M) ? 16 : 0;
                int ar = (arow < M) ? arow : (M - 1);
                cp16(sb + soff, At + (size_t)ar * K + kb + c * 4, aval);
                int brow = ntile * 128 + m;
                cp16(sb + 16384 + soff, Bt + (size_t)brow * K + kb + c * 4, 16);
            }
        };

        load_stage(0, 0);
        cp_commit();

        for (int ch = 0; ch < nch; ++ch) {
            const int nxt = ch + 1;
            if (nxt < nch) { load_stage(nxt & 1, nxt); cp_commit(); }
            if (nxt < nch) cp_wait<1>(); else cp_wait<0>();
            __syncthreads();

            const uint32_t sb = sbase + (ch & 1) * 32768;
#pragma unroll
            for (int k8 = 0; k8 < 4; ++k8) {
                const int c0 = k8 * 2;
                uint32_t af[2][4], bf[8][2];
#pragma unroll
                for (int mt = 0; mt < 2; ++mt) {
                    int ml = warp_m * 32 + mt * 16 + r + ((g & 1) << 3);
                    int cc = c0 + (g >> 1);
                    uint32_t ad = sb + ml * 128 + ((cc ^ (ml & 7)) << 4);
                    ldsm4(af[mt], ad);
                }
#pragma unroll
                for (int nt2 = 0; nt2 < 4; ++nt2) {
                    int nl = warp_n * 64 + nt2 * 16 + r + ((g >> 1) << 3);
                    int cc = c0 + (g & 1);
                    uint32_t bd = sb + 16384 + nl * 128 + ((cc ^ (nl & 7)) << 4);
                    uint32_t tb[4];
                    ldsm4(tb, bd);
                    bf[nt2 * 2][0] = tb[0]; bf[nt2 * 2][1] = tb[1];
                    bf[nt2 * 2 + 1][0] = tb[2]; bf[nt2 * 2 + 1][1] = tb[3];
                }
#pragma unroll
                for (int mt = 0; mt < 2; ++mt)
#pragma unroll
                    for (int nt = 0; nt < 8; ++nt)
                        mma_tf32(acc[mt][nt], af[mt], bf[nt]);
            }
            __syncthreads();
        }

        // epilogue 1: store C as fp16
#pragma unroll
        for (int mt = 0; mt < 2; ++mt) {
            int row0 = mtile * 128 + warp_m * 32 + mt * 16 + (lane >> 2);
#pragma unroll
            for (int nt = 0; nt < 8; ++nt) {
                int col = ntile * 128 + warp_n * 64 + nt * 8 + (lane & 3) * 2;
                if (row0 < M)
                    *reinterpret_cast<__half2*>(&C[(size_t)row0 * Ncols + col]) =
                        __floats2half2_rn(acc[mt][nt][0], acc[mt][nt][1]);
                if (row0 + 8 < M)
                    *reinterpret_cast<__half2*>(&C[(size_t)(row0 + 8) * Ncols + col]) =
                        __floats2half2_rn(acc[mt][nt][2], acc[mt][nt][3]);
            }
        }

        // epilogue 2: fused logits partial dots
        float es[4] = {0.f, 0.f, 0.f, 0.f}, ed[4] = {0.f, 0.f, 0.f, 0.f};
#pragma unroll
        for (int nt = 0; nt < 8; ++nt) {
            int col = ntile * 128 + warp_n * 64 + nt * 8 + (lane & 3) * 2;
            float a0 = as_g[col], a1 = as_g[col + 1];
            float d0 = ad_g[col], d1 = ad_g[col + 1];
#pragma unroll
            for (int mt = 0; mt < 2; ++mt) {
                es[mt * 2 + 0] += acc[mt][nt][0] * a0 + acc[mt][nt][1] * a1;
                es[mt * 2 + 1] += acc[mt][nt][2] * a0 + acc[mt][nt][3] * a1;
                ed[mt * 2 + 0] += acc[mt][nt][0] * d0 + acc[mt][nt][1] * d1;
                ed[mt * 2 + 1] += acc[mt][nt][2] * d0 + acc[mt][nt][3] * d1;
            }
        }
#pragma unroll
        for (int o = 1; o <= 2; o <<= 1)
#pragma unroll
            for (int i = 0; i < 4; ++i) {
                es[i] += __shfl_xor_sync(0xffffffffu, es[i], o);
                ed[i] += __shfl_xor_sync(0xffffffffu, ed[i], o);
            }
        if ((lane & 3) == 0) {
            int hh = (ntile * 128 + warp_n * 64) / Cc;
#pragma unroll
            for (int mt = 0; mt < 2; ++mt) {
                int row = mtile * 128 + warp_m * 32 + mt * 16 + (lane >> 2);
                if (row < M) {
                    atomicAdd(&esrc[row * H + hh], es[mt * 2 + 0]);
                    atomicAdd(&edst[row * H + hh], ed[mt * 2 + 0]);
                }
                if (row + 8 < M) {
                    atomicAdd(&esrc[(row + 8) * H + hh], es[mt * 2 + 1]);
                    atomicAdd(&edst[(row + 8) * H + hh], ed[mt * 2 + 1]);
                }
            }
        }
        __syncthreads();
    }
}

// ======================= CSR build =========================================
__global__ void count_k(const int* __restrict__ dst, int E, int n, int* __restrict__ cnt) {
    int i = blockIdx.x * blockDim.x + threadIdx.x;
    int tot = E + n;
    if (i < tot) {
        int d = (i < E) ? dst[i] : (i - E);
        atomicAdd(&cnt[d], 1);
    }
}

__global__ void scan_k(const int* __restrict__ cnt, int* __restrict__ rowptr, int n) {
    __shared__ int wsum[32];
    __shared__ int carry_sh;
    int tid = threadIdx.x, lane = tid & 31, wid = tid >> 5;
    if (tid == 0) carry_sh = 0;
    __syncthreads();
    for (int base = 0; base < n; base += 1024) {
        int v = (base + tid < n) ? cnt[base + tid] : 0;
        int x = v;
#pragma unroll
        for (int o = 1; o < 32; o <<= 1) {
            int t = __shfl_up_sync(0xffffffffu, x, o);
            if (lane >= o) x += t;
        }
        if (lane == 31) wsum[wid] = x;
        __syncthreads();
        if (wid == 0) {
            int s = wsum[lane];
#pragma unroll
            for (int o = 1; o < 32; o <<= 1) {
                int t = __shfl_up_sync(0xffffffffu, s, o);
                if (lane >= o) s += t;
            }
            wsum[lane] = s;
        }
        __syncthreads();
        int cin = carry_sh;
        int incl = x + ((wid > 0) ? wsum[wid - 1] : 0);
        if (base + tid < n) rowptr[base + tid] = cin + incl - v;
        __syncthreads();
        if (tid == 0) carry_sh = cin + wsum[31];
        __syncthreads();
    }
    if (tid == 0) rowptr[n] = carry_sh;
}

__global__ void fill_k(const int* __restrict__ src, const int* __restrict__ dst,
                       int E, int n, int* __restrict__ cursor, int* __restrict__ col) {
    int i = blockIdx.x * blockDim.x + threadIdx.x;
    int tot = E + n;
    if (i < tot) {
        int s, d;
        if (i < E) { s = src[i]; d = dst[i]; }
        else       { s = d = i - E; }
        int pos = atomicAdd(&cursor[d], 1);
        col[pos] = s;
    }
}

// ======================= fused aggregate + next-layer prep =================
// blocks [0,aggB): aggregate (2 nodes/block, as R13);
// blocks [aggB, aggB+twB): transpose W(l+1); remaining zB: zero next ebuf.
#define AGG_CAP 128

__global__ __launch_bounds__(256)
void aggtw_k(const __half* __restrict__ hbuf,
             const float* __restrict__ esrc, const float* __restrict__ edst,
             const int* __restrict__ rowptr, const int* __restrict__ col,
             const float* __restrict__ bias, float* __restrict__ out,
             float* __restrict__ anext, int write_out,
             int H, int C, int HC, float invH, int N, int aggB,
             const float* __restrict__ Wn, float* __restrict__ Bt,
             int Kn, int HCn, int twB,
             float4* __restrict__ ez, int ez4, int zB) {
    const int b = blockIdx.x;
    const int tid = threadIdx.x;

    if (b >= aggB) {
        if (b < aggB + twB) {
            int bb = b - aggB;
            int nxt = HCn / 32;
            int kb = (bb / nxt) * 32, nb = (bb % nxt) * 32;
            tw_tile(Wn, Bt, Kn, HCn, kb, nb, tid);
        } else if (zB > 0) {
            int i0 = (b - aggB - twB) * 256 + tid;
            int stride = zB * 256;
            float4 z = make_float4(0.f, 0.f, 0.f, 0.f);
            for (int i = i0; i < ez4; i += stride) ez[i] = z;
        }
        return;
    }

    __shared__ float sh_dinv[2][H_MAX];
    __shared__ float w_sh[2][AGG_CAP * 4];
    __shared__ int col_sh[2][AGG_CAP];
    __shared__ float red_sh[2][HC_MAX];
    __shared__ int s_iters;

    const int half = tid >> 7;
    const int u = tid & 127;
    const int hh = u >> 5;
    const int q = u & 31;
    const int n = b * 2 + half;
    const bool nok = (n < N);

    int start = 0, end = 0;
    if (nok) { start = rowptr[n]; end = rowptr[n + 1]; }
    const int len = end - start;

    if (tid == 0) s_iters = 0;
    __syncthreads();
    if (u == 0 && nok) atomicMax(&s_iters, (len + AGG_CAP - 1) / AGG_CAP);
    __syncthreads();
    const int iters = s_iters;

    const float edh = nok ? edst[n * H + hh] : 0.f;
    float ssum = 0.f;

    const int base = hh * C + (q << 3);
    float a0 = 0.f, a1 = 0.f, a2 = 0.f, a3 = 0.f,
          a4 = 0.f, a5 = 0.f, a6 = 0.f, a7 = 0.f;

    for (int it = 0; it < iters; ++it) {
        int cb = start + it * AGG_CAP;
        int cnt = end - cb;
        if (cnt > AGG_CAP) cnt = AGG_CAP;
        if (cnt > 0) {
            for (int e = q; e < cnt; e += 32) {
                int s = col[cb + e];
                if (hh == 0) col_sh[half][e] = s;
                float v = esrc[s * H + hh] + edh;
                v = v > 0.f ? v : 0.2f * v;
                float w = __expf(fminf(v, 60.f));
                w_sh[half][e * 4 + hh] = w;
                ssum += w;
            }
        }
        __syncthreads();
        if (cnt > 0) {
            for (int e = 0; e < cnt; ++e) {
                const uint4 pv = *reinterpret_cast<const uint4*>(
                    hbuf + (size_t)col_sh[half][e] * HC + base);
                const float w = w_sh[half][e * 4 + hh];
                const float2 v01 = __half22float2(*reinterpret_cast<const __half2*>(&pv.x));
                const float2 v23 = __half22float2(*reinterpret_cast<const __half2*>(&pv.y));
                const float2 v45 = __half22float2(*reinterpret_cast<const __half2*>(&pv.z));
                const float2 v67 = __half22float2(*reinterpret_cast<const __half2*>(&pv.w));
                a0 += w * v01.x; a1 += w * v01.y;
                a2 += w * v23.x; a3 += w * v23.y;
                a4 += w * v45.x; a5 += w * v45.y;
                a6 += w * v67.x; a7 += w * v67.y;
            }
        }
        __syncthreads();
    }

#pragma unroll
    for (int o = 16; o > 0; o >>= 1) ssum += __shfl_xor_sync(0xffffffffu, ssum, o);
    if (q == 0) sh_dinv[half][hh] = 1.f / (ssum + 1e-16f);
    __syncthreads();

    {
        const float dinv = sh_dinv[half][hh];
        float* rp = &red_sh[half][base];
        rp[0] = a0 * dinv; rp[1] = a1 * dinv; rp[2] = a2 * dinv; rp[3] = a3 * dinv;
        rp[4] = a4 * dinv; rp[5] = a5 * dinv; rp[6] = a6 * dinv; rp[7] = a7 * dinv;
    }
    __syncthreads();

    if (nok) {
        const int cpt = C >> 7;
        for (int j = 0; j < cpt; ++j) {
            int c = u + j * 128;
            float s = 0.f;
#pragma unroll 4
            for (int h = 0; h < H; ++h) s += red_sh[half][h * C + c];
            float val = s * invH + bias[c];
            if (write_out) out[(size_t)n * C + c] = val;
            else           anext[(size_t)n * C + c] = to_tf32(val);
        }
    }
}

// ======================= host launcher =====================================
extern "C" void kernel_launch(void* const* d_in, const int* in_sizes, int n_in,
                              void* d_out, int out_size) {
    const float* x  = (const float*)d_in[0];
    const int*   ei = (const int*)d_in[1];
    const float* W[3]  = {(const float*)d_in[2],  (const float*)d_in[6],  (const float*)d_in[10]};
    const float* AS[3] = {(const float*)d_in[3],  (const float*)d_in[7],  (const float*)d_in[11]};
    const float* AD[3] = {(const float*)d_in[4],  (const float*)d_in[8],  (const float*)d_in[12]};
    const float* B[3]  = {(const float*)d_in[5],  (const float*)d_in[9],  (const float*)d_in[13]};

    const int Cc[3] = {in_sizes[5], in_sizes[9], in_sizes[13]};
    const int H = in_sizes[3] / Cc[0];
    const int E = in_sizes[1] / 2;
    const int N = out_size / Cc[2];
    const int F_IN = in_sizes[0] / N;

    __half* hbuf;
    float *ebuf, *At, *Bt;
    int *rowptr, *cnt, *cursor, *col;
    cudaGetSymbolAddress((void**)&hbuf,   g_h);
    cudaGetSymbolAddress((void**)&ebuf,   g_e);
    cudaGetSymbolAddress((void**)&At,     g_At);
    cudaGetSymbolAddress((void**)&Bt,     g_Bt);
    cudaGetSymbolAddress((void**)&rowptr, g_rowptr);
    cudaGetSymbolAddress((void**)&cnt,    g_cnt);
    cudaGetSymbolAddress((void**)&cursor, g_cursor);
    cudaGetSymbolAddress((void**)&col,    g_col);

    cudaFuncSetAttribute(gemm_mma, cudaFuncAttributeMaxDynamicSharedMemorySize, GEMM_SMEM);

    const int aggB = (N + 1) / 2;
    const int ez4 = (2 * EOFF) / 4;   // one parity region in float4s

    // ---- fused layer-0 pre-work ----
    {
        int HC0 = H * Cc[0];
        int twB = (HC0 / 32) * (F_IN / 32);
        int total4 = (N * F_IN) >> 2;
        int rB = 1280, z1B = 32, z2B = 4;
        pre0_k<<<twB + rB + z1B + z2B, 256>>>(
            (const float4*)x, (float4*)At, total4, rB,
            W[0], Bt, F_IN, HC0, twB,
            (float4*)ebuf, ez4, z1B,
            (int4*)cnt, (N + 3) / 4);
    }

    // ---- CSR build ----
    {
        int tot = E + N;
        int blocks = (tot + 255) / 256;
        count_k<<<blocks, 256>>>(ei + E, E, N, cnt);
        scan_k<<<1, 1024>>>(cnt, rowptr, N);
        cudaMemcpyAsync(cursor, rowptr, N * sizeof(int), cudaMemcpyDeviceToDevice);
        fill_k<<<blocks, 256>>>(ei, ei + E, E, N, cursor, col);
    }

    int K = F_IN;
    for (int l = 0; l < 3; ++l) {
        int C = Cc[l], HC = H * C;
        int par = l & 1;
        float* esrc = ebuf + par * 2 * EOFF;
        float* edst = esrc + EOFF;

        {
            int nx = HC / 128;
            int ntiles = nx * ((N + 127) / 128);
            int grid = (ntiles < GEMM_GRID) ? ntiles : GEMM_GRID;
            gemm_mma<<<grid, 256, GEMM_SMEM>>>(At, Bt, hbuf,
                                               AS[l], AD[l], esrc, edst,
                                               N, HC, K, C, H, nx, ntiles);
        }

        if (l < 2) {
            int Kn = C, HCn = H * Cc[l + 1];
            int twB = (HCn / 32) * (Kn / 32);
            int zB = 32;
            float4* ezn = (float4*)(ebuf + ((l + 1) & 1) * 2 * EOFF);
            aggtw_k<<<aggB + twB + zB, 256>>>(
                hbuf, esrc, edst, rowptr, col, B[l], (float*)d_out, At, 0,
                H, C, HC, 1.0f / (float)H, N, aggB,
                W[l + 1], Bt, Kn, HCn, twB, ezn, ez4, zB);
        } else {
            aggtw_k<<<aggB, 256>>>(
                hbuf, esrc, edst, rowptr, col, B[l], (float*)d_out, At, 1,
                H, C, HC, 1.0f / (float)H, N, aggB,
                nullptr, nullptr, 0, 0, 0, nullptr, 0, 0);
        }
        K = C;
    }
}

// round 15
// speedup vs baseline: 3.4313x; 1.0132x over previous
#include <cuda_runtime.h>
#include <cuda_bf16.h>
#include <cuda_fp16.h>
#include <cstdint>

// ---------------------------------------------------------------------------
// GAT (3 layers, H=4 heads, concat=False/mean) for B200 (base sm_100 PTX).
//   pre0_k : round x->tf32 + transpose W0 + zero ebuf(par0) + zero cnt (fused)
//   gemm_mma: persistent warp-mma tf32 GEMM + fused logits (+ layer0: CSR count
//             in the persistent tail)
//   scan_k : exclusive scan -> rowptr AND cursor (memcpy fused)
//   aggtw_k: aggregate(layer l) + transpose W(l+1) + zero ebuf(par l+1) fused
// ---------------------------------------------------------------------------

#define N_MAX   10240
#define K_MAXD  512
#define HC_MAX  1024
#define C_MAX   256
#define H_MAX   8
#define ET_MAX  204800
#define GEMM_GRID 296
#define EOFF (N_MAX * H_MAX)

__device__ __align__(128) __half g_h[(size_t)N_MAX * HC_MAX];
__device__ __align__(128) float g_e[4 * EOFF];   // [esrc0|edst0|esrc1|edst1]
__device__ __align__(128) float g_At[(size_t)N_MAX * K_MAXD];
__device__ __align__(128) float g_Bt[(size_t)HC_MAX * K_MAXD];
__device__ int g_rowptr[N_MAX + 1];
__device__ int g_cnt[N_MAX];
__device__ int g_cursor[N_MAX];
__device__ int g_col[ET_MAX];

// ======================= helpers ==========================================
__device__ __forceinline__ uint32_t smem_u32(const void* p) {
    uint32_t a;
    asm("{ .reg .u64 t; cvta.to.shared.u64 t, %1; cvt.u32.u64 %0, t; }" : "=r"(a) : "l"(p));
    return a;
}

__device__ __forceinline__ float to_tf32(float v) {
    uint32_t o;
    asm("cvt.rna.tf32.f32 %0, %1;" : "=r"(o) : "f"(v));
    return __uint_as_float(o);
}

__device__ __forceinline__ void cp16(uint32_t saddr, const void* gaddr, int srcbytes) {
    asm volatile("cp.async.cg.shared.global [%0], [%1], 16, %2;"
                 :: "r"(saddr), "l"(gaddr), "r"(srcbytes) : "memory");
}
__device__ __forceinline__ void cp_commit() {
    asm volatile("cp.async.commit_group;" ::: "memory");
}
template <int NN>
__device__ __forceinline__ void cp_wait() {
    asm volatile("cp.async.wait_group %0;" :: "n"(NN) : "memory");
}

__device__ __forceinline__ void ldsm4(uint32_t* r, uint32_t addr) {
    asm volatile("ldmatrix.sync.aligned.m8n8.x4.shared.b16 {%0,%1,%2,%3}, [%4];"
                 : "=r"(r[0]), "=r"(r[1]), "=r"(r[2]), "=r"(r[3]) : "r"(addr));
}

__device__ __forceinline__ void mma_tf32(float* d, const uint32_t* a, const uint32_t* b) {
    asm volatile(
        "mma.sync.aligned.m16n8k8.row.col.f32.tf32.tf32.f32 "
        "{%0,%1,%2,%3}, {%4,%5,%6,%7}, {%8,%9}, {%0,%1,%2,%3};"
        : "+f"(d[0]), "+f"(d[1]), "+f"(d[2]), "+f"(d[3])
        : "r"(a[0]), "r"(a[1]), "r"(a[2]), "r"(a[3]), "r"(b[0]), "r"(b[1]));
}

// W [K][HC] tile transpose+round helper (one 32x32 tile per block, 256 thr)
__device__ __forceinline__ void tw_tile(const float* __restrict__ W,
                                        float* __restrict__ Bt,
                                        int K, int HC, int kb, int nb, int tid) {
    __shared__ float t[32][33];
    int tx = tid & 31, ty = tid >> 5;     // 32 x 8
    for (int i = ty; i < 32; i += 8)
        t[i][tx] = W[(size_t)(kb + i) * HC + nb + tx];
    __syncthreads();
    for (int i = ty; i < 32; i += 8)
        Bt[(size_t)(nb + i) * K + kb + tx] = to_tf32(t[tx][i]);
}

// ======================= fused layer-0 pre-kernel ==========================
__global__ void pre0_k(const float4* __restrict__ X, float4* __restrict__ At,
                       int total4, int rB,
                       const float* __restrict__ W0, float* __restrict__ Bt,
                       int K, int HC, int twB,
                       float4* __restrict__ ez, int ez4, int z1B,
                       int4* __restrict__ cz, int cz4) {
    int b = blockIdx.x;
    int tid = threadIdx.x;
    if (b < twB) {
        int nxt = HC / 32;
        int kb = (b / nxt) * 32, nb = (b % nxt) * 32;
        tw_tile(W0, Bt, K, HC, kb, nb, tid);
    } else if (b < twB + rB) {
        int i0 = (b - twB) * 256 + tid;
        int stride = rB * 256;
        for (int i = i0; i < total4; i += stride) {
            float4 v = X[i];
            v.x = to_tf32(v.x); v.y = to_tf32(v.y);
            v.z = to_tf32(v.z); v.w = to_tf32(v.w);
            At[i] = v;
        }
    } else if (b < twB + rB + z1B) {
        int i0 = (b - twB - rB) * 256 + tid;
        int stride = z1B * 256;
        float4 z = make_float4(0.f, 0.f, 0.f, 0.f);
        for (int i = i0; i < ez4; i += stride) ez[i] = z;
    } else {
        int i0 = (b - twB - rB - z1B) * 256 + tid;
        int stride = 4 * 256;
        int4 z = make_int4(0, 0, 0, 0);
        for (int i = i0; i < cz4; i += stride) cz[i] = z;
    }
}

// ======================= persistent warp-mma tf32 GEMM + fused logits ======
// Layer 0 additionally performs the CSR degree count (dstE + self loops) in
// the persistent tail: each CTA handles a static slice after its tiles drain.
#define GEMM_SMEM 65536

__global__ __launch_bounds__(256, 2)
void gemm_mma(const float* __restrict__ At, const float* __restrict__ Bt,
              __half* __restrict__ C, const float* __restrict__ as_g,
              const float* __restrict__ ad_g, float* __restrict__ esrc,
              float* __restrict__ edst, int M, int Ncols, int K, int Cc, int H,
              int ntiles_x, int ntiles,
              const int* __restrict__ dstE, int E, int Nn, int* __restrict__ cnt) {
    extern __shared__ __align__(1024) char smem[];
    const uint32_t sbase = smem_u32(smem);
    const int tid = threadIdx.x;
    const int lane = tid & 31, wid = tid >> 5;
    const int warp_m = wid & 3;
    const int warp_n = wid >> 2;
    const int g = lane >> 3, r = lane & 7;
    const int nch = K >> 5;

    for (int tile = blockIdx.x; tile < ntiles; tile += gridDim.x) {
        const int mtile = tile / ntiles_x;
        const int ntile = tile - mtile * ntiles_x;

        float acc[2][8][4] = {};

        auto load_stage = [&](int buf, int ch) {
            const int kb = ch << 5;
            const uint32_t sb = sbase + buf * 32768;
#pragma unroll
            for (int j = 0; j < 4; ++j) {
                int chunk = tid + (j << 8);
                int m = chunk >> 3, c = chunk & 7;
                uint32_t soff = m * 128 + ((c ^ (m & 7)) << 4);
                int arow = mtile * 128 + m;
                int aval = (arow < M) ? 16 : 0;
                int ar = (arow < M) ? arow : (M - 1);
                cp16(sb + soff, At + (size_t)ar * K + kb + c * 4, aval);
                int brow = ntile * 128 + m;
                cp16(sb + 16384 + soff, Bt + (size_t)brow * K + kb + c * 4, 16);
            }
        };

        load_stage(0, 0);
        cp_commit();

        for (int ch = 0; ch < nch; ++ch) {
            const int nxt = ch + 1;
            if (nxt < nch) { load_stage(nxt & 1, nxt); cp_commit(); }
            if (nxt < nch) cp_wait<1>(); else cp_wait<0>();
            __syncthreads();

            const uint32_t sb = sbase + (ch & 1) * 32768;
#pragma unroll
            for (int k8 = 0; k8 < 4; ++k8) {
                const int c0 = k8 * 2;
                uint32_t af[2][4], bf[8][2];
#pragma unroll
                for (int mt = 0; mt < 2; ++mt) {
                    int ml = warp_m * 32 + mt * 16 + r + ((g & 1) << 3);
                    int cc = c0 + (g >> 1);
                    uint32_t ad = sb + ml * 128 + ((cc ^ (ml & 7)) << 4);
                    ldsm4(af[mt], ad);
                }
#pragma unroll
                for (int nt2 = 0; nt2 < 4; ++nt2) {
                    int nl = warp_n * 64 + nt2 * 16 + r + ((g >> 1) << 3);
                    int cc = c0 + (g & 1);
                    uint32_t bd = sb + 16384 + nl * 128 + ((cc ^ (nl & 7)) << 4);
                    uint32_t tb[4];
                    ldsm4(tb, bd);
                    bf[nt2 * 2][0] = tb[0]; bf[nt2 * 2][1] = tb[1];
                    bf[nt2 * 2 + 1][0] = tb[2]; bf[nt2 * 2 + 1][1] = tb[3];
                }
#pragma unroll
                for (int mt = 0; mt < 2; ++mt)
#pragma unroll
                    for (int nt = 0; nt < 8; ++nt)
                        mma_tf32(acc[mt][nt], af[mt], bf[nt]);
            }
            __syncthreads();
        }

        // epilogue 1: store C as fp16
#pragma unroll
        for (int mt = 0; mt < 2; ++mt) {
            int row0 = mtile * 128 + warp_m * 32 + mt * 16 + (lane >> 2);
#pragma unroll
            for (int nt = 0; nt < 8; ++nt) {
                int col = ntile * 128 + warp_n * 64 + nt * 8 + (lane & 3) * 2;
                if (row0 < M)
                    *reinterpret_cast<__half2*>(&C[(size_t)row0 * Ncols + col]) =
                        __floats2half2_rn(acc[mt][nt][0], acc[mt][nt][1]);
                if (row0 + 8 < M)
                    *reinterpret_cast<__half2*>(&C[(size_t)(row0 + 8) * Ncols + col]) =
                        __floats2half2_rn(acc[mt][nt][2], acc[mt][nt][3]);
            }
        }

        // epilogue 2: fused logits partial dots
        float es[4] = {0.f, 0.f, 0.f, 0.f}, ed[4] = {0.f, 0.f, 0.f, 0.f};
#pragma unroll
        for (int nt = 0; nt < 8; ++nt) {
            int col = ntile * 128 + warp_n * 64 + nt * 8 + (lane & 3) * 2;
            float a0 = as_g[col], a1 = as_g[col + 1];
            float d0 = ad_g[col], d1 = ad_g[col + 1];
#pragma unroll
            for (int mt = 0; mt < 2; ++mt) {
                es[mt * 2 + 0] += acc[mt][nt][0] * a0 + acc[mt][nt][1] * a1;
                es[mt * 2 + 1] += acc[mt][nt][2] * a0 + acc[mt][nt][3] * a1;
                ed[mt * 2 + 0] += acc[mt][nt][0] * d0 + acc[mt][nt][1] * d1;
                ed[mt * 2 + 1] += acc[mt][nt][2] * d0 + acc[mt][nt][3] * d1;
            }
        }
#pragma unroll
        for (int o = 1; o <= 2; o <<= 1)
#pragma unroll
            for (int i = 0; i < 4; ++i) {
                es[i] += __shfl_xor_sync(0xffffffffu, es[i], o);
                ed[i] += __shfl_xor_sync(0xffffffffu, ed[i], o);
            }
        if ((lane & 3) == 0) {
            int hh = (ntile * 128 + warp_n * 64) / Cc;
#pragma unroll
            for (int mt = 0; mt < 2; ++mt) {
                int row = mtile * 128 + warp_m * 32 + mt * 16 + (lane >> 2);
                if (row < M) {
                    atomicAdd(&esrc[row * H + hh], es[mt * 2 + 0]);
                    atomicAdd(&edst[row * H + hh], ed[mt * 2 + 0]);
                }
                if (row + 8 < M) {
                    atomicAdd(&esrc[(row + 8) * H + hh], es[mt * 2 + 1]);
                    atomicAdd(&edst[(row + 8) * H + hh], ed[mt * 2 + 1]);
                }
            }
        }
        __syncthreads();
    }

    // ---- persistent tail: CSR degree count (layer 0 only) ----
    if (cnt != nullptr) {
        const int tot = E + Nn;
        const int chunk = (tot + gridDim.x - 1) / gridDim.x;
        const int i0 = blockIdx.x * chunk;
        int i1 = i0 + chunk;
        if (i1 > tot) i1 = tot;
        for (int i = i0 + tid; i < i1; i += 256) {
            int d = (i < E) ? dstE[i] : (i - E);
            atomicAdd(&cnt[d], 1);
        }
    }
}

// ======================= CSR scan (rowptr + cursor) ========================
__global__ void scan_k(const int* __restrict__ cnt, int* __restrict__ rowptr,
                       int* __restrict__ cursor, int n) {
    __shared__ int wsum[32];
    __shared__ int carry_sh;
    int tid = threadIdx.x, lane = tid & 31, wid = tid >> 5;
    if (tid == 0) carry_sh = 0;
    __syncthreads();
    for (int base = 0; base < n; base += 1024) {
        int v = (base + tid < n) ? cnt[base + tid] : 0;
        int x = v;
#pragma unroll
        for (int o = 1; o < 32; o <<= 1) {
            int t = __shfl_up_sync(0xffffffffu, x, o);
            if (lane >= o) x += t;
        }
        if (lane == 31) wsum[wid] = x;
        __syncthreads();
        if (wid == 0) {
            int s = wsum[lane];
#pragma unroll
            for (int o = 1; o < 32; o <<= 1) {
                int t = __shfl_up_sync(0xffffffffu, s, o);
                if (lane >= o) s += t;
            }
            wsum[lane] = s;
        }
        __syncthreads();
        int cin = carry_sh;
        int incl = x + ((wid > 0) ? wsum[wid - 1] : 0);
        if (base + tid < n) {
            int rp = cin + incl - v;
            rowptr[base + tid] = rp;
            cursor[base + tid] = rp;
        }
        __syncthreads();
        if (tid == 0) carry_sh = cin + wsum[31];
        __syncthreads();
    }
    if (tid == 0) rowptr[n] = carry_sh;
}

__global__ void fill_k(const int* __restrict__ src, const int* __restrict__ dst,
                       int E, int n, int* __restrict__ cursor, int* __restrict__ col) {
    int i = blockIdx.x * blockDim.x + threadIdx.x;
    int tot = E + n;
    if (i < tot) {
        int s, d;
        if (i < E) { s = src[i]; d = dst[i]; }
        else       { s = d = i - E; }
        int pos = atomicAdd(&cursor[d], 1);
        col[pos] = s;
    }
}

// ======================= fused aggregate + next-layer prep =================
#define AGG_CAP 128

__global__ __launch_bounds__(256)
void aggtw_k(const __half* __restrict__ hbuf,
             const float* __restrict__ esrc, const float* __restrict__ edst,
             const int* __restrict__ rowptr, const int* __restrict__ col,
             const float* __restrict__ bias, float* __restrict__ out,
             float* __restrict__ anext, int write_out,
             int H, int C, int HC, float invH, int N, int aggB,
             const float* __restrict__ Wn, float* __restrict__ Bt,
             int Kn, int HCn, int twB,
             float4* __restrict__ ez, int ez4, int zB) {
    const int b = blockIdx.x;
    const int tid = threadIdx.x;

    if (b >= aggB) {
        if (b < aggB + twB) {
            int bb = b - aggB;
            int nxt = HCn / 32;
            int kb = (bb / nxt) * 32, nb = (bb % nxt) * 32;
            tw_tile(Wn, Bt, Kn, HCn, kb, nb, tid);
        } else if (zB > 0) {
            int i0 = (b - aggB - twB) * 256 + tid;
            int stride = zB * 256;
            float4 z = make_float4(0.f, 0.f, 0.f, 0.f);
            for (int i = i0; i < ez4; i += stride) ez[i] = z;
        }
        return;
    }

    __shared__ float sh_dinv[2][H_MAX];
    __shared__ float w_sh[2][AGG_CAP * 4];
    __shared__ int col_sh[2][AGG_CAP];
    __shared__ float red_sh[2][HC_MAX];
    __shared__ int s_iters;

    const int half = tid >> 7;
    const int u = tid & 127;
    const int hh = u >> 5;
    const int q = u & 31;
    const int n = b * 2 + half;
    const bool nok = (n < N);

    int start = 0, end = 0;
    if (nok) { start = rowptr[n]; end = rowptr[n + 1]; }
    const int len = end - start;

    if (tid == 0) s_iters = 0;
    __syncthreads();
    if (u == 0 && nok) atomicMax(&s_iters, (len + AGG_CAP - 1) / AGG_CAP);
    __syncthreads();
    const int iters = s_iters;

    const float edh = nok ? edst[n * H + hh] : 0.f;
    float ssum = 0.f;

    const int base = hh * C + (q << 3);
    float a0 = 0.f, a1 = 0.f, a2 = 0.f, a3 = 0.f,
          a4 = 0.f, a5 = 0.f, a6 = 0.f, a7 = 0.f;

    for (int it = 0; it < iters; ++it) {
        int cb = start + it * AGG_CAP;
        int cnt = end - cb;
        if (cnt > AGG_CAP) cnt = AGG_CAP;
        if (cnt > 0) {
            for (int e = q; e < cnt; e += 32) {
                int s = col[cb + e];
                if (hh == 0) col_sh[half][e] = s;
                float v = esrc[s * H + hh] + edh;
                v = v > 0.f ? v : 0.2f * v;
                float w = __expf(fminf(v, 60.f));
                w_sh[half][e * 4 + hh] = w;
                ssum += w;
            }
        }
        __syncthreads();
        if (cnt > 0) {
            for (int e = 0; e < cnt; ++e) {
                const uint4 pv = *reinterpret_cast<const uint4*>(
                    hbuf + (size_t)col_sh[half][e] * HC + base);
                const float w = w_sh[half][e * 4 + hh];
                const float2 v01 = __half22float2(*reinterpret_cast<const __half2*>(&pv.x));
                const float2 v23 = __half22float2(*reinterpret_cast<const __half2*>(&pv.y));
                const float2 v45 = __half22float2(*reinterpret_cast<const __half2*>(&pv.z));
                const float2 v67 = __half22float2(*reinterpret_cast<const __half2*>(&pv.w));
                a0 += w * v01.x; a1 += w * v01.y;
                a2 += w * v23.x; a3 += w * v23.y;
                a4 += w * v45.x; a5 += w * v45.y;
                a6 += w * v67.x; a7 += w * v67.y;
            }
        }
        __syncthreads();
    }

#pragma unroll
    for (int o = 16; o > 0; o >>= 1) ssum += __shfl_xor_sync(0xffffffffu, ssum, o);
    if (q == 0) sh_dinv[half][hh] = 1.f / (ssum + 1e-16f);
    __syncthreads();

    {
        const float dinv = sh_dinv[half][hh];
        float* rp = &red_sh[half][base];
        rp[0] = a0 * dinv; rp[1] = a1 * dinv; rp[2] = a2 * dinv; rp[3] = a3 * dinv;
        rp[4] = a4 * dinv; rp[5] = a5 * dinv; rp[6] = a6 * dinv; rp[7] = a7 * dinv;
    }
    __syncthreads();

    if (nok) {
        const int cpt = C >> 7;
        for (int j = 0; j < cpt; ++j) {
            int c = u + j * 128;
            float s = 0.f;
#pragma unroll 4
            for (int h = 0; h < H; ++h) s += red_sh[half][h * C + c];
            float val = s * invH + bias[c];
            if (write_out) out[(size_t)n * C + c] = val;
            else           anext[(size_t)n * C + c] = to_tf32(val);
        }
    }
}

// ======================= host launcher =====================================
extern "C" void kernel_launch(void* const* d_in, const int* in_sizes, int n_in,
                              void* d_out, int out_size) {
    const float* x  = (const float*)d_in[0];
    const int*   ei = (const int*)d_in[1];
    const float* W[3]  = {(const float*)d_in[2],  (const float*)d_in[6],  (const float*)d_in[10]};
    const float* AS[3] = {(const float*)d_in[3],  (const float*)d_in[7],  (const float*)d_in[11]};
    const float* AD[3] = {(const float*)d_in[4],  (const float*)d_in[8],  (const float*)d_in[12]};
    const float* B[3]  = {(const float*)d_in[5],  (const float*)d_in[9],  (const float*)d_in[13]};

    const int Cc[3] = {in_sizes[5], in_sizes[9], in_sizes[13]};
    const int H = in_sizes[3] / Cc[0];
    const int E = in_sizes[1] / 2;
    const int N = out_size / Cc[2];
    const int F_IN = in_sizes[0] / N;

    __half* hbuf;
    float *ebuf, *At, *Bt;
    int *rowptr, *cnt, *cursor, *col;
    cudaGetSymbolAddress((void**)&hbuf,   g_h);
    cudaGetSymbolAddress((void**)&ebuf,   g_e);
    cudaGetSymbolAddress((void**)&At,     g_At);
    cudaGetSymbolAddress((void**)&Bt,     g_Bt);
    cudaGetSymbolAddress((void**)&rowptr, g_rowptr);
    cudaGetSymbolAddress((void**)&cnt,    g_cnt);
    cudaGetSymbolAddress((void**)&cursor, g_cursor);
    cudaGetSymbolAddress((void**)&col,    g_col);

    cudaFuncSetAttribute(gemm_mma, cudaFuncAttributeMaxDynamicSharedMemorySize, GEMM_SMEM);

    const int aggB = (N + 1) / 2;
    const int ez4 = (2 * EOFF) / 4;

    // ---- fused layer-0 pre-work ----
    {
        int HC0 = H * Cc[0];
        int twB = (HC0 / 32) * (F_IN / 32);
        int total4 = (N * F_IN) >> 2;
        int rB = 1280, z1B = 32, z2B = 4;
        pre0_k<<<twB + rB + z1B + z2B, 256>>>(
            (const float4*)x, (float4*)At, total4, rB,
            W[0], Bt, F_IN, HC0, twB,
            (float4*)ebuf, ez4, z1B,
            (int4*)cnt, (N + 3) / 4);
    }

    int K = F_IN;
    for (int l = 0; l < 3; ++l) {
        int C = Cc[l], HC = H * C;
        int par = l & 1;
        float* esrc = ebuf + par * 2 * EOFF;
        float* edst = esrc + EOFF;

        {
            int nx = HC / 128;
            int ntiles = nx * ((N + 127) / 128);
            int grid = (ntiles < GEMM_GRID) ? ntiles : GEMM_GRID;
            gemm_mma<<<grid, 256, GEMM_SMEM>>>(At, Bt, hbuf,
                                               AS[l], AD[l], esrc, edst,
                                               N, HC, K, C, H, nx, ntiles,
                                               ei + E, E, N,
                                               (l == 0) ? cnt : nullptr);
        }

        if (l == 0) {
            // CSR: scan (writes rowptr + cursor) then fill
            scan_k<<<1, 1024>>>(cnt, rowptr, cursor, N);
            int blocks = (E + N + 255) / 256;
            fill_k<<<blocks, 256>>>(ei, ei + E, E, N, cursor, col);
        }

        if (l < 2) {
            int Kn = C, HCn = H * Cc[l + 1];
            int twB = (HCn / 32) * (Kn / 32);
            int zB = 32;
            float4* ezn = (float4*)(ebuf + ((l + 1) & 1) * 2 * EOFF);
            aggtw_k<<<aggB + twB + zB, 256>>>(
                hbuf, esrc, edst, rowptr, col, B[l], (float*)d_out, At, 0,
                H, C, HC, 1.0f / (float)H, N, aggB,
                W[l + 1], Bt, Kn, HCn, twB, ezn, ez4, zB);
        } else {
            aggtw_k<<<aggB, 256>>>(
                hbuf, esrc, edst, rowptr, col, B[l], (float*)d_out, At, 1,
                H, C, HC, 1.0f / (float)H, N, aggB,
                nullptr, nullptr, 0, 0, 0, nullptr, 0, 0);
        }
        K = C;
    }
}